// round 3
// baseline (speedup 1.0000x reference)
#include <cuda_runtime.h>
#include <math.h>

#define C_DIM 256
#define NHEAD 4
#define HDIM 64
#define AP 65                       // padded row stride for attention smem tiles
#define ATTN_SMEM_BYTES ((4*64*AP + 3*64) * (int)sizeof(float))

// ---------------- device scratch (no allocation allowed) ----------------
__device__ float g_featS[2*2048*256];
__device__ float g_featT[2*2048*256];
__device__ float g_projS[2*2048*256];
__device__ float g_projT[2*2048*256];
__device__ float g_q [8192*256];
__device__ float g_k [8192*256];
__device__ float g_v [8192*256];
__device__ float g_o [8192*256];
__device__ float g_t2[8192*256];
__device__ float g_h [8192*512];
__device__ float g_t1[8192*512];
__device__ float g_ssub[8192*256];
__device__ float g_tsub[8192*256];

// ---------------- GEMM: C[M,N] = A[M,K] @ B[K,N], optional ReLU ----------------
// Requires M%64==0, N%64==0 (also N%4), K%16==0. 256 threads, 64x64 tile, 4x4/thread.
__global__ void gemm_kernel(const float* __restrict__ A, const float* __restrict__ B,
                            float* __restrict__ Cc, int M, int N, int K, int doRelu)
{
    __shared__ float As[16][68];   // transposed: As[k][row]
    __shared__ float Bs[16][68];   // Bs[k][col]
    int tid = threadIdx.x;
    int tx = tid & 15, ty = tid >> 4;
    int rowBase = blockIdx.y << 6;
    int colBase = blockIdx.x << 6;
    int arow = tid >> 2;            // 0..63
    int acol = (tid & 3) << 2;      // 0,4,8,12
    int brow = tid >> 4;            // 0..15
    int bcol = (tid & 15) << 2;     // 0..60
    const float* Ap = A + (size_t)(rowBase + arow) * K + acol;
    const float* Bp = B + (size_t)brow * N + colBase + bcol;
    float acc[4][4] = {};
    for (int k0 = 0; k0 < K; k0 += 16) {
        float4 av = *(const float4*)(Ap + k0);
        float4 bv = *(const float4*)(Bp + (size_t)k0 * N);
        As[acol+0][arow] = av.x; As[acol+1][arow] = av.y;
        As[acol+2][arow] = av.z; As[acol+3][arow] = av.w;
        *(float4*)&Bs[brow][bcol] = bv;
        __syncthreads();
#pragma unroll
        for (int kk = 0; kk < 16; kk++) {
            float4 a = *(const float4*)&As[kk][ty << 2];
            float4 b = *(const float4*)&Bs[kk][tx << 2];
            acc[0][0] += a.x*b.x; acc[0][1] += a.x*b.y; acc[0][2] += a.x*b.z; acc[0][3] += a.x*b.w;
            acc[1][0] += a.y*b.x; acc[1][1] += a.y*b.y; acc[1][2] += a.y*b.z; acc[1][3] += a.y*b.w;
            acc[2][0] += a.z*b.x; acc[2][1] += a.z*b.y; acc[2][2] += a.z*b.z; acc[2][3] += a.z*b.w;
            acc[3][0] += a.w*b.x; acc[3][1] += a.w*b.y; acc[3][2] += a.w*b.z; acc[3][3] += a.w*b.w;
        }
        __syncthreads();
    }
#pragma unroll
    for (int i = 0; i < 4; i++) {
        float4 v;
        v.x = acc[i][0]; v.y = acc[i][1]; v.z = acc[i][2]; v.w = acc[i][3];
        if (doRelu) {
            v.x = fmaxf(v.x, 0.f); v.y = fmaxf(v.y, 0.f);
            v.z = fmaxf(v.z, 0.f); v.w = fmaxf(v.w, 0.f);
        }
        *(float4*)&Cc[(size_t)(rowBase + (ty<<2) + i) * N + colBase + (tx<<2)] = v;
    }
}

// ---------------- Flash attention (fp32), d=64, 64q x 64kv tiles ----------------
// Q,K,V,O layouts: (bs, L, C_DIM) with head h in columns [h*64, h*64+64).
// grid = (Lq/64, NHEAD, bs), 256 threads. Requires Lq%64==0, Lkv%64==0.
__global__ void attn_kernel(const float* __restrict__ Q, const float* __restrict__ K,
                            const float* __restrict__ V, float* __restrict__ O,
                            int Lq, int Lkv)
{
    extern __shared__ float sm[];
    float* Qs  = sm;                 // 64*AP
    float* Ks  = Qs + 64*AP;
    float* Vs  = Ks + 64*AP;
    float* Ss  = Vs + 64*AP;
    float* m_s = Ss + 64*AP;         // 64
    float* l_s = m_s + 64;           // 64
    float* sc_s= l_s + 64;           // 64

    int tid = threadIdx.x;
    int tx = tid & 15, ty = tid >> 4;
    int qt = blockIdx.x, h = blockIdx.y, b = blockIdx.z;

    const float* Qb = Q + ((size_t)b * Lq + qt * 64) * C_DIM + h * HDIM;
    const float* Kb = K + (size_t)b * Lkv * C_DIM + h * HDIM;
    const float* Vb = V + (size_t)b * Lkv * C_DIM + h * HDIM;

    // load Q tile
    {
        int r = tid >> 2;
        int c0 = (tid & 3) << 4;
        const float* qp = Qb + (size_t)r * C_DIM + c0;
        float* qs = Qs + r * AP + c0;
#pragma unroll
        for (int j = 0; j < 16; j += 4) {
            float4 a = *(const float4*)(qp + j);
            qs[j] = a.x; qs[j+1] = a.y; qs[j+2] = a.z; qs[j+3] = a.w;
        }
    }
    if (tid < 64) { m_s[tid] = -INFINITY; l_s[tid] = 0.f; }
    __syncthreads();

    float acc[4][4] = {};
    int q0 = ty << 2, s0l = tx << 2;

    for (int s0 = 0; s0 < Lkv; s0 += 64) {
        // load K,V tiles
        {
            int r = tid >> 2;
            int c0 = (tid & 3) << 4;
            const float* kp = Kb + (size_t)(s0 + r) * C_DIM + c0;
            const float* vp = Vb + (size_t)(s0 + r) * C_DIM + c0;
            float* ks = Ks + r * AP + c0;
            float* vs = Vs + r * AP + c0;
#pragma unroll
            for (int j = 0; j < 16; j += 4) {
                float4 a = *(const float4*)(kp + j);
                float4 c = *(const float4*)(vp + j);
                ks[j] = a.x; ks[j+1] = a.y; ks[j+2] = a.z; ks[j+3] = a.w;
                vs[j] = c.x; vs[j+1] = c.y; vs[j+2] = c.z; vs[j+3] = c.w;
            }
        }
        __syncthreads();

        // S = (Q @ K^T) * 0.125
        {
            float sacc[4][4] = {};
            const float* qr = Qs + q0 * AP;
            const float* kr = Ks + s0l * AP;
#pragma unroll 8
            for (int d = 0; d < 64; d++) {
                float a0 = qr[d], a1 = qr[AP+d], a2 = qr[2*AP+d], a3 = qr[3*AP+d];
                float b0 = kr[d], b1 = kr[AP+d], b2 = kr[2*AP+d], b3 = kr[3*AP+d];
                sacc[0][0]+=a0*b0; sacc[0][1]+=a0*b1; sacc[0][2]+=a0*b2; sacc[0][3]+=a0*b3;
                sacc[1][0]+=a1*b0; sacc[1][1]+=a1*b1; sacc[1][2]+=a1*b2; sacc[1][3]+=a1*b3;
                sacc[2][0]+=a2*b0; sacc[2][1]+=a2*b1; sacc[2][2]+=a2*b2; sacc[2][3]+=a2*b3;
                sacc[3][0]+=a3*b0; sacc[3][1]+=a3*b1; sacc[3][2]+=a3*b2; sacc[3][3]+=a3*b3;
            }
            float* sr = Ss + q0 * AP + s0l;
#pragma unroll
            for (int i = 0; i < 4; i++)
#pragma unroll
                for (int j = 0; j < 4; j++)
                    sr[i*AP + j] = sacc[i][j] * 0.125f;
        }
        __syncthreads();

        // online softmax: 4 threads per row
        {
            int row = tid >> 2;
            int part = tid & 3;
            float* Sr = Ss + row * AP + part * 16;
            float mx = -INFINITY;
#pragma unroll
            for (int k = 0; k < 16; k++) mx = fmaxf(mx, Sr[k]);
            mx = fmaxf(mx, __shfl_xor_sync(0xffffffffu, mx, 1));
            mx = fmaxf(mx, __shfl_xor_sync(0xffffffffu, mx, 2));
            float m_old = m_s[row];
            float m_new = fmaxf(m_old, mx);
            float sum = 0.f;
#pragma unroll
            for (int k = 0; k < 16; k++) {
                float p = __expf(Sr[k] - m_new);
                Sr[k] = p; sum += p;
            }
            sum += __shfl_xor_sync(0xffffffffu, sum, 1);
            sum += __shfl_xor_sync(0xffffffffu, sum, 2);
            if (part == 0) {
                float sc = __expf(m_old - m_new);   // first tile: exp(-inf - finite) = 0
                l_s[row] = l_s[row] * sc + sum;
                m_s[row] = m_new;
                sc_s[row] = sc;
            }
        }
        __syncthreads();

        // O = O*scale + P @ V
        {
            float sc0 = sc_s[q0+0], sc1 = sc_s[q0+1], sc2 = sc_s[q0+2], sc3 = sc_s[q0+3];
#pragma unroll
            for (int j = 0; j < 4; j++) {
                acc[0][j] *= sc0; acc[1][j] *= sc1; acc[2][j] *= sc2; acc[3][j] *= sc3;
            }
            const float* pr = Ss + q0 * AP;
#pragma unroll 8
            for (int s = 0; s < 64; s++) {
                float p0 = pr[s], p1 = pr[AP+s], p2 = pr[2*AP+s], p3 = pr[3*AP+s];
                const float* vr = Vs + s * AP + (tx << 2);
                float v0 = vr[0], v1 = vr[1], v2 = vr[2], v3 = vr[3];
                acc[0][0]+=p0*v0; acc[0][1]+=p0*v1; acc[0][2]+=p0*v2; acc[0][3]+=p0*v3;
                acc[1][0]+=p1*v0; acc[1][1]+=p1*v1; acc[1][2]+=p1*v2; acc[1][3]+=p1*v3;
                acc[2][0]+=p2*v0; acc[2][1]+=p2*v1; acc[2][2]+=p2*v2; acc[2][3]+=p2*v3;
                acc[3][0]+=p3*v0; acc[3][1]+=p3*v1; acc[3][2]+=p3*v2; acc[3][3]+=p3*v3;
            }
        }
        __syncthreads();
    }

    // finalize: divide by l, write out
    float* orow = O + ((size_t)b * Lq + qt * 64 + q0) * C_DIM + h * HDIM + (tx << 2);
#pragma unroll
    for (int i = 0; i < 4; i++) {
        float inv = 1.f / l_s[q0 + i];
        float4 v;
        v.x = acc[i][0]*inv; v.y = acc[i][1]*inv; v.z = acc[i][2]*inv; v.w = acc[i][3]*inv;
        *(float4*)(orow + (size_t)i * C_DIM) = v;
    }
}

// ---------------- LayerNorm kernels (width 256, no affine) ----------------
// h[row, 0:256] = x[row]; h[row, 256:512] = LN(t[row])
__global__ void ln_concat_kernel(const float* __restrict__ x, const float* __restrict__ t,
                                 float* __restrict__ h)
{
    int row = blockIdx.x, c = threadIdx.x;
    float v = t[(size_t)row * C_DIM + c];
    __shared__ float shs[8], shq[8];
    float s = v, q = v * v;
#pragma unroll
    for (int o = 16; o > 0; o >>= 1) {
        s += __shfl_xor_sync(0xffffffffu, s, o);
        q += __shfl_xor_sync(0xffffffffu, q, o);
    }
    if ((c & 31) == 0) { shs[c >> 5] = s; shq[c >> 5] = q; }
    __syncthreads();
    if (c < 32) {
        s = (c < 8) ? shs[c] : 0.f;
        q = (c < 8) ? shq[c] : 0.f;
#pragma unroll
        for (int o = 4; o > 0; o >>= 1) {
            s += __shfl_xor_sync(0xffffffffu, s, o);
            q += __shfl_xor_sync(0xffffffffu, q, o);
        }
        if (c == 0) { shs[0] = s; shq[0] = q; }
    }
    __syncthreads();
    float mean = shs[0] * (1.f / 256.f);
    float var  = shq[0] * (1.f / 256.f) - mean * mean;
    float y = (v - mean) * rsqrtf(var + 1e-5f);
    h[(size_t)row * 512 + c]       = x[(size_t)row * C_DIM + c];
    h[(size_t)row * 512 + 256 + c] = y;
}

// out[row] = x[row] + LN(t[row])
__global__ void ln_add_kernel(const float* __restrict__ x, const float* __restrict__ t,
                              float* __restrict__ outp)
{
    int row = blockIdx.x, c = threadIdx.x;
    float v = t[(size_t)row * C_DIM + c];
    __shared__ float shs[8], shq[8];
    float s = v, q = v * v;
#pragma unroll
    for (int o = 16; o > 0; o >>= 1) {
        s += __shfl_xor_sync(0xffffffffu, s, o);
        q += __shfl_xor_sync(0xffffffffu, q, o);
    }
    if ((c & 31) == 0) { shs[c >> 5] = s; shq[c >> 5] = q; }
    __syncthreads();
    if (c < 32) {
        s = (c < 8) ? shs[c] : 0.f;
        q = (c < 8) ? shq[c] : 0.f;
#pragma unroll
        for (int o = 4; o > 0; o >>= 1) {
            s += __shfl_xor_sync(0xffffffffu, s, o);
            q += __shfl_xor_sync(0xffffffffu, q, o);
        }
        if (c == 0) { shs[0] = s; shq[0] = q; }
    }
    __syncthreads();
    float mean = shs[0] * (1.f / 256.f);
    float var  = shq[0] * (1.f / 256.f) - mean * mean;
    float y = (v - mean) * rsqrtf(var + 1e-5f);
    outp[(size_t)row * C_DIM + c] = x[(size_t)row * C_DIM + c] + y;
}

__global__ void add_kernel(float* __restrict__ x, const float* __restrict__ a, int n)
{
    int i = blockIdx.x * 256 + threadIdx.x;
    if (i < n) x[i] += a[i];
}

// out[g*Lp + l, :] = feat[(g/maskNum)*N + idx, :]  (idx==N -> zeros)
__global__ void gather_kernel(const float* __restrict__ feat, const int* __restrict__ idx,
                              float* __restrict__ outp, int N, int Lp, int maskNum)
{
    int row = blockIdx.x;
    int g = row / Lp;
    int b = g / maskNum;
    int i = idx[row];
    int c = threadIdx.x;
    float val = 0.f;
    if (i >= 0 && i < N) val = feat[((size_t)b * N + i) * C_DIM + c];
    outp[(size_t)row * C_DIM + c] = val;
}

// ---------------- host orchestration ----------------
static void gemm(const float* A, const float* B, float* C, int M, int N, int K, int relu)
{
    dim3 g(N / 64, M / 64);
    gemm_kernel<<<g, 256>>>(A, B, C, M, N, K, relu);
}

struct Scr { float *q, *k, *v, *o, *t2, *h, *t1; };

static void attn_layer(const float* x, const float* src, float* outp,
                       int bs, int Lq, int Lkv, int li,
                       const float* qWA, const float* kWA, const float* vWA,
                       const float* mWA, const float* w1A, const float* w2A,
                       const Scr& S)
{
    int Mq = bs * Lq, Mkv = bs * Lkv;
    const float* qW = qWA + (size_t)li * 256 * 256;
    const float* kW = kWA + (size_t)li * 256 * 256;
    const float* vW = vWA + (size_t)li * 256 * 256;
    const float* mW = mWA + (size_t)li * 256 * 256;
    const float* w1 = w1A + (size_t)li * 512 * 512;
    const float* w2 = w2A + (size_t)li * 512 * 256;

    gemm(x,   qW, S.q, Mq,  256, 256, 0);
    gemm(src, kW, S.k, Mkv, 256, 256, 0);
    gemm(src, vW, S.v, Mkv, 256, 256, 0);
    attn_kernel<<<dim3(Lq / 64, NHEAD, bs), 256, ATTN_SMEM_BYTES>>>(S.q, S.k, S.v, S.o, Lq, Lkv);
    gemm(S.o, mW, S.t2, Mq, 256, 256, 0);
    ln_concat_kernel<<<Mq, 256>>>(x, S.t2, S.h);
    gemm(S.h,  w1, S.t1, Mq, 512, 512, 1);   // fused ReLU
    gemm(S.t1, w2, S.t2, Mq, 256, 512, 0);
    ln_add_kernel<<<Mq, 256>>>(x, S.t2, outp);
}

extern "C" void kernel_launch(void* const* d_in, const int* in_sizes, int n_in,
                              void* d_out, int out_size)
{
    (void)in_sizes; (void)out_size;
    const float* in_srcF = (const float*)d_in[0];
    const float* in_tgtF = (const float*)d_in[1];
    const int*   si      = (const int*)  d_in[6];
    const int*   ti      = (const int*)  d_in[7];
    const float* src2d   = (const float*)d_in[11];
    const float* tgt2d   = (const float*)d_in[12];
    // weights indexed from the END so the scalar 'data' input can't shift them
    const float* w2A   = (const float*)d_in[n_in - 1];
    const float* w1A   = (const float*)d_in[n_in - 2];
    const float* mWA   = (const float*)d_in[n_in - 3];
    const float* vWA   = (const float*)d_in[n_in - 4];
    const float* kWA   = (const float*)d_in[n_in - 5];
    const float* qWA   = (const float*)d_in[n_in - 6];
    const float* dinoW = (const float*)d_in[n_in - 7];
    float* out = (float*)d_out;

    float *featS, *featT, *projS, *projT, *qb, *kb, *vb, *ob, *t2, *hb, *t1, *ssub, *tsub;
    cudaGetSymbolAddress((void**)&featS, g_featS);
    cudaGetSymbolAddress((void**)&featT, g_featT);
    cudaGetSymbolAddress((void**)&projS, g_projS);
    cudaGetSymbolAddress((void**)&projT, g_projT);
    cudaGetSymbolAddress((void**)&qb, g_q);
    cudaGetSymbolAddress((void**)&kb, g_k);
    cudaGetSymbolAddress((void**)&vb, g_v);
    cudaGetSymbolAddress((void**)&ob, g_o);
    cudaGetSymbolAddress((void**)&t2, g_t2);
    cudaGetSymbolAddress((void**)&hb, g_h);
    cudaGetSymbolAddress((void**)&t1, g_t1);
    cudaGetSymbolAddress((void**)&ssub, g_ssub);
    cudaGetSymbolAddress((void**)&tsub, g_tsub);

    cudaFuncSetAttribute(attn_kernel, cudaFuncAttributeMaxDynamicSharedMemorySize,
                         ATTN_SMEM_BYTES);

    Scr S{qb, kb, vb, ob, t2, hb, t1};
    const int Mmain = 2 * 2048;
    const size_t featBytes = (size_t)Mmain * 256 * sizeof(float);

    cudaMemcpyAsync(featS, in_srcF, featBytes, cudaMemcpyDeviceToDevice, 0);
    cudaMemcpyAsync(featT, in_tgtF, featBytes, cudaMemcpyDeviceToDevice, 0);

    // 2D-feature projection (B*N=4096 rows, 384 -> 256)
    gemm(src2d, dinoW, projS, Mmain, 256, 384, 0);
    gemm(tgt2d, dinoW, projT, Mmain, 256, 384, 0);

    // layer 0: self
    add_kernel<<<Mmain * 256 / 256, 256>>>(featS, projS, Mmain * 256);
    add_kernel<<<Mmain * 256 / 256, 256>>>(featT, projT, Mmain * 256);
    attn_layer(featS, featS, featS, 2, 2048, 2048, 0, qWA, kWA, vWA, mWA, w1A, w2A, S);
    attn_layer(featT, featT, featT, 2, 2048, 2048, 0, qWA, kWA, vWA, mWA, w1A, w2A, S);
    // layer 1: cross (tgt uses UPDATED src, matching reference ordering)
    attn_layer(featS, featT, featS, 2, 2048, 2048, 1, qWA, kWA, vWA, mWA, w1A, w2A, S);
    attn_layer(featT, featS, featT, 2, 2048, 2048, 1, qWA, kWA, vWA, mWA, w1A, w2A, S);
    // layer 2: self
    add_kernel<<<Mmain * 256 / 256, 256>>>(featS, projS, Mmain * 256);
    add_kernel<<<Mmain * 256 / 256, 256>>>(featT, projT, Mmain * 256);
    attn_layer(featS, featS, featS, 2, 2048, 2048, 2, qWA, kWA, vWA, mWA, w1A, w2A, S);
    attn_layer(featT, featT, featT, 2, 2048, 2048, 2, qWA, kWA, vWA, mWA, w1A, w2A, S);
    // layer 3: cross
    attn_layer(featS, featT, featS, 2, 2048, 2048, 3, qWA, kWA, vWA, mWA, w1A, w2A, S);
    attn_layer(featT, featS, featT, 2, 2048, 2048, 3, qWA, kWA, vWA, mWA, w1A, w2A, S);

    // layer 4: semantic_subspace_cross — gather G=16 groups of Lp=512 (idx==N -> 0)
    gather_kernel<<<16 * 512, 256>>>(featS, si, ssub, 2048, 512, 8);
    gather_kernel<<<16 * 512, 256>>>(featT, ti, tsub, 2048, 512, 8);
    float* outSsem = out + (size_t)2 * 1048576;
    float* outTsem = outSsem + (size_t)16 * 512 * 256;
    attn_layer(ssub, tsub, outSsem, 16, 512, 512, 4, qWA, kWA, vWA, mWA, w1A, w2A, S);
    attn_layer(tsub, ssub, outTsem, 16, 512, 512, 4, qWA, kWA, vWA, mWA, w1A, w2A, S);

    // pack outputs: (src_feat, tgt_feat, s_sem, t_sem)
    cudaMemcpyAsync(out,            featS, featBytes, cudaMemcpyDeviceToDevice, 0);
    cudaMemcpyAsync(out + 1048576,  featT, featBytes, cudaMemcpyDeviceToDevice, 0);
}

// round 6
// speedup vs baseline: 1.6453x; 1.6453x over previous
#include <cuda_runtime.h>
#include <math.h>
#include <stdint.h>

#define C_DIM 256
#define NHEAD 4
#define HDIM 64

// attention smem: Qs, Ks, Vt, Ps each 64 rows x stride 68 (u32)
#define AT_S 68
#define ATTN_SMEM_BYTES (4 * 64 * AT_S * 4)

// ---------------- device scratch (no allocation allowed) ----------------
__device__ float g_featS[2*2048*256];
__device__ float g_featT[2*2048*256];
__device__ float g_projS[2*2048*256];
__device__ float g_projT[2*2048*256];
__device__ float g_q [8192*256];
__device__ float g_k [8192*256];
__device__ float g_v [8192*256];
__device__ float g_o [8192*256];
__device__ float g_t2[8192*256];
__device__ float g_h [8192*512];
__device__ float g_t1[8192*512];
__device__ float g_ssub[8192*256];
__device__ float g_tsub[8192*256];

// ---------------- helpers ----------------
__device__ __forceinline__ uint32_t f2tf32(float x) {
    uint32_t r;
    asm("cvt.rna.tf32.f32 %0, %1;" : "=r"(r) : "f"(x));
    return r;
}

__device__ __forceinline__ void mma_tf32(float (&d)[4], const uint32_t (&a)[4],
                                         const uint32_t (&b)[2]) {
    asm volatile(
        "mma.sync.aligned.m16n8k8.row.col.f32.tf32.tf32.f32 "
        "{%0,%1,%2,%3}, {%4,%5,%6,%7}, {%8,%9}, {%0,%1,%2,%3};"
        : "+f"(d[0]), "+f"(d[1]), "+f"(d[2]), "+f"(d[3])
        : "r"(a[0]), "r"(a[1]), "r"(a[2]), "r"(a[3]), "r"(b[0]), "r"(b[1]));
}

// ---------------- TF32 tensor-core GEMM: C = A @ B (+ optional ReLU) --------
// M%128==0, N%64==0, K%32==0. 256 threads, block tile 128x64x32,
// 8 warps in 4x2 grid, warp tile 32x32.
#define GAS 36   // As row stride (u32)
#define GBS 72   // Bs row stride (u32)
__global__ void gemm_kernel(const float* __restrict__ A, const float* __restrict__ B,
                            float* __restrict__ Cc, int M, int N, int K, int doRelu)
{
    __shared__ uint32_t As[128 * GAS];
    __shared__ uint32_t Bs[32 * GBS];

    int tid = threadIdx.x;
    int lane = tid & 31;
    int wid = tid >> 5;
    int wm = (wid & 3) * 32;        // warp row offset in tile
    int wn = (wid >> 2) * 32;       // warp col offset in tile
    int rowBase = blockIdx.y << 7;
    int colBase = blockIdx.x << 6;

    int ar = tid >> 3;              // 0..31 (row within 32-row pass)
    int ac = (tid & 7) << 2;        // 0,4,...,28
    int br = tid >> 4;              // 0..15
    int bc = (tid & 15) << 2;       // 0..60

    float acc[2][4][4] = {};

    for (int k0 = 0; k0 < K; k0 += 32) {
        // load A 128x32 (4 passes of 32 rows)
#pragma unroll
        for (int p = 0; p < 4; p++) {
            int r = p * 32 + ar;
            float4 v = *(const float4*)(A + (size_t)(rowBase + r) * K + k0 + ac);
            uint4 u;
            u.x = f2tf32(v.x); u.y = f2tf32(v.y); u.z = f2tf32(v.z); u.w = f2tf32(v.w);
            *(uint4*)&As[r * GAS + ac] = u;
        }
        // load B 32x64 (2 passes of 16 rows)
#pragma unroll
        for (int p = 0; p < 2; p++) {
            int r = p * 16 + br;
            float4 v = *(const float4*)(B + (size_t)(k0 + r) * N + colBase + bc);
            uint4 u;
            u.x = f2tf32(v.x); u.y = f2tf32(v.y); u.z = f2tf32(v.z); u.w = f2tf32(v.w);
            *(uint4*)&Bs[r * GBS + bc] = u;
        }
        __syncthreads();

#pragma unroll
        for (int kt = 0; kt < 4; kt++) {
            int kk = kt * 8;
            uint32_t a[2][4];
#pragma unroll
            for (int mt = 0; mt < 2; mt++) {
                int r = wm + mt * 16 + (lane >> 2);
                a[mt][0] = As[r * GAS + kk + (lane & 3)];
                a[mt][1] = As[(r + 8) * GAS + kk + (lane & 3)];
                a[mt][2] = As[r * GAS + kk + 4 + (lane & 3)];
                a[mt][3] = As[(r + 8) * GAS + kk + 4 + (lane & 3)];
            }
#pragma unroll
            for (int nt = 0; nt < 4; nt++) {
                uint32_t b[2];
                int c = wn + nt * 8 + (lane >> 2);
                b[0] = Bs[(kk + (lane & 3)) * GBS + c];
                b[1] = Bs[(kk + 4 + (lane & 3)) * GBS + c];
                mma_tf32(acc[0][nt], a[0], b);
                mma_tf32(acc[1][nt], a[1], b);
            }
        }
        __syncthreads();
    }

    // epilogue
#pragma unroll
    for (int mt = 0; mt < 2; mt++) {
        int r0 = rowBase + wm + mt * 16 + (lane >> 2);
#pragma unroll
        for (int nt = 0; nt < 4; nt++) {
            int c = colBase + wn + nt * 8 + ((lane & 3) << 1);
            float2 v0 = make_float2(acc[mt][nt][0], acc[mt][nt][1]);
            float2 v1 = make_float2(acc[mt][nt][2], acc[mt][nt][3]);
            if (doRelu) {
                v0.x = fmaxf(v0.x, 0.f); v0.y = fmaxf(v0.y, 0.f);
                v1.x = fmaxf(v1.x, 0.f); v1.y = fmaxf(v1.y, 0.f);
            }
            *(float2*)(Cc + (size_t)r0 * N + c)       = v0;
            *(float2*)(Cc + (size_t)(r0 + 8) * N + c) = v1;
        }
    }
}

// ---------------- TF32 tensor-core flash attention, d=64 --------------------
// Q,K,V,O: (bs, L, C_DIM), head h in cols [h*64, h*64+64).
// grid = (Lq/64, NHEAD, bs), 128 threads (4 warps x 16 q-rows).
__global__ void attn_kernel(const float* __restrict__ Q, const float* __restrict__ K,
                            const float* __restrict__ V, float* __restrict__ O,
                            int Lq, int Lkv)
{
    extern __shared__ uint32_t sm[];
    uint32_t* Qs = sm;                    // [64][AT_S]
    uint32_t* Ks = Qs + 64 * AT_S;
    uint32_t* Vt = Ks + 64 * AT_S;        // transposed: Vt[d][s]
    uint32_t* Ps = Vt + 64 * AT_S;

    int tid = threadIdx.x;
    int lane = tid & 31;
    int wid = tid >> 5;
    int qt = blockIdx.x, h = blockIdx.y, b = blockIdx.z;

    const float* Qb = Q + ((size_t)b * Lq + qt * 64) * C_DIM + h * HDIM;
    const float* Kb = K + (size_t)b * Lkv * C_DIM + h * HDIM;
    const float* Vb = V + (size_t)b * Lkv * C_DIM + h * HDIM;

    int lr = tid >> 4;           // 0..7 (row within 8-row pass)
    int lc = (tid & 15) << 2;    // 0..60

    // load Q tile (64x64)
#pragma unroll
    for (int p = 0; p < 8; p++) {
        int r = p * 8 + lr;
        float4 v = *(const float4*)(Qb + (size_t)r * C_DIM + lc);
        uint4 u;
        u.x = f2tf32(v.x); u.y = f2tf32(v.y); u.z = f2tf32(v.z); u.w = f2tf32(v.w);
        *(uint4*)&Qs[r * AT_S + lc] = u;
    }

    float oacc[8][4] = {};
    float m0 = -INFINITY, m1 = -INFINITY, l0 = 0.f, l1 = 0.f;
    int qr = wid * 16 + (lane >> 2);      // this thread's first q-row in tile

    for (int s0 = 0; s0 < Lkv; s0 += 64) {
        __syncthreads();   // previous iteration's reads of Ks/Vt done
        // load K tile + transposed V tile
#pragma unroll
        for (int p = 0; p < 8; p++) {
            int r = p * 8 + lr;
            float4 kv = *(const float4*)(Kb + (size_t)(s0 + r) * C_DIM + lc);
            uint4 u;
            u.x = f2tf32(kv.x); u.y = f2tf32(kv.y); u.z = f2tf32(kv.z); u.w = f2tf32(kv.w);
            *(uint4*)&Ks[r * AT_S + lc] = u;
            float4 vv = *(const float4*)(Vb + (size_t)(s0 + r) * C_DIM + lc);
            Vt[(lc + 0) * AT_S + r] = f2tf32(vv.x);
            Vt[(lc + 1) * AT_S + r] = f2tf32(vv.y);
            Vt[(lc + 2) * AT_S + r] = f2tf32(vv.z);
            Vt[(lc + 3) * AT_S + r] = f2tf32(vv.w);
        }
        __syncthreads();

        // S = Q @ K^T  (16 q-rows per warp x 64 s)
        float sacc[8][4] = {};
#pragma unroll
        for (int kt = 0; kt < 8; kt++) {
            int kk = kt * 8;
            uint32_t a[4];
            int r = wid * 16 + (lane >> 2);
            a[0] = Qs[r * AT_S + kk + (lane & 3)];
            a[1] = Qs[(r + 8) * AT_S + kk + (lane & 3)];
            a[2] = Qs[r * AT_S + kk + 4 + (lane & 3)];
            a[3] = Qs[(r + 8) * AT_S + kk + 4 + (lane & 3)];
#pragma unroll
            for (int nt = 0; nt < 8; nt++) {
                uint32_t bb[2];
                int c = nt * 8 + (lane >> 2);
                bb[0] = Ks[c * AT_S + kk + (lane & 3)];
                bb[1] = Ks[c * AT_S + kk + 4 + (lane & 3)];
                mma_tf32(sacc[nt], a, bb);
            }
        }

        // scale + online softmax (rows qr and qr+8; each row split over 4 lanes)
        float mx0 = -INFINITY, mx1 = -INFINITY;
#pragma unroll
        for (int nt = 0; nt < 8; nt++) {
            sacc[nt][0] *= 0.125f; sacc[nt][1] *= 0.125f;
            sacc[nt][2] *= 0.125f; sacc[nt][3] *= 0.125f;
            mx0 = fmaxf(mx0, fmaxf(sacc[nt][0], sacc[nt][1]));
            mx1 = fmaxf(mx1, fmaxf(sacc[nt][2], sacc[nt][3]));
        }
        mx0 = fmaxf(mx0, __shfl_xor_sync(0xffffffffu, mx0, 1));
        mx0 = fmaxf(mx0, __shfl_xor_sync(0xffffffffu, mx0, 2));
        mx1 = fmaxf(mx1, __shfl_xor_sync(0xffffffffu, mx1, 1));
        mx1 = fmaxf(mx1, __shfl_xor_sync(0xffffffffu, mx1, 2));
        float mn0 = fmaxf(m0, mx0), mn1 = fmaxf(m1, mx1);
        float sc0 = __expf(m0 - mn0), sc1 = __expf(m1 - mn1);
        float sum0 = 0.f, sum1 = 0.f;
#pragma unroll
        for (int nt = 0; nt < 8; nt++) {
            float p00 = __expf(sacc[nt][0] - mn0);
            float p01 = __expf(sacc[nt][1] - mn0);
            float p10 = __expf(sacc[nt][2] - mn1);
            float p11 = __expf(sacc[nt][3] - mn1);
            sum0 += p00 + p01; sum1 += p10 + p11;
            int c = nt * 8 + ((lane & 3) << 1);
            Ps[qr * AT_S + c]           = f2tf32(p00);
            Ps[qr * AT_S + c + 1]       = f2tf32(p01);
            Ps[(qr + 8) * AT_S + c]     = f2tf32(p10);
            Ps[(qr + 8) * AT_S + c + 1] = f2tf32(p11);
        }
        sum0 += __shfl_xor_sync(0xffffffffu, sum0, 1);
        sum0 += __shfl_xor_sync(0xffffffffu, sum0, 2);
        sum1 += __shfl_xor_sync(0xffffffffu, sum1, 1);
        sum1 += __shfl_xor_sync(0xffffffffu, sum1, 2);
        l0 = l0 * sc0 + sum0; l1 = l1 * sc1 + sum1;
        m0 = mn0; m1 = mn1;

        // rescale O accumulators
#pragma unroll
        for (int nt = 0; nt < 8; nt++) {
            oacc[nt][0] *= sc0; oacc[nt][1] *= sc0;
            oacc[nt][2] *= sc1; oacc[nt][3] *= sc1;
        }
        __syncwarp();

        // O += P @ V   (k = s, n = d; B from transposed Vt)
#pragma unroll
        for (int kt = 0; kt < 8; kt++) {
            int kk = kt * 8;
            uint32_t a[4];
            int r = wid * 16 + (lane >> 2);
            a[0] = Ps[r * AT_S + kk + (lane & 3)];
            a[1] = Ps[(r + 8) * AT_S + kk + (lane & 3)];
            a[2] = Ps[r * AT_S + kk + 4 + (lane & 3)];
            a[3] = Ps[(r + 8) * AT_S + kk + 4 + (lane & 3)];
#pragma unroll
            for (int nt = 0; nt < 8; nt++) {
                uint32_t bb[2];
                int c = nt * 8 + (lane >> 2);
                bb[0] = Vt[c * AT_S + kk + (lane & 3)];
                bb[1] = Vt[c * AT_S + kk + 4 + (lane & 3)];
                mma_tf32(oacc[nt], a, bb);
            }
        }
    }

    // finalize
    float inv0 = 1.f / l0, inv1 = 1.f / l1;
    float* Ob = O + ((size_t)b * Lq + qt * 64 + qr) * C_DIM + h * HDIM;
#pragma unroll
    for (int nt = 0; nt < 8; nt++) {
        int c = nt * 8 + ((lane & 3) << 1);
        *(float2*)(Ob + c) = make_float2(oacc[nt][0] * inv0, oacc[nt][1] * inv0);
        *(float2*)(Ob + (size_t)8 * C_DIM + c) =
            make_float2(oacc[nt][2] * inv1, oacc[nt][3] * inv1);
    }
}

// ---------------- LayerNorm kernels (width 256, no affine) ----------------
__global__ void ln_concat_kernel(const float* __restrict__ x, const float* __restrict__ t,
                                 float* __restrict__ h)
{
    int row = blockIdx.x, c = threadIdx.x;
    float v = t[(size_t)row * C_DIM + c];
    __shared__ float shs[8], shq[8];
    float s = v, q = v * v;
#pragma unroll
    for (int o = 16; o > 0; o >>= 1) {
        s += __shfl_xor_sync(0xffffffffu, s, o);
        q += __shfl_xor_sync(0xffffffffu, q, o);
    }
    if ((c & 31) == 0) { shs[c >> 5] = s; shq[c >> 5] = q; }
    __syncthreads();
    if (c < 32) {
        s = (c < 8) ? shs[c] : 0.f;
        q = (c < 8) ? shq[c] : 0.f;
#pragma unroll
        for (int o = 4; o > 0; o >>= 1) {
            s += __shfl_xor_sync(0xffffffffu, s, o);
            q += __shfl_xor_sync(0xffffffffu, q, o);
        }
        if (c == 0) { shs[0] = s; shq[0] = q; }
    }
    __syncthreads();
    float mean = shs[0] * (1.f / 256.f);
    float var  = shq[0] * (1.f / 256.f) - mean * mean;
    float y = (v - mean) * rsqrtf(var + 1e-5f);
    h[(size_t)row * 512 + c]       = x[(size_t)row * C_DIM + c];
    h[(size_t)row * 512 + 256 + c] = y;
}

__global__ void ln_add_kernel(const float* __restrict__ x, const float* __restrict__ t,
                              float* __restrict__ outp)
{
    int row = blockIdx.x, c = threadIdx.x;
    float v = t[(size_t)row * C_DIM + c];
    __shared__ float shs[8], shq[8];
    float s = v, q = v * v;
#pragma unroll
    for (int o = 16; o > 0; o >>= 1) {
        s += __shfl_xor_sync(0xffffffffu, s, o);
        q += __shfl_xor_sync(0xffffffffu, q, o);
    }
    if ((c & 31) == 0) { shs[c >> 5] = s; shq[c >> 5] = q; }
    __syncthreads();
    if (c < 32) {
        s = (c < 8) ? shs[c] : 0.f;
        q = (c < 8) ? shq[c] : 0.f;
#pragma unroll
        for (int o = 4; o > 0; o >>= 1) {
            s += __shfl_xor_sync(0xffffffffu, s, o);
            q += __shfl_xor_sync(0xffffffffu, q, o);
        }
        if (c == 0) { shs[0] = s; shq[0] = q; }
    }
    __syncthreads();
    float mean = shs[0] * (1.f / 256.f);
    float var  = shq[0] * (1.f / 256.f) - mean * mean;
    float y = (v - mean) * rsqrtf(var + 1e-5f);
    outp[(size_t)row * C_DIM + c] = x[(size_t)row * C_DIM + c] + y;
}

__global__ void add_kernel(float* __restrict__ x, const float* __restrict__ a, int n)
{
    int i = blockIdx.x * 256 + threadIdx.x;
    if (i < n) x[i] += a[i];
}

__global__ void gather_kernel(const float* __restrict__ feat, const int* __restrict__ idx,
                              float* __restrict__ outp, int N, int Lp, int maskNum)
{
    int row = blockIdx.x;
    int g = row / Lp;
    int b = g / maskNum;
    int i = idx[row];
    int c = threadIdx.x;
    float val = 0.f;
    if (i >= 0 && i < N) val = feat[((size_t)b * N + i) * C_DIM + c];
    outp[(size_t)row * C_DIM + c] = val;
}

// ---------------- host orchestration ----------------
static void gemm(const float* A, const float* B, float* C, int M, int N, int K, int relu)
{
    dim3 g(N / 64, M / 128);
    gemm_kernel<<<g, 256>>>(A, B, C, M, N, K, relu);
}

struct Scr { float *q, *k, *v, *o, *t2, *h, *t1; };

static void attn_layer(const float* x, const float* src, float* outp,
                       int bs, int Lq, int Lkv, int li,
                       const float* qWA, const float* kWA, const float* vWA,
                       const float* mWA, const float* w1A, const float* w2A,
                       const Scr& S)
{
    int Mq = bs * Lq, Mkv = bs * Lkv;
    const float* qW = qWA + (size_t)li * 256 * 256;
    const float* kW = kWA + (size_t)li * 256 * 256;
    const float* vW = vWA + (size_t)li * 256 * 256;
    const float* mW = mWA + (size_t)li * 256 * 256;
    const float* w1 = w1A + (size_t)li * 512 * 512;
    const float* w2 = w2A + (size_t)li * 512 * 256;

    gemm(x,   qW, S.q, Mq,  256, 256, 0);
    gemm(src, kW, S.k, Mkv, 256, 256, 0);
    gemm(src, vW, S.v, Mkv, 256, 256, 0);
    attn_kernel<<<dim3(Lq / 64, NHEAD, bs), 128, ATTN_SMEM_BYTES>>>(S.q, S.k, S.v, S.o, Lq, Lkv);
    gemm(S.o, mW, S.t2, Mq, 256, 256, 0);
    ln_concat_kernel<<<Mq, 256>>>(x, S.t2, S.h);
    gemm(S.h,  w1, S.t1, Mq, 512, 512, 1);   // fused ReLU
    gemm(S.t1, w2, S.t2, Mq, 256, 512, 0);
    ln_add_kernel<<<Mq, 256>>>(x, S.t2, outp);
}

extern "C" void kernel_launch(void* const* d_in, const int* in_sizes, int n_in,
                              void* d_out, int out_size)
{
    (void)in_sizes; (void)out_size;
    const float* in_srcF = (const float*)d_in[0];
    const float* in_tgtF = (const float*)d_in[1];
    const int*   si      = (const int*)  d_in[6];
    const int*   ti      = (const int*)  d_in[7];
    const float* src2d   = (const float*)d_in[11];
    const float* tgt2d   = (const float*)d_in[12];
    const float* w2A   = (const float*)d_in[n_in - 1];
    const float* w1A   = (const float*)d_in[n_in - 2];
    const float* mWA   = (const float*)d_in[n_in - 3];
    const float* vWA   = (const float*)d_in[n_in - 4];
    const float* kWA   = (const float*)d_in[n_in - 5];
    const float* qWA   = (const float*)d_in[n_in - 6];
    const float* dinoW = (const float*)d_in[n_in - 7];
    float* out = (float*)d_out;

    float *featS, *featT, *projS, *projT, *qb, *kb, *vb, *ob, *t2, *hb, *t1, *ssub, *tsub;
    cudaGetSymbolAddress((void**)&featS, g_featS);
    cudaGetSymbolAddress((void**)&featT, g_featT);
    cudaGetSymbolAddress((void**)&projS, g_projS);
    cudaGetSymbolAddress((void**)&projT, g_projT);
    cudaGetSymbolAddress((void**)&qb, g_q);
    cudaGetSymbolAddress((void**)&kb, g_k);
    cudaGetSymbolAddress((void**)&vb, g_v);
    cudaGetSymbolAddress((void**)&ob, g_o);
    cudaGetSymbolAddress((void**)&t2, g_t2);
    cudaGetSymbolAddress((void**)&hb, g_h);
    cudaGetSymbolAddress((void**)&t1, g_t1);
    cudaGetSymbolAddress((void**)&ssub, g_ssub);
    cudaGetSymbolAddress((void**)&tsub, g_tsub);

    cudaFuncSetAttribute(attn_kernel, cudaFuncAttributeMaxDynamicSharedMemorySize,
                         ATTN_SMEM_BYTES);

    Scr S{qb, kb, vb, ob, t2, hb, t1};
    const int Mmain = 2 * 2048;
    const size_t featBytes = (size_t)Mmain * 256 * sizeof(float);

    cudaMemcpyAsync(featS, in_srcF, featBytes, cudaMemcpyDeviceToDevice, 0);
    cudaMemcpyAsync(featT, in_tgtF, featBytes, cudaMemcpyDeviceToDevice, 0);

    // 2D-feature projection (4096 rows, 384 -> 256)
    gemm(src2d, dinoW, projS, Mmain, 256, 384, 0);
    gemm(tgt2d, dinoW, projT, Mmain, 256, 384, 0);

    // layer 0: self
    add_kernel<<<Mmain * 256 / 256, 256>>>(featS, projS, Mmain * 256);
    add_kernel<<<Mmain * 256 / 256, 256>>>(featT, projT, Mmain * 256);
    attn_layer(featS, featS, featS, 2, 2048, 2048, 0, qWA, kWA, vWA, mWA, w1A, w2A, S);
    attn_layer(featT, featT, featT, 2, 2048, 2048, 0, qWA, kWA, vWA, mWA, w1A, w2A, S);
    // layer 1: cross (tgt uses UPDATED src)
    attn_layer(featS, featT, featS, 2, 2048, 2048, 1, qWA, kWA, vWA, mWA, w1A, w2A, S);
    attn_layer(featT, featS, featT, 2, 2048, 2048, 1, qWA, kWA, vWA, mWA, w1A, w2A, S);
    // layer 2: self
    add_kernel<<<Mmain * 256 / 256, 256>>>(featS, projS, Mmain * 256);
    add_kernel<<<Mmain * 256 / 256, 256>>>(featT, projT, Mmain * 256);
    attn_layer(featS, featS, featS, 2, 2048, 2048, 2, qWA, kWA, vWA, mWA, w1A, w2A, S);
    attn_layer(featT, featT, featT, 2, 2048, 2048, 2, qWA, kWA, vWA, mWA, w1A, w2A, S);
    // layer 3: cross
    attn_layer(featS, featT, featS, 2, 2048, 2048, 3, qWA, kWA, vWA, mWA, w1A, w2A, S);
    attn_layer(featT, featS, featT, 2, 2048, 2048, 3, qWA, kWA, vWA, mWA, w1A, w2A, S);

    // layer 4: semantic_subspace_cross
    gather_kernel<<<16 * 512, 256>>>(featS, si, ssub, 2048, 512, 8);
    gather_kernel<<<16 * 512, 256>>>(featT, ti, tsub, 2048, 512, 8);
    float* outSsem = out + (size_t)2 * 1048576;
    float* outTsem = outSsem + (size_t)16 * 512 * 256;
    attn_layer(ssub, tsub, outSsem, 16, 512, 512, 4, qWA, kWA, vWA, mWA, w1A, w2A, S);
    attn_layer(tsub, ssub, outTsem, 16, 512, 512, 4, qWA, kWA, vWA, mWA, w1A, w2A, S);

    cudaMemcpyAsync(out,           featS, featBytes, cudaMemcpyDeviceToDevice, 0);
    cudaMemcpyAsync(out + 1048576, featT, featBytes, cudaMemcpyDeviceToDevice, 0);
}

// round 7
// speedup vs baseline: 3.2563x; 1.9792x over previous
#include <cuda_runtime.h>
#include <math.h>
#include <stdint.h>

#define C_DIM 256
#define NHEAD 4

// ---------------- device scratch (no allocation allowed) ----------------
__device__ float g_featS[2*2048*256];
__device__ float g_featT[2*2048*256];
__device__ float g_projS[2*2048*256];
__device__ float g_projT[2*2048*256];
__device__ float g_qkv[8192*768];
__device__ float g_o [8192*256];
__device__ float g_t2[8192*256];
__device__ float g_h [8192*512];
__device__ float g_t1[8192*512];
__device__ float g_ssub[8192*256];
__device__ float g_tsub[8192*256];
__device__ float g_wpack[5*256*768];   // packed [qW|kW|vW] per layer

// ---------------- helpers ----------------
__device__ __forceinline__ uint32_t f2tf32(float x) {
    uint32_t r;
    asm("cvt.rna.tf32.f32 %0, %1;" : "=r"(r) : "f"(x));
    return r;
}
__device__ __forceinline__ void mma_tf32(float (&d)[4], const uint32_t (&a)[4],
                                         const uint32_t (&b)[2]) {
    asm volatile(
        "mma.sync.aligned.m16n8k8.row.col.f32.tf32.tf32.f32 "
        "{%0,%1,%2,%3}, {%4,%5,%6,%7}, {%8,%9}, {%0,%1,%2,%3};"
        : "+f"(d[0]), "+f"(d[1]), "+f"(d[2]), "+f"(d[3])
        : "r"(a[0]), "r"(a[1]), "r"(a[2]), "r"(a[3]), "r"(b[0]), "r"(b[1]));
}
__device__ __forceinline__ void cp16(uint32_t smem_dst, const void* gsrc) {
    asm volatile("cp.async.cg.shared.global [%0], [%1], 16;"
                 :: "r"(smem_dst), "l"(gsrc));
}
#define CP_COMMIT() asm volatile("cp.async.commit_group;" ::: "memory")
#define CP_WAIT(n)  asm volatile("cp.async.wait_group %0;" :: "n"(n) : "memory")

// ---------------- TF32 GEMM, double-buffered ------------------------------
// C[M,N](ldc) = A[M,K] @ B[K,N](ldb). flags: 1=ReLU, 2=round output to tf32.
// M%128==0, N%64==0, K%32==0. 256 threads, tile 128x64x32, 8 warps 32x32.
#define GAS 36
#define GBS 72
#define GEMM_BUF_U32 (128*GAS + 32*GBS)            // 6912
#define GEMM_SMEM_BYTES (2 * GEMM_BUF_U32 * 4)     // 55296

__global__ __launch_bounds__(256, 1)
void gemm_kernel(const float* __restrict__ A, const float* __restrict__ B,
                 float* __restrict__ Cc, int M, int N, int K,
                 int ldb, int ldc, int flags)
{
    extern __shared__ uint32_t gsm[];
    int tid = threadIdx.x;
    int lane = tid & 31, wid = tid >> 5;
    int wm = (wid & 3) * 32, wn = (wid >> 2) * 32;
    int rowBase = blockIdx.y << 7, colBase = blockIdx.x << 6;

    int ar = tid >> 3, ac = (tid & 7) << 2;     // A fill: 4 passes of 32 rows
    int br = tid >> 4, bc = (tid & 15) << 2;    // B fill: 2 passes of 16 rows
    const float* Ap = A + (size_t)(rowBase + ar) * K + ac;
    const float* Bp = B + (size_t)br * ldb + colBase + bc;

    float4 a_st[4];
    float4 b_st[2];
#pragma unroll
    for (int p = 0; p < 4; p++) a_st[p] = *(const float4*)(Ap + (size_t)p * 32 * K);
#pragma unroll
    for (int p = 0; p < 2; p++) b_st[p] = *(const float4*)(Bp + (size_t)p * 16 * ldb);

    // store chunk 0 into buffer 0
    {
        uint32_t* As = gsm;
        uint32_t* Bs = gsm + 128 * GAS;
#pragma unroll
        for (int p = 0; p < 4; p++) {
            uint4 u;
            u.x = f2tf32(a_st[p].x); u.y = f2tf32(a_st[p].y);
            u.z = f2tf32(a_st[p].z); u.w = f2tf32(a_st[p].w);
            *(uint4*)&As[(p * 32 + ar) * GAS + ac] = u;
        }
#pragma unroll
        for (int p = 0; p < 2; p++) {
            uint4 u;
            u.x = f2tf32(b_st[p].x); u.y = f2tf32(b_st[p].y);
            u.z = f2tf32(b_st[p].z); u.w = f2tf32(b_st[p].w);
            *(uint4*)&Bs[(p * 16 + br) * GBS + bc] = u;
        }
    }
    __syncthreads();

    float acc[2][4][4] = {};
    int buf = 0;
    for (int k0 = 0; k0 < K; k0 += 32) {
        bool more = (k0 + 32 < K);
        if (more) {
#pragma unroll
            for (int p = 0; p < 4; p++)
                a_st[p] = *(const float4*)(Ap + k0 + 32 + (size_t)p * 32 * K);
#pragma unroll
            for (int p = 0; p < 2; p++)
                b_st[p] = *(const float4*)(Bp + (size_t)(k0 + 32 + p * 16) * ldb);
        }
        const uint32_t* As = gsm + buf * GEMM_BUF_U32;
        const uint32_t* Bs = As + 128 * GAS;
#pragma unroll
        for (int kt = 0; kt < 4; kt++) {
            int kk = kt * 8;
            uint32_t a[2][4];
#pragma unroll
            for (int mt = 0; mt < 2; mt++) {
                int r = wm + mt * 16 + (lane >> 2);
                a[mt][0] = As[r * GAS + kk + (lane & 3)];
                a[mt][1] = As[(r + 8) * GAS + kk + (lane & 3)];
                a[mt][2] = As[r * GAS + kk + 4 + (lane & 3)];
                a[mt][3] = As[(r + 8) * GAS + kk + 4 + (lane & 3)];
            }
#pragma unroll
            for (int nt = 0; nt < 4; nt++) {
                uint32_t b[2];
                int c = wn + nt * 8 + (lane >> 2);
                b[0] = Bs[(kk + (lane & 3)) * GBS + c];
                b[1] = Bs[(kk + 4 + (lane & 3)) * GBS + c];
                mma_tf32(acc[0][nt], a[0], b);
                mma_tf32(acc[1][nt], a[1], b);
            }
        }
        if (more) {
            uint32_t* As2 = gsm + (buf ^ 1) * GEMM_BUF_U32;
            uint32_t* Bs2 = As2 + 128 * GAS;
#pragma unroll
            for (int p = 0; p < 4; p++) {
                uint4 u;
                u.x = f2tf32(a_st[p].x); u.y = f2tf32(a_st[p].y);
                u.z = f2tf32(a_st[p].z); u.w = f2tf32(a_st[p].w);
                *(uint4*)&As2[(p * 32 + ar) * GAS + ac] = u;
            }
#pragma unroll
            for (int p = 0; p < 2; p++) {
                uint4 u;
                u.x = f2tf32(b_st[p].x); u.y = f2tf32(b_st[p].y);
                u.z = f2tf32(b_st[p].z); u.w = f2tf32(b_st[p].w);
                *(uint4*)&Bs2[(p * 16 + br) * GBS + bc] = u;
            }
        }
        __syncthreads();
        buf ^= 1;
    }

#pragma unroll
    for (int mt = 0; mt < 2; mt++) {
        int r0 = rowBase + wm + mt * 16 + (lane >> 2);
#pragma unroll
        for (int nt = 0; nt < 4; nt++) {
            int c = colBase + wn + nt * 8 + ((lane & 3) << 1);
            float v[4] = {acc[mt][nt][0], acc[mt][nt][1], acc[mt][nt][2], acc[mt][nt][3]};
            if (flags & 1) {
#pragma unroll
                for (int e = 0; e < 4; e++) v[e] = fmaxf(v[e], 0.f);
            }
            if (flags & 2) {
#pragma unroll
                for (int e = 0; e < 4; e++) v[e] = __uint_as_float(f2tf32(v[e]));
            }
            *(float2*)(Cc + (size_t)r0 * ldc + c)       = make_float2(v[0], v[1]);
            *(float2*)(Cc + (size_t)(r0 + 8) * ldc + c) = make_float2(v[2], v[3]);
        }
    }
}

// ---------------- TF32 flash attention, d=64, q-tile 128, kv-tile 64 --------
// QKV packed: row stride 768; Q cols [0,256), K [256,512), V [512,768)
// (head h at +h*64 in each). O: (bs, Lq, 256). Inputs pre-rounded to tf32.
// grid = (Lq/128, NHEAD, bs), 128 threads (4 warps x 32 q-rows).
#define QST 68
#define VST 72
#define SM_QS 0
#define SM_PS (128*QST)
#define SM_KS (2*128*QST)
#define SM_VS (SM_KS + 2*64*QST)
#define ATTN_SMEM_BYTES ((SM_VS + 2*64*VST) * 4)   // 141312

__global__ __launch_bounds__(128, 1)
void attn_kernel(const float* __restrict__ QKV, float* __restrict__ O,
                 int Lq, int Lkv)
{
    extern __shared__ uint32_t sm[];
    uint32_t smaddr = (uint32_t)__cvta_generic_to_shared(sm);
    int tid = threadIdx.x;
    int lane = tid & 31, wid = tid >> 5;
    int l4 = lane >> 2, la3 = lane & 3;
    int qt = blockIdx.x, h = blockIdx.y, b = blockIdx.z;
    int wq = wid * 32;

    const float* Qb = QKV + ((size_t)b * Lq + qt * 128) * 768 + h * 64;
    const float* Kb = QKV + (size_t)b * Lkv * 768 + 256 + h * 64;
    const float* Vb = Kb + 256;

    // issue Q (128x64) + K/V tile 0 as async group 0
#pragma unroll
    for (int p = 0; p < 16; p++) {
        int idx = p * 128 + tid;
        int r = idx >> 4, c = (idx & 15) << 2;
        cp16(smaddr + (SM_QS + r * QST + c) * 4, Qb + (size_t)r * 768 + c);
    }
#pragma unroll
    for (int p = 0; p < 8; p++) {
        int idx = p * 128 + tid;
        int r = idx >> 4, c = (idx & 15) << 2;
        cp16(smaddr + (SM_KS + r * QST + c) * 4, Kb + (size_t)r * 768 + c);
        cp16(smaddr + (SM_VS + r * VST + c) * 4, Vb + (size_t)r * 768 + c);
    }
    CP_COMMIT();

    float oacc[2][8][4] = {};
    float mrow[4] = {-INFINITY, -INFINITY, -INFINITY, -INFINITY};
    float lrow[4] = {0.f, 0.f, 0.f, 0.f};
    int buf = 0;
    int nTiles = Lkv >> 6;

    for (int t = 0; t < nTiles; t++) {
        __syncthreads();                    // all warps done with buf^1
        if (t + 1 < nTiles) {
            int s0 = (t + 1) * 64;
            int nb = buf ^ 1;
#pragma unroll
            for (int p = 0; p < 8; p++) {
                int idx = p * 128 + tid;
                int r = idx >> 4, c = (idx & 15) << 2;
                cp16(smaddr + (SM_KS + nb * 64 * QST + r * QST + c) * 4,
                     Kb + (size_t)(s0 + r) * 768 + c);
                cp16(smaddr + (SM_VS + nb * 64 * VST + r * VST + c) * 4,
                     Vb + (size_t)(s0 + r) * 768 + c);
            }
            CP_COMMIT();
            CP_WAIT(1);
        } else {
            CP_WAIT(0);
        }
        __syncthreads();

        const uint32_t* Qs = sm + SM_QS;
        const uint32_t* Ks = sm + SM_KS + buf * 64 * QST;
        const uint32_t* Vs = sm + SM_VS + buf * 64 * VST;
        uint32_t* Ps = sm + SM_PS;

        // ---- S = Q @ K^T ----
        float sacc[2][8][4] = {};
#pragma unroll
        for (int kt = 0; kt < 8; kt++) {
            int kk = kt * 8;
            uint32_t a[2][4];
#pragma unroll
            for (int mt = 0; mt < 2; mt++) {
                int r = wq + mt * 16 + l4;
                a[mt][0] = Qs[r * QST + kk + la3];
                a[mt][1] = Qs[(r + 8) * QST + kk + la3];
                a[mt][2] = Qs[r * QST + kk + 4 + la3];
                a[mt][3] = Qs[(r + 8) * QST + kk + 4 + la3];
            }
#pragma unroll
            for (int nt = 0; nt < 8; nt++) {
                uint32_t bb[2];
                int cc = nt * 8 + l4;
                bb[0] = Ks[cc * QST + kk + la3];
                bb[1] = Ks[cc * QST + kk + 4 + la3];
                mma_tf32(sacc[0][nt], a[0], bb);
                mma_tf32(sacc[1][nt], a[1], bb);
            }
        }

        // ---- online softmax over 4 owned rows ----
        float mx[4] = {-INFINITY, -INFINITY, -INFINITY, -INFINITY};
#pragma unroll
        for (int mt = 0; mt < 2; mt++)
#pragma unroll
            for (int nt = 0; nt < 8; nt++) {
#pragma unroll
                for (int e = 0; e < 4; e++) sacc[mt][nt][e] *= 0.125f;
                mx[2*mt]   = fmaxf(mx[2*mt],   fmaxf(sacc[mt][nt][0], sacc[mt][nt][1]));
                mx[2*mt+1] = fmaxf(mx[2*mt+1], fmaxf(sacc[mt][nt][2], sacc[mt][nt][3]));
            }
        float mn[4], sc[4], sum[4];
#pragma unroll
        for (int j = 0; j < 4; j++) {
            mx[j] = fmaxf(mx[j], __shfl_xor_sync(0xffffffffu, mx[j], 1));
            mx[j] = fmaxf(mx[j], __shfl_xor_sync(0xffffffffu, mx[j], 2));
            mn[j] = fmaxf(mrow[j], mx[j]);
            sc[j] = __expf(mrow[j] - mn[j]);
            sum[j] = 0.f;
        }
#pragma unroll
        for (int mt = 0; mt < 2; mt++) {
            int row0 = wq + mt * 16 + l4;
#pragma unroll
            for (int nt = 0; nt < 8; nt++) {
                float p0 = __expf(sacc[mt][nt][0] - mn[2*mt]);
                float p1 = __expf(sacc[mt][nt][1] - mn[2*mt]);
                float p2 = __expf(sacc[mt][nt][2] - mn[2*mt+1]);
                float p3 = __expf(sacc[mt][nt][3] - mn[2*mt+1]);
                sum[2*mt]   += p0 + p1;
                sum[2*mt+1] += p2 + p3;
                uint2 u0 = make_uint2(f2tf32(p0), f2tf32(p1));
                uint2 u1 = make_uint2(f2tf32(p2), f2tf32(p3));
                *(uint2*)&Ps[row0 * QST + nt * 8 + la3 * 2]       = u0;
                *(uint2*)&Ps[(row0 + 8) * QST + nt * 8 + la3 * 2] = u1;
            }
        }
#pragma unroll
        for (int j = 0; j < 4; j++) {
            sum[j] += __shfl_xor_sync(0xffffffffu, sum[j], 1);
            sum[j] += __shfl_xor_sync(0xffffffffu, sum[j], 2);
            lrow[j] = lrow[j] * sc[j] + sum[j];
            mrow[j] = mn[j];
        }
#pragma unroll
        for (int mt = 0; mt < 2; mt++)
#pragma unroll
            for (int nt = 0; nt < 8; nt++) {
                oacc[mt][nt][0] *= sc[2*mt];   oacc[mt][nt][1] *= sc[2*mt];
                oacc[mt][nt][2] *= sc[2*mt+1]; oacc[mt][nt][3] *= sc[2*mt+1];
            }
        __syncwarp();

        // ---- O += P @ V ----
#pragma unroll
        for (int kt = 0; kt < 8; kt++) {
            int kk = kt * 8;
            uint32_t a[2][4];
#pragma unroll
            for (int mt = 0; mt < 2; mt++) {
                int r = wq + mt * 16 + l4;
                a[mt][0] = Ps[r * QST + kk + la3];
                a[mt][1] = Ps[(r + 8) * QST + kk + la3];
                a[mt][2] = Ps[r * QST + kk + 4 + la3];
                a[mt][3] = Ps[(r + 8) * QST + kk + 4 + la3];
            }
#pragma unroll
            for (int nt = 0; nt < 8; nt++) {
                uint32_t bb[2];
                int cc = nt * 8 + l4;
                bb[0] = Vs[(kk + la3) * VST + cc];
                bb[1] = Vs[(kk + 4 + la3) * VST + cc];
                mma_tf32(oacc[0][nt], a[0], bb);
                mma_tf32(oacc[1][nt], a[1], bb);
            }
        }
        buf ^= 1;
    }

    // ---- finalize ----
    float inv[4];
#pragma unroll
    for (int j = 0; j < 4; j++) inv[j] = 1.f / lrow[j];
#pragma unroll
    for (int mt = 0; mt < 2; mt++) {
        int rg = qt * 128 + wq + mt * 16 + l4;
#pragma unroll
        for (int nt = 0; nt < 8; nt++) {
            int c = h * 64 + nt * 8 + la3 * 2;
            *(float2*)(O + ((size_t)b * Lq + rg) * C_DIM + c) =
                make_float2(oacc[mt][nt][0] * inv[2*mt], oacc[mt][nt][1] * inv[2*mt]);
            *(float2*)(O + ((size_t)b * Lq + rg + 8) * C_DIM + c) =
                make_float2(oacc[mt][nt][2] * inv[2*mt+1], oacc[mt][nt][3] * inv[2*mt+1]);
        }
    }
}

// ---------------- LayerNorm / misc kernels ----------------
__global__ void ln_concat_kernel(const float* __restrict__ x, const float* __restrict__ t,
                                 float* __restrict__ h)
{
    int row = blockIdx.x, c = threadIdx.x;
    float v = t[(size_t)row * C_DIM + c];
    __shared__ float shs[8], shq[8];
    float s = v, q = v * v;
#pragma unroll
    for (int o = 16; o > 0; o >>= 1) {
        s += __shfl_xor_sync(0xffffffffu, s, o);
        q += __shfl_xor_sync(0xffffffffu, q, o);
    }
    if ((c & 31) == 0) { shs[c >> 5] = s; shq[c >> 5] = q; }
    __syncthreads();
    if (c < 32) {
        s = (c < 8) ? shs[c] : 0.f;
        q = (c < 8) ? shq[c] : 0.f;
#pragma unroll
        for (int o = 4; o > 0; o >>= 1) {
            s += __shfl_xor_sync(0xffffffffu, s, o);
            q += __shfl_xor_sync(0xffffffffu, q, o);
        }
        if (c == 0) { shs[0] = s; shq[0] = q; }
    }
    __syncthreads();
    float mean = shs[0] * (1.f / 256.f);
    float var  = shq[0] * (1.f / 256.f) - mean * mean;
    float y = (v - mean) * rsqrtf(var + 1e-5f);
    h[(size_t)row * 512 + c]       = x[(size_t)row * C_DIM + c];
    h[(size_t)row * 512 + 256 + c] = y;
}

__global__ void ln_add_kernel(const float* __restrict__ x, const float* __restrict__ t,
                              float* __restrict__ outp)
{
    int row = blockIdx.x, c = threadIdx.x;
    float v = t[(size_t)row * C_DIM + c];
    __shared__ float shs[8], shq[8];
    float s = v, q = v * v;
#pragma unroll
    for (int o = 16; o > 0; o >>= 1) {
        s += __shfl_xor_sync(0xffffffffu, s, o);
        q += __shfl_xor_sync(0xffffffffu, q, o);
    }
    if ((c & 31) == 0) { shs[c >> 5] = s; shq[c >> 5] = q; }
    __syncthreads();
    if (c < 32) {
        s = (c < 8) ? shs[c] : 0.f;
        q = (c < 8) ? shq[c] : 0.f;
#pragma unroll
        for (int o = 4; o > 0; o >>= 1) {
            s += __shfl_xor_sync(0xffffffffu, s, o);
            q += __shfl_xor_sync(0xffffffffu, q, o);
        }
        if (c == 0) { shs[0] = s; shq[0] = q; }
    }
    __syncthreads();
    float mean = shs[0] * (1.f / 256.f);
    float var  = shq[0] * (1.f / 256.f) - mean * mean;
    float y = (v - mean) * rsqrtf(var + 1e-5f);
    outp[(size_t)row * C_DIM + c] = x[(size_t)row * C_DIM + c] + y;
}

__global__ void add_kernel(float* __restrict__ x, const float* __restrict__ a, int n)
{
    int i = blockIdx.x * 256 + threadIdx.x;
    if (i < n) x[i] += a[i];
}

__global__ void gather_kernel(const float* __restrict__ feat, const int* __restrict__ idx,
                              float* __restrict__ outp, int N, int Lp, int maskNum)
{
    int row = blockIdx.x;
    int g = row / Lp;
    int b = g / maskNum;
    int i = idx[row];
    int c = threadIdx.x;
    float val = 0.f;
    if (i >= 0 && i < N) val = feat[((size_t)b * N + i) * C_DIM + c];
    outp[(size_t)row * C_DIM + c] = val;
}

// ---------------- host orchestration ----------------
static void gemm(const float* A, const float* B, float* C, int M, int N, int K,
                 int ldb, int ldc, int flags)
{
    dim3 g(N / 64, M / 128);
    gemm_kernel<<<g, 256, GEMM_SMEM_BYTES>>>(A, B, C, M, N, K, ldb, ldc, flags);
}

struct Scr { float *qkv, *o, *t2, *h, *t1, *wpack; };

static void attn_layer(const float* x, const float* src, float* outp,
                       int bs, int Lq, int Lkv, int li,
                       const float* mWA, const float* w1A, const float* w2A,
                       const Scr& S)
{
    int Mq = bs * Lq, Mkv = bs * Lkv;
    const float* packL = S.wpack + (size_t)li * 256 * 768;
    const float* mW = mWA + (size_t)li * 256 * 256;
    const float* w1 = w1A + (size_t)li * 512 * 512;
    const float* w2 = w2A + (size_t)li * 512 * 256;

    if (x == src) {
        gemm(x, packL, S.qkv, Mq, 768, 256, 768, 768, 2);          // QKV fused
    } else {
        gemm(x,   packL,       S.qkv,       Mq,  256, 256, 768, 768, 2);
        gemm(src, packL + 256, S.qkv + 256, Mkv, 512, 256, 768, 768, 2);
    }
    attn_kernel<<<dim3(Lq / 128, NHEAD, bs), 128, ATTN_SMEM_BYTES>>>(S.qkv, S.o, Lq, Lkv);
    gemm(S.o, mW, S.t2, Mq, 256, 256, 256, 256, 0);
    ln_concat_kernel<<<Mq, 256>>>(x, S.t2, S.h);
    gemm(S.h,  w1, S.t1, Mq, 512, 512, 512, 512, 1);               // fused ReLU
    gemm(S.t1, w2, S.t2, Mq, 256, 512, 256, 256, 0);
    ln_add_kernel<<<Mq, 256>>>(x, S.t2, outp);
}

extern "C" void kernel_launch(void* const* d_in, const int* in_sizes, int n_in,
                              void* d_out, int out_size)
{
    (void)in_sizes; (void)out_size;
    const float* in_srcF = (const float*)d_in[0];
    const float* in_tgtF = (const float*)d_in[1];
    const int*   si      = (const int*)  d_in[6];
    const int*   ti      = (const int*)  d_in[7];
    const float* src2d   = (const float*)d_in[11];
    const float* tgt2d   = (const float*)d_in[12];
    const float* w2A   = (const float*)d_in[n_in - 1];
    const float* w1A   = (const float*)d_in[n_in - 2];
    const float* mWA   = (const float*)d_in[n_in - 3];
    const float* vWA   = (const float*)d_in[n_in - 4];
    const float* kWA   = (const float*)d_in[n_in - 5];
    const float* qWA   = (const float*)d_in[n_in - 6];
    const float* dinoW = (const float*)d_in[n_in - 7];
    float* out = (float*)d_out;

    float *featS, *featT, *projS, *projT, *qkv, *ob, *t2, *hb, *t1, *ssub, *tsub, *wpack;
    cudaGetSymbolAddress((void**)&featS, g_featS);
    cudaGetSymbolAddress((void**)&featT, g_featT);
    cudaGetSymbolAddress((void**)&projS, g_projS);
    cudaGetSymbolAddress((void**)&projT, g_projT);
    cudaGetSymbolAddress((void**)&qkv, g_qkv);
    cudaGetSymbolAddress((void**)&ob, g_o);
    cudaGetSymbolAddress((void**)&t2, g_t2);
    cudaGetSymbolAddress((void**)&hb, g_h);
    cudaGetSymbolAddress((void**)&t1, g_t1);
    cudaGetSymbolAddress((void**)&ssub, g_ssub);
    cudaGetSymbolAddress((void**)&tsub, g_tsub);
    cudaGetSymbolAddress((void**)&wpack, g_wpack);

    cudaFuncSetAttribute(attn_kernel, cudaFuncAttributeMaxDynamicSharedMemorySize,
                         ATTN_SMEM_BYTES);
    cudaFuncSetAttribute(gemm_kernel, cudaFuncAttributeMaxDynamicSharedMemorySize,
                         GEMM_SMEM_BYTES);

    // pack [qW|kW|vW] per layer into [256][768]
    for (int li = 0; li < 5; li++) {
        float* dst = wpack + (size_t)li * 256 * 768;
        const size_t woff = (size_t)li * 256 * 256;
        cudaMemcpy2DAsync(dst,       768 * 4, qWA + woff, 256 * 4, 256 * 4, 256,
                          cudaMemcpyDeviceToDevice, 0);
        cudaMemcpy2DAsync(dst + 256, 768 * 4, kWA + woff, 256 * 4, 256 * 4, 256,
                          cudaMemcpyDeviceToDevice, 0);
        cudaMemcpy2DAsync(dst + 512, 768 * 4, vWA + woff, 256 * 4, 256 * 4, 256,
                          cudaMemcpyDeviceToDevice, 0);
    }

    Scr S{qkv, ob, t2, hb, t1, wpack};
    const int Mmain = 2 * 2048;
    const size_t featBytes = (size_t)Mmain * 256 * sizeof(float);

    cudaMemcpyAsync(featS, in_srcF, featBytes, cudaMemcpyDeviceToDevice, 0);
    cudaMemcpyAsync(featT, in_tgtF, featBytes, cudaMemcpyDeviceToDevice, 0);

    // 2D-feature projection (4096 rows, 384 -> 256)
    gemm(src2d, dinoW, projS, Mmain, 256, 384, 256, 256, 0);
    gemm(tgt2d, dinoW, projT, Mmain, 256, 384, 256, 256, 0);

    // layer 0: self
    add_kernel<<<Mmain * 256 / 256, 256>>>(featS, projS, Mmain * 256);
    add_kernel<<<Mmain * 256 / 256, 256>>>(featT, projT, Mmain * 256);
    attn_layer(featS, featS, featS, 2, 2048, 2048, 0, mWA, w1A, w2A, S);
    attn_layer(featT, featT, featT, 2, 2048, 2048, 0, mWA, w1A, w2A, S);
    // layer 1: cross (tgt uses UPDATED src)
    attn_layer(featS, featT, featS, 2, 2048, 2048, 1, mWA, w1A, w2A, S);
    attn_layer(featT, featS, featT, 2, 2048, 2048, 1, mWA, w1A, w2A, S);
    // layer 2: self
    add_kernel<<<Mmain * 256 / 256, 256>>>(featS, projS, Mmain * 256);
    add_kernel<<<Mmain * 256 / 256, 256>>>(featT, projT, Mmain * 256);
    attn_layer(featS, featS, featS, 2, 2048, 2048, 2, mWA, w1A, w2A, S);
    attn_layer(featT, featT, featT, 2, 2048, 2048, 2, mWA, w1A, w2A, S);
    // layer 3: cross
    attn_layer(featS, featT, featS, 2, 2048, 2048, 3, mWA, w1A, w2A, S);
    attn_layer(featT, featS, featT, 2, 2048, 2048, 3, mWA, w1A, w2A, S);

    // layer 4: semantic_subspace_cross
    gather_kernel<<<16 * 512, 256>>>(featS, si, ssub, 2048, 512, 8);
    gather_kernel<<<16 * 512, 256>>>(featT, ti, tsub, 2048, 512, 8);
    float* outSsem = out + (size_t)2 * 1048576;
    float* outTsem = outSsem + (size_t)16 * 512 * 256;
    attn_layer(ssub, tsub, outSsem, 16, 512, 512, 4, mWA, w1A, w2A, S);
    attn_layer(tsub, ssub, outTsem, 16, 512, 512, 4, mWA, w1A, w2A, S);

    cudaMemcpyAsync(out,           featS, featBytes, cudaMemcpyDeviceToDevice, 0);
    cudaMemcpyAsync(out + 1048576, featT, featBytes, cudaMemcpyDeviceToDevice, 0);
}

// round 9
// speedup vs baseline: 4.5808x; 1.4067x over previous
#include <cuda_runtime.h>
#include <cuda_fp16.h>
#include <math.h>
#include <stdint.h>

#define C_DIM 256
#define NHEAD 4

// ---------------- device scratch (no allocation allowed) ----------------
__device__ float  g_featS[2*2048*256];
__device__ float  g_featT[2*2048*256];
__device__ float  g_projS[2*2048*256];
__device__ float  g_projT[2*2048*256];
__device__ __half g_qkv[8192*768];
__device__ float  g_o [8192*256];
__device__ float  g_t2[8192*256];
__device__ float  g_h [8192*512];
__device__ float  g_t1[8192*512];
__device__ float  g_ssub[8192*256];
__device__ float  g_tsub[8192*256];
__device__ float  g_wpack[5*256*768];   // packed [qW|kW|vW] per layer

// ---------------- helpers ----------------
__device__ __forceinline__ uint32_t packh2(float a, float b) {
    __half2 h = __floats2half2_rn(a, b);       // .x = a (low), .y = b (high)
    return *(uint32_t*)&h;
}
__device__ __forceinline__ void mma_f16(float (&d)[4], const uint32_t (&a)[4],
                                        const uint32_t (&b)[2]) {
    asm volatile(
        "mma.sync.aligned.m16n8k16.row.col.f32.f16.f16.f32 "
        "{%0,%1,%2,%3}, {%4,%5,%6,%7}, {%8,%9}, {%0,%1,%2,%3};"
        : "+f"(d[0]), "+f"(d[1]), "+f"(d[2]), "+f"(d[3])
        : "r"(a[0]), "r"(a[1]), "r"(a[2]), "r"(a[3]), "r"(b[0]), "r"(b[1]));
}

// ---------------- FP16 GEMM, double-buffered ------------------------------
// C[M,N](ldc) = A[M,K] @ B[K,N](ldb). flags: 1=ReLU, 2=half output.
// M%128==0, N%64==0, K%32==0. 256 threads, tile 128x64x32, 8 warps 32x32.
// As2: u32[r][k/2] stride 20 (=4 mod 32); Bs2: k-pair interleaved u32[k/2][n]
// stride 72 (=8 mod 32). Fragment loads provably conflict-free.
#define GAS2 20
#define GBS2 72
#define GBUF (128*GAS2 + 16*GBS2)              // 3712 u32
#define GEMM_SMEM_BYTES (2 * GBUF * 4)         // 29696

__global__ __launch_bounds__(256, 1)
void gemm_kernel(const float* __restrict__ A, const float* __restrict__ B,
                 void* __restrict__ Cv, int M, int N, int K,
                 int ldb, int ldc, int flags)
{
    extern __shared__ uint32_t gsm[];
    int tid = threadIdx.x;
    int lane = tid & 31, wid = tid >> 5;
    int l4 = lane >> 2, la3 = lane & 3;
    int wm = (wid & 3) * 32, wn = (wid >> 2) * 32;
    int rowBase = blockIdx.y << 7, colBase = blockIdx.x << 6;

    int ar = tid >> 3, acu = (tid & 7) * 2;    // A fill: 4 passes of 32 rows
    int br2 = tid >> 4, bc = (tid & 15) * 4;   // B fill: k-pair rows
    const float* Ap = A + (size_t)(rowBase + ar) * K + (tid & 7) * 4;
    const float* Bp = B + (size_t)(2 * br2) * ldb + colBase + bc;

    float4 a_st[4];
    float4 b_st[2];
#pragma unroll
    for (int p = 0; p < 4; p++) a_st[p] = *(const float4*)(Ap + (size_t)p * 32 * K);
    b_st[0] = *(const float4*)(Bp);
    b_st[1] = *(const float4*)(Bp + ldb);

    {   // store chunk 0 into buffer 0
        uint32_t* As = gsm;
        uint32_t* Bs = gsm + 128 * GAS2;
#pragma unroll
        for (int p = 0; p < 4; p++) {
            int r = p * 32 + ar;
            As[r * GAS2 + acu]     = packh2(a_st[p].x, a_st[p].y);
            As[r * GAS2 + acu + 1] = packh2(a_st[p].z, a_st[p].w);
        }
        uint4 o;
        o.x = packh2(b_st[0].x, b_st[1].x); o.y = packh2(b_st[0].y, b_st[1].y);
        o.z = packh2(b_st[0].z, b_st[1].z); o.w = packh2(b_st[0].w, b_st[1].w);
        *(uint4*)&Bs[br2 * GBS2 + bc] = o;
    }
    __syncthreads();

    float acc[2][4][4] = {};
    int buf = 0;
    for (int k0 = 0; k0 < K; k0 += 32) {
        bool more = (k0 + 32 < K);
        if (more) {
#pragma unroll
            for (int p = 0; p < 4; p++)
                a_st[p] = *(const float4*)(Ap + k0 + 32 + (size_t)p * 32 * K);
            b_st[0] = *(const float4*)(Bp + (size_t)(k0 + 32) * ldb);
            b_st[1] = *(const float4*)(Bp + (size_t)(k0 + 33) * ldb);
        }
        const uint32_t* As = gsm + buf * GBUF;
        const uint32_t* Bs = As + 128 * GAS2;
#pragma unroll
        for (int kt = 0; kt < 2; kt++) {
            int kk = kt * 8;
            uint32_t a[2][4];
#pragma unroll
            for (int mt = 0; mt < 2; mt++) {
                int r = wm + mt * 16 + l4;
                a[mt][0] = As[r * GAS2 + kk + la3];
                a[mt][1] = As[(r + 8) * GAS2 + kk + la3];
                a[mt][2] = As[r * GAS2 + kk + 4 + la3];
                a[mt][3] = As[(r + 8) * GAS2 + kk + 4 + la3];
            }
#pragma unroll
            for (int nt = 0; nt < 4; nt++) {
                uint32_t b[2];
                int c = wn + nt * 8 + l4;
                b[0] = Bs[(kk + la3) * GBS2 + c];
                b[1] = Bs[(kk + 4 + la3) * GBS2 + c];
                mma_f16(acc[0][nt], a[0], b);
                mma_f16(acc[1][nt], a[1], b);
            }
        }
        if (more) {
            uint32_t* As2 = gsm + (buf ^ 1) * GBUF;
            uint32_t* Bs2 = As2 + 128 * GAS2;
#pragma unroll
            for (int p = 0; p < 4; p++) {
                int r = p * 32 + ar;
                As2[r * GAS2 + acu]     = packh2(a_st[p].x, a_st[p].y);
                As2[r * GAS2 + acu + 1] = packh2(a_st[p].z, a_st[p].w);
            }
            uint4 o;
            o.x = packh2(b_st[0].x, b_st[1].x); o.y = packh2(b_st[0].y, b_st[1].y);
            o.z = packh2(b_st[0].z, b_st[1].z); o.w = packh2(b_st[0].w, b_st[1].w);
            *(uint4*)&Bs2[br2 * GBS2 + bc] = o;
        }
        __syncthreads();
        buf ^= 1;
    }

#pragma unroll
    for (int mt = 0; mt < 2; mt++) {
        int r0 = rowBase + wm + mt * 16 + l4;
#pragma unroll
        for (int nt = 0; nt < 4; nt++) {
            int c = colBase + wn + nt * 8 + la3 * 2;
            float v[4] = {acc[mt][nt][0], acc[mt][nt][1], acc[mt][nt][2], acc[mt][nt][3]};
            if (flags & 1) {
#pragma unroll
                for (int e = 0; e < 4; e++) v[e] = fmaxf(v[e], 0.f);
            }
            if (flags & 2) {
                __half* Ch = (__half*)Cv;
                *(uint32_t*)&Ch[(size_t)r0 * ldc + c]       = packh2(v[0], v[1]);
                *(uint32_t*)&Ch[(size_t)(r0 + 8) * ldc + c] = packh2(v[2], v[3]);
            } else {
                float* Cf = (float*)Cv;
                *(float2*)(Cf + (size_t)r0 * ldc + c)       = make_float2(v[0], v[1]);
                *(float2*)(Cf + (size_t)(r0 + 8) * ldc + c) = make_float2(v[2], v[3]);
            }
        }
    }
}

// ---------------- FP16 flash attention, d=64, q-tile 128, kv-tile 64 --------
// QKV half-packed: row stride 768 halves; Q [0,256), K [256,512), V [512,768),
// head h at +h*64. O f32 (bs, Lq, 256). P stays in registers.
// grid = (Lq/128, NHEAD, bs), 256 threads (8 warps x 16 q-rows).
#define AQS 36
#define AVS 72
#define SM_Q 0
#define SM_K (128*AQS)
#define SM_V (SM_K + 2*64*AQS)
#define ATTN_SMEM_BYTES ((SM_V + 2*32*AVS) * 4)   // 55296

__global__ __launch_bounds__(256, 1)
void attn_kernel(const __half* __restrict__ QKV, float* __restrict__ O,
                 int Lq, int Lkv)
{
    extern __shared__ uint32_t sm[];
    int tid = threadIdx.x;
    int lane = tid & 31, wid = tid >> 5;
    int l4 = lane >> 2, la3 = lane & 3;
    int qt = blockIdx.x, h = blockIdx.y, b = blockIdx.z;
    int wq = wid * 16;

    const __half* Qb = QKV + ((size_t)b * Lq + qt * 128) * 768 + h * 64;
    const __half* Kb = QKV + (size_t)b * Lkv * 768 + 256 + h * 64;
    const __half* Vb = Kb + 256;

    // ---- prologue: Q (direct) + K/V tile 0 ----
#pragma unroll
    for (int p = 0; p < 4; p++) {
        int idx = p * 256 + tid;
        int r = idx >> 3, cg = idx & 7;
        uint4 v = *(const uint4*)(Qb + (size_t)r * 768 + cg * 8);
        *(uint4*)&sm[SM_Q + r * AQS + cg * 4] = v;
    }
    {
#pragma unroll
        for (int p = 0; p < 2; p++) {
            int idx = p * 256 + tid;
            int r = idx >> 3, cg = idx & 7;
            uint4 v = *(const uint4*)(Kb + (size_t)r * 768 + cg * 8);
            *(uint4*)&sm[SM_K + r * AQS + cg * 4] = v;
        }
        int q = tid >> 3, dg = tid & 7;
        uint4 va = *(const uint4*)(Vb + (size_t)(2 * q) * 768 + dg * 8);
        uint4 vb = *(const uint4*)(Vb + (size_t)(2 * q + 1) * 768 + dg * 8);
        uint4 o0, o1;
        o0.x = __byte_perm(va.x, vb.x, 0x5410); o0.y = __byte_perm(va.x, vb.x, 0x7632);
        o0.z = __byte_perm(va.y, vb.y, 0x5410); o0.w = __byte_perm(va.y, vb.y, 0x7632);
        o1.x = __byte_perm(va.z, vb.z, 0x5410); o1.y = __byte_perm(va.z, vb.z, 0x7632);
        o1.z = __byte_perm(va.w, vb.w, 0x5410); o1.w = __byte_perm(va.w, vb.w, 0x7632);
        *(uint4*)&sm[SM_V + q * AVS + dg * 8]     = o0;
        *(uint4*)&sm[SM_V + q * AVS + dg * 8 + 4] = o1;
    }
    __syncthreads();

    float oacc[8][4] = {};
    float mrow[2] = {-INFINITY, -INFINITY};
    float lrow[2] = {0.f, 0.f};
    int buf = 0;
    int nTiles = Lkv >> 6;

    for (int t = 0; t < nTiles; t++) {
        bool more = (t + 1 < nTiles);
        uint4 kst[2], vsta, vstb;
        if (more) {
            const __half* Kn = Kb + (size_t)(t + 1) * 64 * 768;
            const __half* Vn = Vb + (size_t)(t + 1) * 64 * 768;
#pragma unroll
            for (int p = 0; p < 2; p++) {
                int idx = p * 256 + tid;
                int r = idx >> 3, cg = idx & 7;
                kst[p] = *(const uint4*)(Kn + (size_t)r * 768 + cg * 8);
            }
            int q = tid >> 3, dg = tid & 7;
            vsta = *(const uint4*)(Vn + (size_t)(2 * q) * 768 + dg * 8);
            vstb = *(const uint4*)(Vn + (size_t)(2 * q + 1) * 768 + dg * 8);
        }

        const uint32_t* Qs = sm + SM_Q;
        const uint32_t* Ks = sm + SM_K + buf * 64 * AQS;
        const uint32_t* Vs = sm + SM_V + buf * 32 * AVS;

        // ---- S = Q @ K^T ----
        float sacc[8][4] = {};
#pragma unroll
        for (int kt = 0; kt < 4; kt++) {
            int kk = kt * 8;
            uint32_t a[4];
            int r = wq + l4;
            a[0] = Qs[r * AQS + kk + la3];
            a[1] = Qs[(r + 8) * AQS + kk + la3];
            a[2] = Qs[r * AQS + kk + 4 + la3];
            a[3] = Qs[(r + 8) * AQS + kk + 4 + la3];
#pragma unroll
            for (int nt = 0; nt < 8; nt++) {
                uint32_t bb[2];
                int c = nt * 8 + l4;
                bb[0] = Ks[c * AQS + kk + la3];
                bb[1] = Ks[c * AQS + kk + 4 + la3];
                mma_f16(sacc[nt], a, bb);
            }
        }

        // ---- online softmax (rows wq+l4 and wq+l4+8; 4 lanes per row) ----
        float mx0 = -INFINITY, mx1 = -INFINITY;
#pragma unroll
        for (int nt = 0; nt < 8; nt++) {
#pragma unroll
            for (int e = 0; e < 4; e++) sacc[nt][e] *= 0.125f;
            mx0 = fmaxf(mx0, fmaxf(sacc[nt][0], sacc[nt][1]));
            mx1 = fmaxf(mx1, fmaxf(sacc[nt][2], sacc[nt][3]));
        }
        mx0 = fmaxf(mx0, __shfl_xor_sync(0xffffffffu, mx0, 1));
        mx0 = fmaxf(mx0, __shfl_xor_sync(0xffffffffu, mx0, 2));
        mx1 = fmaxf(mx1, __shfl_xor_sync(0xffffffffu, mx1, 1));
        mx1 = fmaxf(mx1, __shfl_xor_sync(0xffffffffu, mx1, 2));
        float mn0 = fmaxf(mrow[0], mx0), mn1 = fmaxf(mrow[1], mx1);
        float sc0 = __expf(mrow[0] - mn0), sc1 = __expf(mrow[1] - mn1);
        float sum0 = 0.f, sum1 = 0.f;
#pragma unroll
        for (int nt = 0; nt < 8; nt++) {
            sacc[nt][0] = __expf(sacc[nt][0] - mn0);
            sacc[nt][1] = __expf(sacc[nt][1] - mn0);
            sacc[nt][2] = __expf(sacc[nt][2] - mn1);
            sacc[nt][3] = __expf(sacc[nt][3] - mn1);
            sum0 += sacc[nt][0] + sacc[nt][1];
            sum1 += sacc[nt][2] + sacc[nt][3];
        }
        sum0 += __shfl_xor_sync(0xffffffffu, sum0, 1);
        sum0 += __shfl_xor_sync(0xffffffffu, sum0, 2);
        sum1 += __shfl_xor_sync(0xffffffffu, sum1, 1);
        sum1 += __shfl_xor_sync(0xffffffffu, sum1, 2);
        lrow[0] = lrow[0] * sc0 + sum0;
        lrow[1] = lrow[1] * sc1 + sum1;
        mrow[0] = mn0; mrow[1] = mn1;
#pragma unroll
        for (int nt = 0; nt < 8; nt++) {
            oacc[nt][0] *= sc0; oacc[nt][1] *= sc0;
            oacc[nt][2] *= sc1; oacc[nt][3] *= sc1;
        }

        // ---- pack P into register A-fragments (no smem round trip) ----
        uint32_t pa[4][4];
#pragma unroll
        for (int kt = 0; kt < 4; kt++) {
            pa[kt][0] = packh2(sacc[2*kt][0],   sacc[2*kt][1]);
            pa[kt][1] = packh2(sacc[2*kt][2],   sacc[2*kt][3]);
            pa[kt][2] = packh2(sacc[2*kt+1][0], sacc[2*kt+1][1]);
            pa[kt][3] = packh2(sacc[2*kt+1][2], sacc[2*kt+1][3]);
        }

        // ---- O += P @ V ----
#pragma unroll
        for (int kt = 0; kt < 4; kt++) {
            int kk = kt * 8;
#pragma unroll
            for (int nt = 0; nt < 8; nt++) {
                uint32_t bb[2];
                int c = nt * 8 + l4;
                bb[0] = Vs[(kk + la3) * AVS + c];
                bb[1] = Vs[(kk + 4 + la3) * AVS + c];
                mma_f16(oacc[nt], pa[kt], bb);
            }
        }

        if (more) {
            uint32_t* Ks2 = sm + SM_K + (buf ^ 1) * 64 * AQS;
            uint32_t* Vs2 = sm + SM_V + (buf ^ 1) * 32 * AVS;
#pragma unroll
            for (int p = 0; p < 2; p++) {
                int idx = p * 256 + tid;
                int r = idx >> 3, cg = idx & 7;
                *(uint4*)&Ks2[r * AQS + cg * 4] = kst[p];
            }
            int q = tid >> 3, dg = tid & 7;
            uint4 o0, o1;
            o0.x = __byte_perm(vsta.x, vstb.x, 0x5410); o0.y = __byte_perm(vsta.x, vstb.x, 0x7632);
            o0.z = __byte_perm(vsta.y, vstb.y, 0x5410); o0.w = __byte_perm(vsta.y, vstb.y, 0x7632);
            o1.x = __byte_perm(vsta.z, vstb.z, 0x5410); o1.y = __byte_perm(vsta.z, vstb.z, 0x7632);
            o1.z = __byte_perm(vsta.w, vstb.w, 0x5410); o1.w = __byte_perm(vsta.w, vstb.w, 0x7632);
            *(uint4*)&Vs2[q * AVS + dg * 8]     = o0;
            *(uint4*)&Vs2[q * AVS + dg * 8 + 4] = o1;
        }
        __syncthreads();
        buf ^= 1;
    }

    // ---- finalize ----
    float inv0 = 1.f / lrow[0], inv1 = 1.f / lrow[1];
    int rg = qt * 128 + wq + l4;
#pragma unroll
    for (int nt = 0; nt < 8; nt++) {
        int c = h * 64 + nt * 8 + la3 * 2;
        *(float2*)(O + ((size_t)b * Lq + rg) * C_DIM + c) =
            make_float2(oacc[nt][0] * inv0, oacc[nt][1] * inv0);
        *(float2*)(O + ((size_t)b * Lq + rg + 8) * C_DIM + c) =
            make_float2(oacc[nt][2] * inv1, oacc[nt][3] * inv1);
    }
}

// ---------------- LayerNorm / misc kernels ----------------
__global__ void ln_concat_kernel(const float* __restrict__ x, const float* __restrict__ t,
                                 float* __restrict__ h)
{
    int row = blockIdx.x, c = threadIdx.x;
    float v = t[(size_t)row * C_DIM + c];
    __shared__ float shs[8], shq[8];
    float s = v, q = v * v;
#pragma unroll
    for (int o = 16; o > 0; o >>= 1) {
        s += __shfl_xor_sync(0xffffffffu, s, o);
        q += __shfl_xor_sync(0xffffffffu, q, o);
    }
    if ((c & 31) == 0) { shs[c >> 5] = s; shq[c >> 5] = q; }
    __syncthreads();
    if (c < 32) {
        s = (c < 8) ? shs[c] : 0.f;
        q = (c < 8) ? shq[c] : 0.f;
#pragma unroll
        for (int o = 4; o > 0; o >>= 1) {
            s += __shfl_xor_sync(0xffffffffu, s, o);
            q += __shfl_xor_sync(0xffffffffu, q, o);
        }
        if (c == 0) { shs[0] = s; shq[0] = q; }
    }
    __syncthreads();
    float mean = shs[0] * (1.f / 256.f);
    float var  = shq[0] * (1.f / 256.f) - mean * mean;
    float y = (v - mean) * rsqrtf(var + 1e-5f);
    h[(size_t)row * 512 + c]       = x[(size_t)row * C_DIM + c];
    h[(size_t)row * 512 + 256 + c] = y;
}

__global__ void ln_add_kernel(const float* __restrict__ x, const float* __restrict__ t,
                              float* __restrict__ outp)
{
    int row = blockIdx.x, c = threadIdx.x;
    float v = t[(size_t)row * C_DIM + c];
    __shared__ float shs[8], shq[8];
    float s = v, q = v * v;
#pragma unroll
    for (int o = 16; o > 0; o >>= 1) {
        s += __shfl_xor_sync(0xffffffffu, s, o);
        q += __shfl_xor_sync(0xffffffffu, q, o);
    }
    if ((c & 31) == 0) { shs[c >> 5] = s; shq[c >> 5] = q; }
    __syncthreads();
    if (c < 32) {
        s = (c < 8) ? shs[c] : 0.f;
        q = (c < 8) ? shq[c] : 0.f;
#pragma unroll
        for (int o = 4; o > 0; o >>= 1) {
            s += __shfl_xor_sync(0xffffffffu, s, o);
            q += __shfl_xor_sync(0xffffffffu, q, o);
        }
        if (c == 0) { shs[0] = s; shq[0] = q; }
    }
    __syncthreads();
    float mean = shs[0] * (1.f / 256.f);
    float var  = shq[0] * (1.f / 256.f) - mean * mean;
    float y = (v - mean) * rsqrtf(var + 1e-5f);
    outp[(size_t)row * C_DIM + c] = x[(size_t)row * C_DIM + c] + y;
}

__global__ void add_kernel(float* __restrict__ x, const float* __restrict__ a, int n)
{
    int i = blockIdx.x * 256 + threadIdx.x;
    if (i < n) x[i] += a[i];
}

__global__ void gather_kernel(const float* __restrict__ feat, const int* __restrict__ idx,
                              float* __restrict__ outp, int N, int Lp, int maskNum)
{
    int row = blockIdx.x;
    int g = row / Lp;
    int b = g / maskNum;
    int i = idx[row];
    int c = threadIdx.x;
    float val = 0.f;
    if (i >= 0 && i < N) val = feat[((size_t)b * N + i) * C_DIM + c];
    outp[(size_t)row * C_DIM + c] = val;
}

// ---------------- host orchestration ----------------
static void gemm(const float* A, const float* B, void* C, int M, int N, int K,
                 int ldb, int ldc, int flags)
{
    dim3 g(N / 64, M / 128);
    gemm_kernel<<<g, 256, GEMM_SMEM_BYTES>>>(A, B, C, M, N, K, ldb, ldc, flags);
}

struct Scr { __half* qkv; float *o, *t2, *h, *t1, *wpack; };

static void attn_layer(const float* x, const float* src, float* outp,
                       int bs, int Lq, int Lkv, int li,
                       const float* mWA, const float* w1A, const float* w2A,
                       const Scr& S)
{
    int Mq = bs * Lq, Mkv = bs * Lkv;
    const float* packL = S.wpack + (size_t)li * 256 * 768;
    const float* mW = mWA + (size_t)li * 256 * 256;
    const float* w1 = w1A + (size_t)li * 512 * 512;
    const float* w2 = w2A + (size_t)li * 512 * 256;

    if (x == src) {
        gemm(x, packL, S.qkv, Mq, 768, 256, 768, 768, 2);          // QKV fused, half out
    } else {
        gemm(x,   packL,       S.qkv,       Mq,  256, 256, 768, 768, 2);
        gemm(src, packL + 256, S.qkv + 256, Mkv, 512, 256, 768, 768, 2);
    }
    attn_kernel<<<dim3(Lq / 128, NHEAD, bs), 256, ATTN_SMEM_BYTES>>>(S.qkv, S.o, Lq, Lkv);
    gemm(S.o, mW, S.t2, Mq, 256, 256, 256, 256, 0);
    ln_concat_kernel<<<Mq, 256>>>(x, S.t2, S.h);
    gemm(S.h,  w1, S.t1, Mq, 512, 512, 512, 512, 1);               // fused ReLU
    gemm(S.t1, w2, S.t2, Mq, 256, 512, 256, 256, 0);
    ln_add_kernel<<<Mq, 256>>>(x, S.t2, outp);
}

extern "C" void kernel_launch(void* const* d_in, const int* in_sizes, int n_in,
                              void* d_out, int out_size)
{
    (void)in_sizes; (void)out_size;
    const float* in_srcF = (const float*)d_in[0];
    const float* in_tgtF = (const float*)d_in[1];
    const int*   si      = (const int*)  d_in[6];
    const int*   ti      = (const int*)  d_in[7];
    const float* src2d   = (const float*)d_in[11];
    const float* tgt2d   = (const float*)d_in[12];
    const float* w2A   = (const float*)d_in[n_in - 1];
    const float* w1A   = (const float*)d_in[n_in - 2];
    const float* mWA   = (const float*)d_in[n_in - 3];
    const float* vWA   = (const float*)d_in[n_in - 4];
    const float* kWA   = (const float*)d_in[n_in - 5];
    const float* qWA   = (const float*)d_in[n_in - 6];
    const float* dinoW = (const float*)d_in[n_in - 7];
    float* out = (float*)d_out;

    float *featS, *featT, *projS, *projT, *ob, *t2, *hb, *t1, *ssub, *tsub, *wpack;
    __half* qkvh;
    cudaGetSymbolAddress((void**)&featS, g_featS);
    cudaGetSymbolAddress((void**)&featT, g_featT);
    cudaGetSymbolAddress((void**)&projS, g_projS);
    cudaGetSymbolAddress((void**)&projT, g_projT);
    cudaGetSymbolAddress((void**)&qkvh, g_qkv);
    cudaGetSymbolAddress((void**)&ob, g_o);
    cudaGetSymbolAddress((void**)&t2, g_t2);
    cudaGetSymbolAddress((void**)&hb, g_h);
    cudaGetSymbolAddress((void**)&t1, g_t1);
    cudaGetSymbolAddress((void**)&ssub, g_ssub);
    cudaGetSymbolAddress((void**)&tsub, g_tsub);
    cudaGetSymbolAddress((void**)&wpack, g_wpack);

    cudaFuncSetAttribute(attn_kernel, cudaFuncAttributeMaxDynamicSharedMemorySize,
                         ATTN_SMEM_BYTES);

    // pack [qW|kW|vW] per layer into [256][768]
    for (int li = 0; li < 5; li++) {
        float* dst = wpack + (size_t)li * 256 * 768;
        const size_t woff = (size_t)li * 256 * 256;
        cudaMemcpy2DAsync(dst,       768 * 4, qWA + woff, 256 * 4, 256 * 4, 256,
                          cudaMemcpyDeviceToDevice, 0);
        cudaMemcpy2DAsync(dst + 256, 768 * 4, kWA + woff, 256 * 4, 256 * 4, 256,
                          cudaMemcpyDeviceToDevice, 0);
        cudaMemcpy2DAsync(dst + 512, 768 * 4, vWA + woff, 256 * 4, 256 * 4, 256,
                          cudaMemcpyDeviceToDevice, 0);
    }

    Scr S{qkvh, ob, t2, hb, t1, wpack};
    const int Mmain = 2 * 2048;
    const size_t featBytes = (size_t)Mmain * 256 * sizeof(float);

    cudaMemcpyAsync(featS, in_srcF, featBytes, cudaMemcpyDeviceToDevice, 0);
    cudaMemcpyAsync(featT, in_tgtF, featBytes, cudaMemcpyDeviceToDevice, 0);

    // 2D-feature projection (4096 rows, 384 -> 256)
    gemm(src2d, dinoW, projS, Mmain, 256, 384, 256, 256, 0);
    gemm(tgt2d, dinoW, projT, Mmain, 256, 384, 256, 256, 0);

    // layer 0: self
    add_kernel<<<Mmain * 256 / 256, 256>>>(featS, projS, Mmain * 256);
    add_kernel<<<Mmain * 256 / 256, 256>>>(featT, projT, Mmain * 256);
    attn_layer(featS, featS, featS, 2, 2048, 2048, 0, mWA, w1A, w2A, S);
    attn_layer(featT, featT, featT, 2, 2048, 2048, 0, mWA, w1A, w2A, S);
    // layer 1: cross (tgt uses UPDATED src)
    attn_layer(featS, featT, featS, 2, 2048, 2048, 1, mWA, w1A, w2A, S);
    attn_layer(featT, featS, featT, 2, 2048, 2048, 1, mWA, w1A, w2A, S);
    // layer 2: self
    add_kernel<<<Mmain * 256 / 256, 256>>>(featS, projS, Mmain * 256);
    add_kernel<<<Mmain * 256 / 256, 256>>>(featT, projT, Mmain * 256);
    attn_layer(featS, featS, featS, 2, 2048, 2048, 2, mWA, w1A, w2A, S);
    attn_layer(featT, featT, featT, 2, 2048, 2048, 2, mWA, w1A, w2A, S);
    // layer 3: cross
    attn_layer(featS, featT, featS, 2, 2048, 2048, 3, mWA, w1A, w2A, S);
    attn_layer(featT, featS, featT, 2, 2048, 2048, 3, mWA, w1A, w2A, S);

    // layer 4: semantic_subspace_cross
    gather_kernel<<<16 * 512, 256>>>(featS, si, ssub, 2048, 512, 8);
    gather_kernel<<<16 * 512, 256>>>(featT, ti, tsub, 2048, 512, 8);
    float* outSsem = out + (size_t)2 * 1048576;
    float* outTsem = outSsem + (size_t)16 * 512 * 256;
    attn_layer(ssub, tsub, outSsem, 16, 512, 512, 4, mWA, w1A, w2A, S);
    attn_layer(tsub, ssub, outTsem, 16, 512, 512, 4, mWA, w1A, w2A, S);

    cudaMemcpyAsync(out,           featS, featBytes, cudaMemcpyDeviceToDevice, 0);
    cudaMemcpyAsync(out + 1048576, featT, featBytes, cudaMemcpyDeviceToDevice, 0);
}

// round 11
// speedup vs baseline: 4.9317x; 1.0766x over previous
#include <cuda_runtime.h>
#include <cuda_fp16.h>
#include <math.h>
#include <stdint.h>

#define C_DIM 256
#define NHEAD 4

// ---------------- device scratch (no allocation allowed) ----------------
// feat: [side0(4096 rows) | side1(4096 rows)] x 256
__device__ float  g_feat [8192*256];
__device__ float  g_proj [8192*256];
__device__ float  g_sub  [16384*256];    // [ssub | tsub]
__device__ float  g_t2   [16384*256];
__device__ float  g_h    [16384*512];
__device__ float  g_t1   [16384*512];
__device__ __half g_qkv  [16384*768];
__device__ __half g_semh [16384*256];    // half dump for semantic ln_add
__device__ float  g_wpack[5*256*768];    // packed [qW|kW|vW] per layer

// ---------------- helpers ----------------
__device__ __forceinline__ uint32_t packh2(float a, float b) {
    __half2 h = __floats2half2_rn(a, b);
    return *(uint32_t*)&h;
}
__device__ __forceinline__ void mma_f16(float (&d)[4], const uint32_t (&a)[4],
                                        const uint32_t (&b)[2]) {
    asm volatile(
        "mma.sync.aligned.m16n8k16.row.col.f32.f16.f16.f32 "
        "{%0,%1,%2,%3}, {%4,%5,%6,%7}, {%8,%9}, {%0,%1,%2,%3};"
        : "+f"(d[0]), "+f"(d[1]), "+f"(d[2]), "+f"(d[3])
        : "r"(a[0]), "r"(a[1]), "r"(a[2]), "r"(a[3]), "r"(b[0]), "r"(b[1]));
}

// ---------------- FP16 GEMM, double-buffered (proven R9 kernel) -------------
// C[M,N](ldc) = A[M,K] @ B[K,N](ldb). flags: 1=ReLU, 2=half output.
// M%128==0, N%64==0, K%32==0. 256 threads, tile 128x64x32, 8 warps 32x32.
#define GAS2 20
#define GBS2 72
#define GBUF (128*GAS2 + 16*GBS2)              // 3712 u32
#define GEMM_SMEM_BYTES (2 * GBUF * 4)         // 29696

__global__ __launch_bounds__(256, 1)
void gemm_kernel(const float* __restrict__ A, const float* __restrict__ B,
                 void* __restrict__ Cv, int M, int N, int K,
                 int ldb, int ldc, int flags)
{
    extern __shared__ uint32_t gsm[];
    int tid = threadIdx.x;
    int lane = tid & 31, wid = tid >> 5;
    int l4 = lane >> 2, la3 = lane & 3;
    int wm = (wid & 3) * 32, wn = (wid >> 2) * 32;
    int rowBase = blockIdx.y << 7, colBase = blockIdx.x << 6;

    int ar = tid >> 3, acu = (tid & 7) * 2;
    int br2 = tid >> 4, bc = (tid & 15) * 4;
    const float* Ap = A + (size_t)(rowBase + ar) * K + (tid & 7) * 4;
    const float* Bp = B + (size_t)(2 * br2) * ldb + colBase + bc;

    float4 a_st[4];
    float4 b_st[2];
#pragma unroll
    for (int p = 0; p < 4; p++) a_st[p] = *(const float4*)(Ap + (size_t)p * 32 * K);
    b_st[0] = *(const float4*)(Bp);
    b_st[1] = *(const float4*)(Bp + ldb);

    {
        uint32_t* As = gsm;
        uint32_t* Bs = gsm + 128 * GAS2;
#pragma unroll
        for (int p = 0; p < 4; p++) {
            int r = p * 32 + ar;
            As[r * GAS2 + acu]     = packh2(a_st[p].x, a_st[p].y);
            As[r * GAS2 + acu + 1] = packh2(a_st[p].z, a_st[p].w);
        }
        uint4 o;
        o.x = packh2(b_st[0].x, b_st[1].x); o.y = packh2(b_st[0].y, b_st[1].y);
        o.z = packh2(b_st[0].z, b_st[1].z); o.w = packh2(b_st[0].w, b_st[1].w);
        *(uint4*)&Bs[br2 * GBS2 + bc] = o;
    }
    __syncthreads();

    float acc[2][4][4] = {};
    int buf = 0;
    for (int k0 = 0; k0 < K; k0 += 32) {
        bool more = (k0 + 32 < K);
        if (more) {
#pragma unroll
            for (int p = 0; p < 4; p++)
                a_st[p] = *(const float4*)(Ap + k0 + 32 + (size_t)p * 32 * K);
            b_st[0] = *(const float4*)(Bp + (size_t)(k0 + 32) * ldb);
            b_st[1] = *(const float4*)(Bp + (size_t)(k0 + 33) * ldb);
        }
        const uint32_t* As = gsm + buf * GBUF;
        const uint32_t* Bs = As + 128 * GAS2;
#pragma unroll
        for (int kt = 0; kt < 2; kt++) {
            int kk = kt * 8;
            uint32_t a[2][4];
#pragma unroll
            for (int mt = 0; mt < 2; mt++) {
                int r = wm + mt * 16 + l4;
                a[mt][0] = As[r * GAS2 + kk + la3];
                a[mt][1] = As[(r + 8) * GAS2 + kk + la3];
                a[mt][2] = As[r * GAS2 + kk + 4 + la3];
                a[mt][3] = As[(r + 8) * GAS2 + kk + 4 + la3];
            }
#pragma unroll
            for (int nt = 0; nt < 4; nt++) {
                uint32_t b[2];
                int c = wn + nt * 8 + l4;
                b[0] = Bs[(kk + la3) * GBS2 + c];
                b[1] = Bs[(kk + 4 + la3) * GBS2 + c];
                mma_f16(acc[0][nt], a[0], b);
                mma_f16(acc[1][nt], a[1], b);
            }
        }
        if (more) {
            uint32_t* As2 = gsm + (buf ^ 1) * GBUF;
            uint32_t* Bs2 = As2 + 128 * GAS2;
#pragma unroll
            for (int p = 0; p < 4; p++) {
                int r = p * 32 + ar;
                As2[r * GAS2 + acu]     = packh2(a_st[p].x, a_st[p].y);
                As2[r * GAS2 + acu + 1] = packh2(a_st[p].z, a_st[p].w);
            }
            uint4 o;
            o.x = packh2(b_st[0].x, b_st[1].x); o.y = packh2(b_st[0].y, b_st[1].y);
            o.z = packh2(b_st[0].z, b_st[1].z); o.w = packh2(b_st[0].w, b_st[1].w);
            *(uint4*)&Bs2[br2 * GBS2 + bc] = o;
        }
        __syncthreads();
        buf ^= 1;
    }

#pragma unroll
    for (int mt = 0; mt < 2; mt++) {
        int r0 = rowBase + wm + mt * 16 + l4;
#pragma unroll
        for (int nt = 0; nt < 4; nt++) {
            int c = colBase + wn + nt * 8 + la3 * 2;
            float v[4] = {acc[mt][nt][0], acc[mt][nt][1], acc[mt][nt][2], acc[mt][nt][3]};
            if (flags & 1) {
#pragma unroll
                for (int e = 0; e < 4; e++) v[e] = fmaxf(v[e], 0.f);
            }
            if (flags & 2) {
                __half* Ch = (__half*)Cv;
                *(uint32_t*)&Ch[(size_t)r0 * ldc + c]       = packh2(v[0], v[1]);
                *(uint32_t*)&Ch[(size_t)(r0 + 8) * ldc + c] = packh2(v[2], v[3]);
            } else {
                float* Cf = (float*)Cv;
                *(float2*)(Cf + (size_t)r0 * ldc + c)       = make_float2(v[0], v[1]);
                *(float2*)(Cf + (size_t)(r0 + 8) * ldc + c) = make_float2(v[2], v[3]);
            }
        }
    }
}

// ---------------- FP16 flash attention, d=64, q-tile 128, kv-tile 64 --------
// Qp/KVp half rows of stride 768: Q cols [0,256), K [256,512), V [512,768),
// head h at +h*64. Batch b reads KV from batch (b ^ kvx). O f32.
// grid = (Lq/128, NHEAD, nBatch), 256 threads (8 warps x 16 q-rows).
#define AQS 36
#define AVS 72
#define SM_Q 0
#define SM_K (128*AQS)
#define SM_V (SM_K + 2*64*AQS)
#define ATTN_SMEM_BYTES ((SM_V + 2*32*AVS) * 4)

__global__ __launch_bounds__(256, 1)
void attn_kernel(const __half* __restrict__ Qp, const __half* __restrict__ KVp,
                 float* __restrict__ O, int Lq, int Lkv, int kvx)
{
    extern __shared__ uint32_t sm[];
    int tid = threadIdx.x;
    int lane = tid & 31, wid = tid >> 5;
    int l4 = lane >> 2, la3 = lane & 3;
    int qt = blockIdx.x, h = blockIdx.y, b = blockIdx.z;
    int bk = b ^ kvx;
    int wq = wid * 16;

    const __half* Qb = Qp + ((size_t)b * Lq + qt * 128) * 768 + h * 64;
    const __half* Kb = KVp + (size_t)bk * Lkv * 768 + 256 + h * 64;
    const __half* Vb = Kb + 256;

    // ---- prologue: Q + K/V tile 0 ----
#pragma unroll
    for (int p = 0; p < 4; p++) {
        int idx = p * 256 + tid;
        int r = idx >> 3, cg = idx & 7;
        uint4 v = *(const uint4*)(Qb + (size_t)r * 768 + cg * 8);
        *(uint4*)&sm[SM_Q + r * AQS + cg * 4] = v;
    }
    {
#pragma unroll
        for (int p = 0; p < 2; p++) {
            int idx = p * 256 + tid;
            int r = idx >> 3, cg = idx & 7;
            uint4 v = *(const uint4*)(Kb + (size_t)r * 768 + cg * 8);
            *(uint4*)&sm[SM_K + r * AQS + cg * 4] = v;
        }
        int q = tid >> 3, dg = tid & 7;
        uint4 va = *(const uint4*)(Vb + (size_t)(2 * q) * 768 + dg * 8);
        uint4 vb = *(const uint4*)(Vb + (size_t)(2 * q + 1) * 768 + dg * 8);
        uint4 o0, o1;
        o0.x = __byte_perm(va.x, vb.x, 0x5410); o0.y = __byte_perm(va.x, vb.x, 0x7632);
        o0.z = __byte_perm(va.y, vb.y, 0x5410); o0.w = __byte_perm(va.y, vb.y, 0x7632);
        o1.x = __byte_perm(va.z, vb.z, 0x5410); o1.y = __byte_perm(va.z, vb.z, 0x7632);
        o1.z = __byte_perm(va.w, vb.w, 0x5410); o1.w = __byte_perm(va.w, vb.w, 0x7632);
        *(uint4*)&sm[SM_V + q * AVS + dg * 8]     = o0;
        *(uint4*)&sm[SM_V + q * AVS + dg * 8 + 4] = o1;
    }
    __syncthreads();

    // ---- hoist Q fragments into registers (reused every KV tile) ----
    uint32_t qa[4][4];
#pragma unroll
    for (int kt = 0; kt < 4; kt++) {
        int kk = kt * 8;
        int r = wq + l4;
        qa[kt][0] = sm[SM_Q + r * AQS + kk + la3];
        qa[kt][1] = sm[SM_Q + (r + 8) * AQS + kk + la3];
        qa[kt][2] = sm[SM_Q + r * AQS + kk + 4 + la3];
        qa[kt][3] = sm[SM_Q + (r + 8) * AQS + kk + 4 + la3];
    }

    float oacc[8][4] = {};
    float mrow[2] = {-INFINITY, -INFINITY};
    float lrow[2] = {0.f, 0.f};
    int buf = 0;
    int nTiles = Lkv >> 6;

    for (int t = 0; t < nTiles; t++) {
        bool more = (t + 1 < nTiles);
        uint4 kst[2], vsta, vstb;
        if (more) {
            const __half* Kn = Kb + (size_t)(t + 1) * 64 * 768;
            const __half* Vn = Vb + (size_t)(t + 1) * 64 * 768;
#pragma unroll
            for (int p = 0; p < 2; p++) {
                int idx = p * 256 + tid;
                int r = idx >> 3, cg = idx & 7;
                kst[p] = *(const uint4*)(Kn + (size_t)r * 768 + cg * 8);
            }
            int q = tid >> 3, dg = tid & 7;
            vsta = *(const uint4*)(Vn + (size_t)(2 * q) * 768 + dg * 8);
            vstb = *(const uint4*)(Vn + (size_t)(2 * q + 1) * 768 + dg * 8);
        }

        const uint32_t* Ks = sm + SM_K + buf * 64 * AQS;
        const uint32_t* Vs = sm + SM_V + buf * 32 * AVS;

        // ---- S = Q @ K^T ----
        float sacc[8][4] = {};
#pragma unroll
        for (int kt = 0; kt < 4; kt++) {
            int kk = kt * 8;
#pragma unroll
            for (int nt = 0; nt < 8; nt++) {
                uint32_t bb[2];
                int c = nt * 8 + l4;
                bb[0] = Ks[c * AQS + kk + la3];
                bb[1] = Ks[c * AQS + kk + 4 + la3];
                mma_f16(sacc[nt], qa[kt], bb);
            }
        }

        // ---- online softmax ----
        float mx0 = -INFINITY, mx1 = -INFINITY;
#pragma unroll
        for (int nt = 0; nt < 8; nt++) {
#pragma unroll
            for (int e = 0; e < 4; e++) sacc[nt][e] *= 0.125f;
            mx0 = fmaxf(mx0, fmaxf(sacc[nt][0], sacc[nt][1]));
            mx1 = fmaxf(mx1, fmaxf(sacc[nt][2], sacc[nt][3]));
        }
        mx0 = fmaxf(mx0, __shfl_xor_sync(0xffffffffu, mx0, 1));
        mx0 = fmaxf(mx0, __shfl_xor_sync(0xffffffffu, mx0, 2));
        mx1 = fmaxf(mx1, __shfl_xor_sync(0xffffffffu, mx1, 1));
        mx1 = fmaxf(mx1, __shfl_xor_sync(0xffffffffu, mx1, 2));
        float mn0 = fmaxf(mrow[0], mx0), mn1 = fmaxf(mrow[1], mx1);
        float sc0 = __expf(mrow[0] - mn0), sc1 = __expf(mrow[1] - mn1);
        float sum0 = 0.f, sum1 = 0.f;
#pragma unroll
        for (int nt = 0; nt < 8; nt++) {
            sacc[nt][0] = __expf(sacc[nt][0] - mn0);
            sacc[nt][1] = __expf(sacc[nt][1] - mn0);
            sacc[nt][2] = __expf(sacc[nt][2] - mn1);
            sacc[nt][3] = __expf(sacc[nt][3] - mn1);
            sum0 += sacc[nt][0] + sacc[nt][1];
            sum1 += sacc[nt][2] + sacc[nt][3];
        }
        sum0 += __shfl_xor_sync(0xffffffffu, sum0, 1);
        sum0 += __shfl_xor_sync(0xffffffffu, sum0, 2);
        sum1 += __shfl_xor_sync(0xffffffffu, sum1, 1);
        sum1 += __shfl_xor_sync(0xffffffffu, sum1, 2);
        lrow[0] = lrow[0] * sc0 + sum0;
        lrow[1] = lrow[1] * sc1 + sum1;
        mrow[0] = mn0; mrow[1] = mn1;
#pragma unroll
        for (int nt = 0; nt < 8; nt++) {
            oacc[nt][0] *= sc0; oacc[nt][1] *= sc0;
            oacc[nt][2] *= sc1; oacc[nt][3] *= sc1;
        }

        // ---- pack P into register A-fragments ----
        uint32_t pa[4][4];
#pragma unroll
        for (int kt = 0; kt < 4; kt++) {
            pa[kt][0] = packh2(sacc[2*kt][0],   sacc[2*kt][1]);
            pa[kt][1] = packh2(sacc[2*kt][2],   sacc[2*kt][3]);
            pa[kt][2] = packh2(sacc[2*kt+1][0], sacc[2*kt+1][1]);
            pa[kt][3] = packh2(sacc[2*kt+1][2], sacc[2*kt+1][3]);
        }

        // ---- O += P @ V ----
#pragma unroll
        for (int kt = 0; kt < 4; kt++) {
            int kk = kt * 8;
#pragma unroll
            for (int nt = 0; nt < 8; nt++) {
                uint32_t bb[2];
                int c = nt * 8 + l4;
                bb[0] = Vs[(kk + la3) * AVS + c];
                bb[1] = Vs[(kk + 4 + la3) * AVS + c];
                mma_f16(oacc[nt], pa[kt], bb);
            }
        }

        if (more) {
            uint32_t* Ks2 = sm + SM_K + (buf ^ 1) * 64 * AQS;
            uint32_t* Vs2 = sm + SM_V + (buf ^ 1) * 32 * AVS;
#pragma unroll
            for (int p = 0; p < 2; p++) {
                int idx = p * 256 + tid;
                int r = idx >> 3, cg = idx & 7;
                *(uint4*)&Ks2[r * AQS + cg * 4] = kst[p];
            }
            int q = tid >> 3, dg = tid & 7;
            uint4 o0, o1;
            o0.x = __byte_perm(vsta.x, vstb.x, 0x5410); o0.y = __byte_perm(vsta.x, vstb.x, 0x7632);
            o0.z = __byte_perm(vsta.y, vstb.y, 0x5410); o0.w = __byte_perm(vsta.y, vstb.y, 0x7632);
            o1.x = __byte_perm(vsta.z, vstb.z, 0x5410); o1.y = __byte_perm(vsta.z, vstb.z, 0x7632);
            o1.z = __byte_perm(vsta.w, vstb.w, 0x5410); o1.w = __byte_perm(vsta.w, vstb.w, 0x7632);
            *(uint4*)&Vs2[q * AVS + dg * 8]     = o0;
            *(uint4*)&Vs2[q * AVS + dg * 8 + 4] = o1;
        }
        __syncthreads();
        buf ^= 1;
    }

    // ---- finalize ----
    float inv0 = 1.f / lrow[0], inv1 = 1.f / lrow[1];
    int rg = qt * 128 + wq + l4;
#pragma unroll
    for (int nt = 0; nt < 8; nt++) {
        int c = h * 64 + nt * 8 + la3 * 2;
        *(float2*)(O + ((size_t)b * Lq + rg) * C_DIM + c) =
            make_float2(oacc[nt][0] * inv0, oacc[nt][1] * inv0);
        *(float2*)(O + ((size_t)b * Lq + rg + 8) * C_DIM + c) =
            make_float2(oacc[nt][2] * inv1, oacc[nt][3] * inv1);
    }
}

// ---------------- LayerNorm / misc kernels ----------------
__global__ void ln_concat_kernel(const float* __restrict__ x, const float* __restrict__ t,
                                 float* __restrict__ h)
{
    int row = blockIdx.x, c = threadIdx.x;
    float v = t[(size_t)row * C_DIM + c];
    __shared__ float shs[8], shq[8];
    float s = v, q = v * v;
#pragma unroll
    for (int o = 16; o > 0; o >>= 1) {
        s += __shfl_xor_sync(0xffffffffu, s, o);
        q += __shfl_xor_sync(0xffffffffu, q, o);
    }
    if ((c & 31) == 0) { shs[c >> 5] = s; shq[c >> 5] = q; }
    __syncthreads();
    if (c < 32) {
        s = (c < 8) ? shs[c] : 0.f;
        q = (c < 8) ? shq[c] : 0.f;
#pragma unroll
        for (int o = 4; o > 0; o >>= 1) {
            s += __shfl_xor_sync(0xffffffffu, s, o);
            q += __shfl_xor_sync(0xffffffffu, q, o);
        }
        if (c == 0) { shs[0] = s; shq[0] = q; }
    }
    __syncthreads();
    float mean = shs[0] * (1.f / 256.f);
    float var  = shq[0] * (1.f / 256.f) - mean * mean;
    float y = (v - mean) * rsqrtf(var + 1e-5f);
    h[(size_t)row * 512 + c]       = x[(size_t)row * C_DIM + c];
    h[(size_t)row * 512 + 256 + c] = y;
}

__global__ void ln_add_kernel(const float* __restrict__ x, const float* __restrict__ t,
                              float* __restrict__ outp)
{
    int row = blockIdx.x, c = threadIdx.x;
    float v = t[(size_t)row * C_DIM + c];
    __shared__ float shs[8], shq[8];
    float s = v, q = v * v;
#pragma unroll
    for (int o = 16; o > 0; o >>= 1) {
        s += __shfl_xor_sync(0xffffffffu, s, o);
        q += __shfl_xor_sync(0xffffffffu, q, o);
    }
    if ((c & 31) == 0) { shs[c >> 5] = s; shq[c >> 5] = q; }
    __syncthreads();
    if (c < 32) {
        s = (c < 8) ? shs[c] : 0.f;
        q = (c < 8) ? shq[c] : 0.f;
#pragma unroll
        for (int o = 4; o > 0; o >>= 1) {
            s += __shfl_xor_sync(0xffffffffu, s, o);
            q += __shfl_xor_sync(0xffffffffu, q, o);
        }
        if (c == 0) { shs[0] = s; shq[0] = q; }
    }
    __syncthreads();
    float mean = shs[0] * (1.f / 256.f);
    float var  = shq[0] * (1.f / 256.f) - mean * mean;
    float y = (v - mean) * rsqrtf(var + 1e-5f);
    outp[(size_t)row * C_DIM + c] = x[(size_t)row * C_DIM + c] + y;
}

__global__ void add_kernel(float* __restrict__ x, const float* __restrict__ a, int n)
{
    int i = blockIdx.x * 256 + threadIdx.x;
    if (i < n) x[i] += a[i];
}

__global__ void gather_kernel(const float* __restrict__ feat, const int* __restrict__ idx,
                              float* __restrict__ outp, int N, int Lp, int maskNum)
{
    int row = blockIdx.x;
    int g = row / Lp;
    int b = g / maskNum;
    int i = idx[row];
    int c = threadIdx.x;
    float val = 0.f;
    if (i >= 0 && i < N) val = feat[((size_t)b * N + i) * C_DIM + c];
    outp[(size_t)row * C_DIM + c] = val;
}

// ---------------- host orchestration ----------------
static void gemm(const float* A, const float* B, void* C, int M, int N, int K,
                 int ldb, int ldc, int flags)
{
    dim3 g(N / 64, M / 128);
    gemm_kernel<<<g, 256, GEMM_SMEM_BYTES>>>(A, B, C, M, N, K, ldb, ldc, flags);
}

struct Scr { __half* qkv; float *o, *t2, *h, *t1, *wpack; };

// mW -> ln_concat -> w1(ReLU) -> w2 -> ln_add tail over M rows
static void layer_tail(const float* x, float* outp, int M, int li,
                       const float* mWA, const float* w1A, const float* w2A,
                       const Scr& S)
{
    const float* mW = mWA + (size_t)li * 256 * 256;
    const float* w1 = w1A + (size_t)li * 512 * 512;
    const float* w2 = w2A + (size_t)li * 512 * 256;
    gemm(S.o, mW, S.t2, M, 256, 256, 256, 256, 0);
    ln_concat_kernel<<<M, 256>>>(x, S.t2, S.h);
    gemm(S.h,  w1, S.t1, M, 512, 512, 512, 512, 1);
    gemm(S.t1, w2, S.t2, M, 256, 512, 256, 256, 0);
    ln_add_kernel<<<M, 256>>>(x, S.t2, outp);
}

extern "C" void kernel_launch(void* const* d_in, const int* in_sizes, int n_in,
                              void* d_out, int out_size)
{
    (void)in_sizes; (void)out_size;
    const float* in_srcF = (const float*)d_in[0];
    const float* in_tgtF = (const float*)d_in[1];
    const int*   si      = (const int*)  d_in[6];
    const int*   ti      = (const int*)  d_in[7];
    const float* src2d   = (const float*)d_in[11];
    const float* tgt2d   = (const float*)d_in[12];
    const float* w2A   = (const float*)d_in[n_in - 1];
    const float* w1A   = (const float*)d_in[n_in - 2];
    const float* mWA   = (const float*)d_in[n_in - 3];
    const float* vWA   = (const float*)d_in[n_in - 4];
    const float* kWA   = (const float*)d_in[n_in - 5];
    const float* qWA   = (const float*)d_in[n_in - 6];
    const float* dinoW = (const float*)d_in[n_in - 7];
    float* out = (float*)d_out;

    float *feat, *proj, *sub, *t2, *hb, *t1, *wpack;
    __half *qkv; float* semO; __half* semh;
    cudaGetSymbolAddress((void**)&feat, g_feat);
    cudaGetSymbolAddress((void**)&proj, g_proj);
    cudaGetSymbolAddress((void**)&sub, g_sub);
    cudaGetSymbolAddress((void**)&t2, g_t2);
    cudaGetSymbolAddress((void**)&hb, g_h);
    cudaGetSymbolAddress((void**)&t1, g_t1);
    cudaGetSymbolAddress((void**)&qkv, g_qkv);
    cudaGetSymbolAddress((void**)&semh, g_semh);
    cudaGetSymbolAddress((void**)&wpack, g_wpack);
    semO = (float*)semh;  (void)semO;

    cudaFuncSetAttribute(attn_kernel, cudaFuncAttributeMaxDynamicSharedMemorySize,
                         ATTN_SMEM_BYTES);

    float* featS = feat;
    float* featT = feat + (size_t)4096 * 256;
    float* projS = proj;
    float* projT = proj + (size_t)4096 * 256;
    // o buffer aliases: attention writes f32 rows matching the Q rows
    float* obuf = t1;   // reuse t1 (16384x512 f32) as attention output (16384x256) before w1 pass
    // NOTE: obuf must not clash with S.t1 usage window: attention -> mW(reads obuf)
    //       happens before w1 writes t1. Same dependency order as separate buffers.

    // pack [qW|kW|vW] per layer into [256][768]
    for (int li = 0; li < 5; li++) {
        float* dst = wpack + (size_t)li * 256 * 768;
        const size_t woff = (size_t)li * 256 * 256;
        cudaMemcpy2DAsync(dst,       768 * 4, qWA + woff, 256 * 4, 256 * 4, 256,
                          cudaMemcpyDeviceToDevice, 0);
        cudaMemcpy2DAsync(dst + 256, 768 * 4, kWA + woff, 256 * 4, 256 * 4, 256,
                          cudaMemcpyDeviceToDevice, 0);
        cudaMemcpy2DAsync(dst + 512, 768 * 4, vWA + woff, 256 * 4, 256 * 4, 256,
                          cudaMemcpyDeviceToDevice, 0);
    }

    Scr S{qkv, obuf, t2, hb, t1, wpack};
    const size_t sideBytes = (size_t)4096 * 256 * sizeof(float);

    cudaMemcpyAsync(featS, in_srcF, sideBytes, cudaMemcpyDeviceToDevice, 0);
    cudaMemcpyAsync(featT, in_tgtF, sideBytes, cudaMemcpyDeviceToDevice, 0);

    // 2D-feature projection (both sides share dinoW; two M=4096 GEMMs)
    gemm(src2d, dinoW, projS, 4096, 256, 384, 256, 256, 0);
    gemm(tgt2d, dinoW, projT, 4096, 256, 384, 256, 256, 0);

    for (int li = 0; li < 4; li++) {
        const float* packL = wpack + (size_t)li * 256 * 768;
        if ((li & 1) == 0) {
            // ---- self layer, fused both sides: M = 8192 ----
            add_kernel<<<8192 * 256 / 256, 256>>>(feat, proj, 8192 * 256);
            gemm(feat, packL, qkv, 8192, 768, 256, 768, 768, 2);
            attn_kernel<<<dim3(16, NHEAD, 4), 256, ATTN_SMEM_BYTES>>>(
                qkv, qkv, obuf, 2048, 2048, 0);
            layer_tail(feat, feat, 8192, li, mWA, w1A, w2A, S);
        } else {
            // ---- cross layer: src then tgt (tgt uses UPDATED src) ----
            // src side: Q(featS), KV(featT)
            gemm(featS, packL,       qkv,       4096, 256, 256, 768, 768, 2);
            gemm(featT, packL + 256, qkv + 256, 4096, 512, 256, 768, 768, 2);
            attn_kernel<<<dim3(16, NHEAD, 2), 256, ATTN_SMEM_BYTES>>>(
                qkv, qkv, obuf, 2048, 2048, 0);
            layer_tail(featS, featS, 4096, li, mWA, w1A, w2A, S);
            // tgt side: Q(featT), KV(featS updated)
            gemm(featT, packL,       qkv,       4096, 256, 256, 768, 768, 2);
            gemm(featS, packL + 256, qkv + 256, 4096, 512, 256, 768, 768, 2);
            attn_kernel<<<dim3(16, NHEAD, 2), 256, ATTN_SMEM_BYTES>>>(
                qkv, qkv, obuf, 2048, 2048, 0);
            layer_tail(featT, featT, 4096, li, mWA, w1A, w2A, S);
        }
    }

    // ---- layer 4: semantic_subspace_cross, fused both directions: M = 16384 ----
    float* ssub = sub;
    float* tsub = sub + (size_t)8192 * 256;
    gather_kernel<<<16 * 512, 256>>>(featS, si, ssub, 2048, 512, 8);
    gather_kernel<<<16 * 512, 256>>>(featT, ti, tsub, 2048, 512, 8);
    {
        const float* packL = wpack + (size_t)4 * 256 * 768;
        gemm(sub, packL, qkv, 16384, 768, 256, 768, 768, 2);
        // batch b in [0,32): Q from batch b, KV from batch b^16 (s<->t swap)
        attn_kernel<<<dim3(4, NHEAD, 32), 256, ATTN_SMEM_BYTES>>>(
            qkv, qkv, obuf, 512, 512, 16);
        layer_tail(sub, out + (size_t)2 * 1048576, 16384, 4, mWA, w1A, w2A, S);
    }

    cudaMemcpyAsync(out,           featS, sideBytes, cudaMemcpyDeviceToDevice, 0);
    cudaMemcpyAsync(out + 1048576, featT, sideBytes, cudaMemcpyDeviceToDevice, 0);
}

// round 12
// speedup vs baseline: 5.8182x; 1.1797x over previous
#include <cuda_runtime.h>
#include <cuda_fp16.h>
#include <math.h>
#include <stdint.h>

#define C_DIM 256
#define NHEAD 4

// ---------------- device scratch (no allocation allowed) ----------------
__device__ float  g_feat [8192*256];
__device__ float  g_proj [8192*256];
__device__ float  g_sub  [16384*256];
__device__ float  g_t2   [16384*256];
__device__ __half g_feath[8192*256];
__device__ __half g_subh [16384*256];
__device__ __half g_oh   [16384*256];
__device__ __half g_hh   [16384*512];
__device__ __half g_t1h  [16384*512];
__device__ __half g_qkv  [16384*768];
__device__ __half g_semh [16384*256];
__device__ __half g_2dh  [2*4096*384];
// half weights (same [K][N] layouts as f32 originals)
__device__ __half g_wpackh[5*256*768];
__device__ __half g_mWh  [5*256*256];
__device__ __half g_w1h  [5*512*512];
__device__ __half g_w2h  [5*512*256];
__device__ __half g_dinoh[384*256];

// ---------------- helpers ----------------
__device__ __forceinline__ uint32_t packh2(float a, float b) {
    __half2 h = __floats2half2_rn(a, b);
    return *(uint32_t*)&h;
}
__device__ __forceinline__ void mma_f16(float (&d)[4], const uint32_t (&a)[4],
                                        const uint32_t (&b)[2]) {
    asm volatile(
        "mma.sync.aligned.m16n8k16.row.col.f32.f16.f16.f32 "
        "{%0,%1,%2,%3}, {%4,%5,%6,%7}, {%8,%9}, {%0,%1,%2,%3};"
        : "+f"(d[0]), "+f"(d[1]), "+f"(d[2]), "+f"(d[3])
        : "r"(a[0]), "r"(a[1]), "r"(a[2]), "r"(a[3]), "r"(b[0]), "r"(b[1]));
}
__device__ __forceinline__ void cp16(uint32_t smem_dst, const void* gsrc) {
    asm volatile("cp.async.cg.shared.global [%0], [%1], 16;"
                 :: "r"(smem_dst), "l"(gsrc));
}
#define CP_COMMIT() asm volatile("cp.async.commit_group;" ::: "memory")
#define CP_WAIT(n)  asm volatile("cp.async.wait_group %0;" :: "n"(n) : "memory")
__device__ __forceinline__ void ldsm_x4(uint32_t (&r)[4], uint32_t a) {
    asm volatile("ldmatrix.sync.aligned.m8n8.x4.shared.b16 {%0,%1,%2,%3}, [%4];"
        : "=r"(r[0]), "=r"(r[1]), "=r"(r[2]), "=r"(r[3]) : "r"(a));
}
__device__ __forceinline__ void ldsm_x4_t(uint32_t (&r)[4], uint32_t a) {
    asm volatile("ldmatrix.sync.aligned.m8n8.x4.trans.shared.b16 {%0,%1,%2,%3}, [%4];"
        : "=r"(r[0]), "=r"(r[1]), "=r"(r[2]), "=r"(r[3]) : "r"(a));
}

// ---------------- FP16 GEMM: ldmatrix + cp.async, 128x128x32 ---------------
// C[M,N](ldc) = A[M,K] @ B[K,N](ldb); A,B half. flags: 1=ReLU, 2=half out.
// M%128==0, N%128==0, K%32==0. 256 threads, 8 warps (2m x 4n), warp 64x32.
// A smem: [128 rows][40 halves] (80B stride); B smem: [32 k][136 halves] (272B).
#define GA_STRIDE 80
#define GB_STRIDE 272
#define GBUF_BYTES (128*GA_STRIDE + 32*GB_STRIDE)   // 10240 + 8704 = 18944
#define GEMM_SMEM_BYTES (2 * GBUF_BYTES)            // 37888

__device__ __forceinline__ void fill_chunk(uint32_t sa, uint32_t sb,
                                           const __half* A, const __half* B,
                                           int K, int ldb, int rowBase, int colBase,
                                           int kbase, int tid)
{
#pragma unroll
    for (int p = 0; p < 2; p++) {            // A: 128 rows x 32 halves
        int t = p * 256 + tid;
        int r = t >> 2, seg = t & 3;
        cp16(sa + r * GA_STRIDE + seg * 16,
             A + (size_t)(rowBase + r) * K + kbase + seg * 8);
    }
#pragma unroll
    for (int p = 0; p < 2; p++) {            // B: 32 k-rows x 128 halves
        int t = p * 256 + tid;
        int r = t >> 4, seg = t & 15;
        cp16(sb + r * GB_STRIDE + seg * 16,
             B + (size_t)(kbase + r) * ldb + colBase + seg * 8);
    }
}

__global__ __launch_bounds__(256, 2)
void gemm_h(const __half* __restrict__ A, const __half* __restrict__ B,
            void* __restrict__ Cv, int M, int N, int K,
            int ldb, int ldc, int flags)
{
    extern __shared__ uint8_t gs[];
    uint32_t sbase = (uint32_t)__cvta_generic_to_shared(gs);
    int tid = threadIdx.x;
    int lane = tid & 31, wid = tid >> 5;
    int l4 = lane >> 2, la3 = lane & 3;
    int wm = (wid & 1) * 64, wn = (wid >> 1) * 32;
    int rowBase = blockIdx.y << 7, colBase = blockIdx.x << 7;
    int nC = K >> 5;

    // per-lane ldmatrix addressing components
    int mtx = lane >> 3, rr = lane & 7;
    int a_row = (mtx & 1) * 8 + rr;          // + wm + mt*16
    int a_kc  = (mtx >> 1) * 8;              // + kk
    int b_kr  = (mtx & 1) * 8 + rr;          // + kk
    int b_nc  = (mtx >> 1) * 8;              // + wn + np*16

    fill_chunk(sbase, sbase + 128 * GA_STRIDE, A, B, K, ldb, rowBase, colBase, 0, tid);
    CP_COMMIT();

    float acc[4][4][4] = {};
    int buf = 0;
    for (int ci = 0; ci < nC; ci++) {
        if (ci + 1 < nC) {
            uint32_t nb = sbase + (buf ^ 1) * GBUF_BYTES;
            fill_chunk(nb, nb + 128 * GA_STRIDE, A, B, K, ldb, rowBase, colBase,
                       (ci + 1) << 5, tid);
            CP_COMMIT();
            CP_WAIT(1);
        } else {
            CP_WAIT(0);
        }
        __syncthreads();

        uint32_t SAb = sbase + buf * GBUF_BYTES;
        uint32_t SBb = SAb + 128 * GA_STRIDE;
#pragma unroll
        for (int kt = 0; kt < 2; kt++) {
            int kk = kt * 16;
            uint32_t af[4][4];
#pragma unroll
            for (int mt = 0; mt < 4; mt++)
                ldsm_x4(af[mt], SAb + (wm + mt * 16 + a_row) * GA_STRIDE + (kk + a_kc) * 2);
            uint32_t bf[2][4];
#pragma unroll
            for (int np = 0; np < 2; np++)
                ldsm_x4_t(bf[np], SBb + (kk + b_kr) * GB_STRIDE + (wn + np * 16 + b_nc) * 2);
#pragma unroll
            for (int mt = 0; mt < 4; mt++)
#pragma unroll
                for (int nt = 0; nt < 4; nt++) {
                    uint32_t bb[2] = {bf[nt >> 1][(nt & 1) * 2],
                                      bf[nt >> 1][(nt & 1) * 2 + 1]};
                    mma_f16(acc[mt][nt], af[mt], bb);
                }
        }
        __syncthreads();
        buf ^= 1;
    }

#pragma unroll
    for (int mt = 0; mt < 4; mt++) {
        int r0 = rowBase + wm + mt * 16 + l4;
#pragma unroll
        for (int nt = 0; nt < 4; nt++) {
            int c = colBase + wn + nt * 8 + la3 * 2;
            float v[4] = {acc[mt][nt][0], acc[mt][nt][1], acc[mt][nt][2], acc[mt][nt][3]};
            if (flags & 1) {
#pragma unroll
                for (int e = 0; e < 4; e++) v[e] = fmaxf(v[e], 0.f);
            }
            if (flags & 2) {
                __half* Ch = (__half*)Cv;
                *(uint32_t*)&Ch[(size_t)r0 * ldc + c]       = packh2(v[0], v[1]);
                *(uint32_t*)&Ch[(size_t)(r0 + 8) * ldc + c] = packh2(v[2], v[3]);
            } else {
                float* Cf = (float*)Cv;
                *(float2*)(Cf + (size_t)r0 * ldc + c)       = make_float2(v[0], v[1]);
                *(float2*)(Cf + (size_t)(r0 + 8) * ldc + c) = make_float2(v[2], v[3]);
            }
        }
    }
}

// ---------------- FP16 flash attention (R11, half output) -------------------
#define AQS 36
#define AVS 72
#define SM_Q 0
#define SM_K (128*AQS)
#define SM_V (SM_K + 2*64*AQS)
#define ATTN_SMEM_BYTES ((SM_V + 2*32*AVS) * 4)

__global__ __launch_bounds__(256, 1)
void attn_kernel(const __half* __restrict__ Qp, const __half* __restrict__ KVp,
                 __half* __restrict__ O, int Lq, int Lkv, int kvx)
{
    extern __shared__ uint32_t sm[];
    int tid = threadIdx.x;
    int lane = tid & 31, wid = tid >> 5;
    int l4 = lane >> 2, la3 = lane & 3;
    int qt = blockIdx.x, h = blockIdx.y, b = blockIdx.z;
    int bk = b ^ kvx;
    int wq = wid * 16;

    const __half* Qb = Qp + ((size_t)b * Lq + qt * 128) * 768 + h * 64;
    const __half* Kb = KVp + (size_t)bk * Lkv * 768 + 256 + h * 64;
    const __half* Vb = Kb + 256;

#pragma unroll
    for (int p = 0; p < 4; p++) {
        int idx = p * 256 + tid;
        int r = idx >> 3, cg = idx & 7;
        uint4 v = *(const uint4*)(Qb + (size_t)r * 768 + cg * 8);
        *(uint4*)&sm[SM_Q + r * AQS + cg * 4] = v;
    }
    {
#pragma unroll
        for (int p = 0; p < 2; p++) {
            int idx = p * 256 + tid;
            int r = idx >> 3, cg = idx & 7;
            uint4 v = *(const uint4*)(Kb + (size_t)r * 768 + cg * 8);
            *(uint4*)&sm[SM_K + r * AQS + cg * 4] = v;
        }
        int q = tid >> 3, dg = tid & 7;
        uint4 va = *(const uint4*)(Vb + (size_t)(2 * q) * 768 + dg * 8);
        uint4 vb = *(const uint4*)(Vb + (size_t)(2 * q + 1) * 768 + dg * 8);
        uint4 o0, o1;
        o0.x = __byte_perm(va.x, vb.x, 0x5410); o0.y = __byte_perm(va.x, vb.x, 0x7632);
        o0.z = __byte_perm(va.y, vb.y, 0x5410); o0.w = __byte_perm(va.y, vb.y, 0x7632);
        o1.x = __byte_perm(va.z, vb.z, 0x5410); o1.y = __byte_perm(va.z, vb.z, 0x7632);
        o1.z = __byte_perm(va.w, vb.w, 0x5410); o1.w = __byte_perm(va.w, vb.w, 0x7632);
        *(uint4*)&sm[SM_V + q * AVS + dg * 8]     = o0;
        *(uint4*)&sm[SM_V + q * AVS + dg * 8 + 4] = o1;
    }
    __syncthreads();

    uint32_t qa[4][4];
#pragma unroll
    for (int kt = 0; kt < 4; kt++) {
        int kk = kt * 8;
        int r = wq + l4;
        qa[kt][0] = sm[SM_Q + r * AQS + kk + la3];
        qa[kt][1] = sm[SM_Q + (r + 8) * AQS + kk + la3];
        qa[kt][2] = sm[SM_Q + r * AQS + kk + 4 + la3];
        qa[kt][3] = sm[SM_Q + (r + 8) * AQS + kk + 4 + la3];
    }

    float oacc[8][4] = {};
    float mrow[2] = {-INFINITY, -INFINITY};
    float lrow[2] = {0.f, 0.f};
    int buf = 0;
    int nTiles = Lkv >> 6;

    for (int t = 0; t < nTiles; t++) {
        bool more = (t + 1 < nTiles);
        uint4 kst[2], vsta, vstb;
        if (more) {
            const __half* Kn = Kb + (size_t)(t + 1) * 64 * 768;
            const __half* Vn = Vb + (size_t)(t + 1) * 64 * 768;
#pragma unroll
            for (int p = 0; p < 2; p++) {
                int idx = p * 256 + tid;
                int r = idx >> 3, cg = idx & 7;
                kst[p] = *(const uint4*)(Kn + (size_t)r * 768 + cg * 8);
            }
            int q = tid >> 3, dg = tid & 7;
            vsta = *(const uint4*)(Vn + (size_t)(2 * q) * 768 + dg * 8);
            vstb = *(const uint4*)(Vn + (size_t)(2 * q + 1) * 768 + dg * 8);
        }

        const uint32_t* Ks = sm + SM_K + buf * 64 * AQS;
        const uint32_t* Vs = sm + SM_V + buf * 32 * AVS;

        float sacc[8][4] = {};
#pragma unroll
        for (int kt = 0; kt < 4; kt++) {
            int kk = kt * 8;
#pragma unroll
            for (int nt = 0; nt < 8; nt++) {
                uint32_t bb[2];
                int c = nt * 8 + l4;
                bb[0] = Ks[c * AQS + kk + la3];
                bb[1] = Ks[c * AQS + kk + 4 + la3];
                mma_f16(sacc[nt], qa[kt], bb);
            }
        }

        float mx0 = -INFINITY, mx1 = -INFINITY;
#pragma unroll
        for (int nt = 0; nt < 8; nt++) {
#pragma unroll
            for (int e = 0; e < 4; e++) sacc[nt][e] *= 0.125f;
            mx0 = fmaxf(mx0, fmaxf(sacc[nt][0], sacc[nt][1]));
            mx1 = fmaxf(mx1, fmaxf(sacc[nt][2], sacc[nt][3]));
        }
        mx0 = fmaxf(mx0, __shfl_xor_sync(0xffffffffu, mx0, 1));
        mx0 = fmaxf(mx0, __shfl_xor_sync(0xffffffffu, mx0, 2));
        mx1 = fmaxf(mx1, __shfl_xor_sync(0xffffffffu, mx1, 1));
        mx1 = fmaxf(mx1, __shfl_xor_sync(0xffffffffu, mx1, 2));
        float mn0 = fmaxf(mrow[0], mx0), mn1 = fmaxf(mrow[1], mx1);
        float sc0 = __expf(mrow[0] - mn0), sc1 = __expf(mrow[1] - mn1);
        float sum0 = 0.f, sum1 = 0.f;
#pragma unroll
        for (int nt = 0; nt < 8; nt++) {
            sacc[nt][0] = __expf(sacc[nt][0] - mn0);
            sacc[nt][1] = __expf(sacc[nt][1] - mn0);
            sacc[nt][2] = __expf(sacc[nt][2] - mn1);
            sacc[nt][3] = __expf(sacc[nt][3] - mn1);
            sum0 += sacc[nt][0] + sacc[nt][1];
            sum1 += sacc[nt][2] + sacc[nt][3];
        }
        sum0 += __shfl_xor_sync(0xffffffffu, sum0, 1);
        sum0 += __shfl_xor_sync(0xffffffffu, sum0, 2);
        sum1 += __shfl_xor_sync(0xffffffffu, sum1, 1);
        sum1 += __shfl_xor_sync(0xffffffffu, sum1, 2);
        lrow[0] = lrow[0] * sc0 + sum0;
        lrow[1] = lrow[1] * sc1 + sum1;
        mrow[0] = mn0; mrow[1] = mn1;
#pragma unroll
        for (int nt = 0; nt < 8; nt++) {
            oacc[nt][0] *= sc0; oacc[nt][1] *= sc0;
            oacc[nt][2] *= sc1; oacc[nt][3] *= sc1;
        }

        uint32_t pa[4][4];
#pragma unroll
        for (int kt = 0; kt < 4; kt++) {
            pa[kt][0] = packh2(sacc[2*kt][0],   sacc[2*kt][1]);
            pa[kt][1] = packh2(sacc[2*kt][2],   sacc[2*kt][3]);
            pa[kt][2] = packh2(sacc[2*kt+1][0], sacc[2*kt+1][1]);
            pa[kt][3] = packh2(sacc[2*kt+1][2], sacc[2*kt+1][3]);
        }

#pragma unroll
        for (int kt = 0; kt < 4; kt++) {
            int kk = kt * 8;
#pragma unroll
            for (int nt = 0; nt < 8; nt++) {
                uint32_t bb[2];
                int c = nt * 8 + l4;
                bb[0] = Vs[(kk + la3) * AVS + c];
                bb[1] = Vs[(kk + 4 + la3) * AVS + c];
                mma_f16(oacc[nt], pa[kt], bb);
            }
        }

        if (more) {
            uint32_t* Ks2 = sm + SM_K + (buf ^ 1) * 64 * AQS;
            uint32_t* Vs2 = sm + SM_V + (buf ^ 1) * 32 * AVS;
#pragma unroll
            for (int p = 0; p < 2; p++) {
                int idx = p * 256 + tid;
                int r = idx >> 3, cg = idx & 7;
                *(uint4*)&Ks2[r * AQS + cg * 4] = kst[p];
            }
            int q = tid >> 3, dg = tid & 7;
            uint4 o0, o1;
            o0.x = __byte_perm(vsta.x, vstb.x, 0x5410); o0.y = __byte_perm(vsta.x, vstb.x, 0x7632);
            o0.z = __byte_perm(vsta.y, vstb.y, 0x5410); o0.w = __byte_perm(vsta.y, vstb.y, 0x7632);
            o1.x = __byte_perm(vsta.z, vstb.z, 0x5410); o1.y = __byte_perm(vsta.z, vstb.z, 0x7632);
            o1.z = __byte_perm(vsta.w, vstb.w, 0x5410); o1.w = __byte_perm(vsta.w, vstb.w, 0x7632);
            *(uint4*)&Vs2[q * AVS + dg * 8]     = o0;
            *(uint4*)&Vs2[q * AVS + dg * 8 + 4] = o1;
        }
        __syncthreads();
        buf ^= 1;
    }

    float inv0 = 1.f / lrow[0], inv1 = 1.f / lrow[1];
    int rg = qt * 128 + wq + l4;
#pragma unroll
    for (int nt = 0; nt < 8; nt++) {
        int c = h * 64 + nt * 8 + la3 * 2;
        *(uint32_t*)&O[((size_t)b * Lq + rg) * C_DIM + c] =
            packh2(oacc[nt][0] * inv0, oacc[nt][1] * inv0);
        *(uint32_t*)&O[((size_t)b * Lq + rg + 8) * C_DIM + c] =
            packh2(oacc[nt][2] * inv1, oacc[nt][3] * inv1);
    }
}

// ---------------- LayerNorm / misc kernels ----------------
__global__ void ln_concat_kernel(const float* __restrict__ x, const float* __restrict__ t,
                                 __half* __restrict__ hh)
{
    int row = blockIdx.x, c = threadIdx.x;
    float v = t[(size_t)row * C_DIM + c];
    __shared__ float shs[8], shq[8];
    float s = v, q = v * v;
#pragma unroll
    for (int o = 16; o > 0; o >>= 1) {
        s += __shfl_xor_sync(0xffffffffu, s, o);
        q += __shfl_xor_sync(0xffffffffu, q, o);
    }
    if ((c & 31) == 0) { shs[c >> 5] = s; shq[c >> 5] = q; }
    __syncthreads();
    if (c < 32) {
        s = (c < 8) ? shs[c] : 0.f;
        q = (c < 8) ? shq[c] : 0.f;
#pragma unroll
        for (int o = 4; o > 0; o >>= 1) {
            s += __shfl_xor_sync(0xffffffffu, s, o);
            q += __shfl_xor_sync(0xffffffffu, q, o);
        }
        if (c == 0) { shs[0] = s; shq[0] = q; }
    }
    __syncthreads();
    float mean = shs[0] * (1.f / 256.f);
    float var  = shq[0] * (1.f / 256.f) - mean * mean;
    float y = (v - mean) * rsqrtf(var + 1e-5f);
    hh[(size_t)row * 512 + c]       = __float2half(x[(size_t)row * C_DIM + c]);
    hh[(size_t)row * 512 + 256 + c] = __float2half(y);
}

__global__ void ln_add_kernel(const float* __restrict__ x, const float* __restrict__ t,
                              float* __restrict__ outp, __half* __restrict__ outh)
{
    int row = blockIdx.x, c = threadIdx.x;
    float v = t[(size_t)row * C_DIM + c];
    __shared__ float shs[8], shq[8];
    float s = v, q = v * v;
#pragma unroll
    for (int o = 16; o > 0; o >>= 1) {
        s += __shfl_xor_sync(0xffffffffu, s, o);
        q += __shfl_xor_sync(0xffffffffu, q, o);
    }
    if ((c & 31) == 0) { shs[c >> 5] = s; shq[c >> 5] = q; }
    __syncthreads();
    if (c < 32) {
        s = (c < 8) ? shs[c] : 0.f;
        q = (c < 8) ? shq[c] : 0.f;
#pragma unroll
        for (int o = 4; o > 0; o >>= 1) {
            s += __shfl_xor_sync(0xffffffffu, s, o);
            q += __shfl_xor_sync(0xffffffffu, q, o);
        }
        if (c == 0) { shs[0] = s; shq[0] = q; }
    }
    __syncthreads();
    float mean = shs[0] * (1.f / 256.f);
    float var  = shq[0] * (1.f / 256.f) - mean * mean;
    float y = (v - mean) * rsqrtf(var + 1e-5f);
    float r = x[(size_t)row * C_DIM + c] + y;
    outp[(size_t)row * C_DIM + c] = r;
    outh[(size_t)row * C_DIM + c] = __float2half(r);
}

__global__ void add_kernel(float* __restrict__ x, __half* __restrict__ xh,
                           const float* __restrict__ a, int n)
{
    int i = blockIdx.x * 256 + threadIdx.x;
    if (i < n) {
        float v = x[i] + a[i];
        x[i] = v;
        xh[i] = __float2half(v);
    }
}

__global__ void gather_kernel(const float* __restrict__ feat, const int* __restrict__ idx,
                              float* __restrict__ outp, __half* __restrict__ outh,
                              int N, int Lp, int maskNum)
{
    int row = blockIdx.x;
    int g = row / Lp;
    int b = g / maskNum;
    int i = idx[row];
    int c = threadIdx.x;
    float val = 0.f;
    if (i >= 0 && i < N) val = feat[((size_t)b * N + i) * C_DIM + c];
    outp[(size_t)row * C_DIM + c] = val;
    outh[(size_t)row * C_DIM + c] = __float2half(val);
}

__global__ void cvt_h_kernel(const float* __restrict__ s, __half* __restrict__ d, int n)
{
    int i = blockIdx.x * 256 + threadIdx.x;
    if (i < n) d[i] = __float2half(s[i]);
}

// convert all weights to half (wpack also interleaves q|k|v per layer)
__global__ void cvt_weights(const float* qW, const float* kW, const float* vW,
                            const float* mW, const float* w1, const float* w2,
                            const float* dino,
                            __half* wpackh, __half* mWh, __half* w1h, __half* w2h,
                            __half* dinoh)
{
    const int S1 = 5*256*768, S2 = 5*256*256, S3 = 5*512*512, S4 = 5*512*256, S5 = 384*256;
    int i = blockIdx.x * 256 + threadIdx.x;
    if (i < S1) {
        int li = i / (256 * 768), rem = i % (256 * 768);
        int k = rem / 768, j = rem % 768;
        int w = j >> 8, n = j & 255;
        const float* src = (w == 0) ? qW : (w == 1) ? kW : vW;
        wpackh[i] = __float2half(src[(size_t)li * 65536 + k * 256 + n]);
    } else if (i < S1 + S2) {
        mWh[i - S1] = __float2half(mW[i - S1]);
    } else if (i < S1 + S2 + S3) {
        w1h[i - S1 - S2] = __float2half(w1[i - S1 - S2]);
    } else if (i < S1 + S2 + S3 + S4) {
        w2h[i - S1 - S2 - S3] = __float2half(w2[i - S1 - S2 - S3]);
    } else if (i < S1 + S2 + S3 + S4 + S5) {
        dinoh[i - S1 - S2 - S3 - S4] = __float2half(dino[i - S1 - S2 - S3 - S4]);
    }
}

// ---------------- host orchestration ----------------
static void gemm(const __half* A, const __half* B, void* C, int M, int N, int K,
                 int ldb, int ldc, int flags)
{
    dim3 g(N / 128, M / 128);
    gemm_h<<<g, 256, GEMM_SMEM_BYTES>>>(A, B, C, M, N, K, ldb, ldc, flags);
}

struct Scr { __half *qkv, *oh, *hh, *t1h, *wpackh, *mWh, *w1h, *w2h; float* t2; };

static void layer_tail(const float* x, float* outp, __half* outh, int M, int li,
                       const Scr& S)
{
    const __half* mW = S.mWh + (size_t)li * 256 * 256;
    const __half* w1 = S.w1h + (size_t)li * 512 * 512;
    const __half* w2 = S.w2h + (size_t)li * 512 * 256;
    gemm(S.oh, mW, S.t2, M, 256, 256, 256, 256, 0);
    ln_concat_kernel<<<M, 256>>>(x, S.t2, S.hh);
    gemm(S.hh,  w1, S.t1h, M, 512, 512, 512, 512, 3);    // ReLU + half out
    gemm(S.t1h, w2, S.t2,  M, 256, 512, 256, 256, 0);
    ln_add_kernel<<<M, 256>>>(x, S.t2, outp, outh);
}

extern "C" void kernel_launch(void* const* d_in, const int* in_sizes, int n_in,
                              void* d_out, int out_size)
{
    (void)in_sizes; (void)out_size;
    const float* in_srcF = (const float*)d_in[0];
    const float* in_tgtF = (const float*)d_in[1];
    const int*   si      = (const int*)  d_in[6];
    const int*   ti      = (const int*)  d_in[7];
    const float* src2d   = (const float*)d_in[11];
    const float* tgt2d   = (const float*)d_in[12];
    const float* w2A   = (const float*)d_in[n_in - 1];
    const float* w1A   = (const float*)d_in[n_in - 2];
    const float* mWA   = (const float*)d_in[n_in - 3];
    const float* vWA   = (const float*)d_in[n_in - 4];
    const float* kWA   = (const float*)d_in[n_in - 5];
    const float* qWA   = (const float*)d_in[n_in - 6];
    const float* dinoW = (const float*)d_in[n_in - 7];
    float* out = (float*)d_out;

    float *feat, *proj, *sub, *t2;
    __half *feath, *subh, *oh, *hh, *t1h, *qkv, *semh, *d2h;
    __half *wpackh, *mWh, *w1h, *w2h, *dinoh;
    cudaGetSymbolAddress((void**)&feat, g_feat);
    cudaGetSymbolAddress((void**)&proj, g_proj);
    cudaGetSymbolAddress((void**)&sub, g_sub);
    cudaGetSymbolAddress((void**)&t2, g_t2);
    cudaGetSymbolAddress((void**)&feath, g_feath);
    cudaGetSymbolAddress((void**)&subh, g_subh);
    cudaGetSymbolAddress((void**)&oh, g_oh);
    cudaGetSymbolAddress((void**)&hh, g_hh);
    cudaGetSymbolAddress((void**)&t1h, g_t1h);
    cudaGetSymbolAddress((void**)&qkv, g_qkv);
    cudaGetSymbolAddress((void**)&semh, g_semh);
    cudaGetSymbolAddress((void**)&d2h, g_2dh);
    cudaGetSymbolAddress((void**)&wpackh, g_wpackh);
    cudaGetSymbolAddress((void**)&mWh, g_mWh);
    cudaGetSymbolAddress((void**)&w1h, g_w1h);
    cudaGetSymbolAddress((void**)&w2h, g_w2h);
    cudaGetSymbolAddress((void**)&dinoh, g_dinoh);

    cudaFuncSetAttribute(attn_kernel, cudaFuncAttributeMaxDynamicSharedMemorySize,
                         ATTN_SMEM_BYTES);
    cudaFuncSetAttribute(gemm_h, cudaFuncAttributeMaxDynamicSharedMemorySize,
                         GEMM_SMEM_BYTES);

    float* featS = feat;
    float* featT = feat + (size_t)4096 * 256;
    __half* featSh = feath;
    __half* featTh = feath + (size_t)4096 * 256;
    float* projS = proj;
    float* projT = proj + (size_t)4096 * 256;
    __half* src2h = d2h;
    __half* tgt2h = d2h + (size_t)4096 * 384;

    // weights -> half (packed), 2d feats -> half
    {
        const int TOT = 5*256*768 + 5*256*256 + 5*512*512 + 5*512*256 + 384*256;
        cvt_weights<<<(TOT + 255) / 256, 256>>>(qWA, kWA, vWA, mWA, w1A, w2A, dinoW,
                                                wpackh, mWh, w1h, w2h, dinoh);
    }
    cvt_h_kernel<<<(4096 * 384 + 255) / 256, 256>>>(src2d, src2h, 4096 * 384);
    cvt_h_kernel<<<(4096 * 384 + 255) / 256, 256>>>(tgt2d, tgt2h, 4096 * 384);

    Scr S{qkv, oh, hh, t1h, wpackh, mWh, w1h, w2h, t2};
    const size_t sideBytes = (size_t)4096 * 256 * sizeof(float);

    cudaMemcpyAsync(featS, in_srcF, sideBytes, cudaMemcpyDeviceToDevice, 0);
    cudaMemcpyAsync(featT, in_tgtF, sideBytes, cudaMemcpyDeviceToDevice, 0);

    // 2D-feature projection (both sides, 384 -> 256), f32 output
    gemm(src2h, dinoh, projS, 4096, 256, 384, 256, 256, 0);
    gemm(tgt2h, dinoh, projT, 4096, 256, 384, 256, 256, 0);

    for (int li = 0; li < 4; li++) {
        const __half* packL = wpackh + (size_t)li * 256 * 768;
        if ((li & 1) == 0) {
            // self layer, both sides fused: M = 8192
            add_kernel<<<8192 * 256 / 256, 256>>>(feat, feath, proj, 8192 * 256);
            gemm(feath, packL, qkv, 8192, 768, 256, 768, 768, 2);
            attn_kernel<<<dim3(16, NHEAD, 4), 256, ATTN_SMEM_BYTES>>>(
                qkv, qkv, oh, 2048, 2048, 0);
            layer_tail(feat, feat, feath, 8192, li, S);
        } else {
            // cross layer: src then tgt (tgt uses UPDATED src)
            gemm(featSh, packL,       qkv,       4096, 256, 256, 768, 768, 2);
            gemm(featTh, packL + 256, qkv + 256, 4096, 512, 256, 768, 768, 2);
            attn_kernel<<<dim3(16, NHEAD, 2), 256, ATTN_SMEM_BYTES>>>(
                qkv, qkv, oh, 2048, 2048, 0);
            layer_tail(featS, featS, featSh, 4096, li, S);
            gemm(featTh, packL,       qkv,       4096, 256, 256, 768, 768, 2);
            gemm(featSh, packL + 256, qkv + 256, 4096, 512, 256, 768, 768, 2);
            attn_kernel<<<dim3(16, NHEAD, 2), 256, ATTN_SMEM_BYTES>>>(
                qkv, qkv, oh, 2048, 2048, 0);
            layer_tail(featT, featT, featTh, 4096, li, S);
        }
    }

    // layer 4: semantic_subspace_cross, both directions fused: M = 16384
    float* ssub = sub;
    float* tsub = sub + (size_t)8192 * 256;
    __half* ssubh = subh;
    __half* tsubh = subh + (size_t)8192 * 256;
    gather_kernel<<<16 * 512, 256>>>(featS, si, ssub, ssubh, 2048, 512, 8);
    gather_kernel<<<16 * 512, 256>>>(featT, ti, tsub, tsubh, 2048, 512, 8);
    {
        const __half* packL = wpackh + (size_t)4 * 256 * 768;
        gemm(subh, packL, qkv, 16384, 768, 256, 768, 768, 2);
        attn_kernel<<<dim3(4, NHEAD, 32), 256, ATTN_SMEM_BYTES>>>(
            qkv, qkv, oh, 512, 512, 16);
        layer_tail(sub, out + (size_t)2 * 1048576, semh, 16384, 4, S);
    }

    cudaMemcpyAsync(out,           featS, sideBytes, cudaMemcpyDeviceToDevice, 0);
    cudaMemcpyAsync(out + 1048576, featT, sideBytes, cudaMemcpyDeviceToDevice, 0);
}

// round 13
// speedup vs baseline: 6.0006x; 1.0314x over previous
#include <cuda_runtime.h>
#include <cuda_fp16.h>
#include <math.h>
#include <stdint.h>

#define C_DIM 256
#define NHEAD 4

// ---------------- device scratch (no allocation allowed) ----------------
__device__ float  g_feat [8192*256];
__device__ float  g_proj [8192*256];
__device__ float  g_sub  [16384*256];
__device__ float  g_t2   [16384*256];
__device__ __half g_feath[8192*256];
__device__ __half g_subh [16384*256];
__device__ __half g_oh   [16384*256];
__device__ __half g_hh   [16384*512];
__device__ __half g_t1h  [16384*512];
__device__ __half g_qkv  [16384*768];
__device__ __half g_semh [16384*256];
__device__ __half g_2dh  [2*4096*384];
__device__ __half g_wpackh[5*256*768];
__device__ __half g_mWh  [5*256*256];
__device__ __half g_w1h  [5*512*512];
__device__ __half g_w2h  [5*512*256];
__device__ __half g_dinoh[384*256];

// ---------------- helpers ----------------
__device__ __forceinline__ uint32_t packh2(float a, float b) {
    __half2 h = __floats2half2_rn(a, b);
    return *(uint32_t*)&h;
}
__device__ __forceinline__ void mma_f16(float (&d)[4], const uint32_t (&a)[4],
                                        const uint32_t (&b)[2]) {
    asm volatile(
        "mma.sync.aligned.m16n8k16.row.col.f32.f16.f16.f32 "
        "{%0,%1,%2,%3}, {%4,%5,%6,%7}, {%8,%9}, {%0,%1,%2,%3};"
        : "+f"(d[0]), "+f"(d[1]), "+f"(d[2]), "+f"(d[3])
        : "r"(a[0]), "r"(a[1]), "r"(a[2]), "r"(a[3]), "r"(b[0]), "r"(b[1]));
}
__device__ __forceinline__ void cp16(uint32_t smem_dst, const void* gsrc) {
    asm volatile("cp.async.cg.shared.global [%0], [%1], 16;"
                 :: "r"(smem_dst), "l"(gsrc));
}
#define CP_COMMIT() asm volatile("cp.async.commit_group;" ::: "memory")
#define CP_WAIT(n)  asm volatile("cp.async.wait_group %0;" :: "n"(n) : "memory")
__device__ __forceinline__ void ldsm_x4(uint32_t (&r)[4], uint32_t a) {
    asm volatile("ldmatrix.sync.aligned.m8n8.x4.shared.b16 {%0,%1,%2,%3}, [%4];"
        : "=r"(r[0]), "=r"(r[1]), "=r"(r[2]), "=r"(r[3]) : "r"(a));
}
__device__ __forceinline__ void ldsm_x4_t(uint32_t (&r)[4], uint32_t a) {
    asm volatile("ldmatrix.sync.aligned.m8n8.x4.trans.shared.b16 {%0,%1,%2,%3}, [%4];"
        : "=r"(r[0]), "=r"(r[1]), "=r"(r[2]), "=r"(r[3]) : "r"(a));
}

// ---------------- FP16 GEMM: ldmatrix + cp.async, MTx128x32 ----------------
// C[M,N](ldc) = A[M,K] @ B[K,N](ldb); A,B half. flags: 1=ReLU, 2=half out.
// M%MT==0, N%128==0, K%32==0. 256 threads, 8 warps (2m x 4n), warp MT/2 x 32.
#define GA_STRIDE 80
#define GB_STRIDE 272

template<int MT>
__global__ __launch_bounds__(256, 2)
void gemm_h(const __half* __restrict__ A, const __half* __restrict__ B,
            void* __restrict__ Cv, int M, int N, int K,
            int ldb, int ldc, int flags)
{
    constexpr int MC = MT / 32;                      // m-fragments per warp
    constexpr int BUF = MT * GA_STRIDE + 32 * GB_STRIDE;
    extern __shared__ uint8_t gs[];
    uint32_t sbase = (uint32_t)__cvta_generic_to_shared(gs);
    int tid = threadIdx.x;
    int lane = tid & 31, wid = tid >> 5;
    int l4 = lane >> 2, la3 = lane & 3;
    int wm = (wid & 1) * (MT / 2), wn = (wid >> 1) * 32;
    int rowBase = blockIdx.y * MT, colBase = blockIdx.x << 7;
    int nC = K >> 5;

    int mtx = lane >> 3, rr = lane & 7;
    int a_row = (mtx & 1) * 8 + rr;
    int a_kc  = (mtx >> 1) * 8;
    int b_kr  = (mtx & 1) * 8 + rr;
    int b_nc  = (mtx >> 1) * 8;

    // fill chunk 0
    {
        uint32_t sa = sbase, sb = sbase + MT * GA_STRIDE;
#pragma unroll
        for (int p = 0; p < MT / 64; p++) {
            int t = p * 256 + tid;
            int r = t >> 2, seg = t & 3;
            cp16(sa + r * GA_STRIDE + seg * 16, A + (size_t)(rowBase + r) * K + seg * 8);
        }
#pragma unroll
        for (int p = 0; p < 2; p++) {
            int t = p * 256 + tid;
            int r = t >> 4, seg = t & 15;
            cp16(sb + r * GB_STRIDE + seg * 16, B + (size_t)r * ldb + colBase + seg * 8);
        }
    }
    CP_COMMIT();

    float acc[MC][4][4] = {};
    int buf = 0;
    for (int ci = 0; ci < nC; ci++) {
        if (ci + 1 < nC) {
            uint32_t sa = sbase + (buf ^ 1) * BUF;
            uint32_t sb = sa + MT * GA_STRIDE;
            int kb = (ci + 1) << 5;
#pragma unroll
            for (int p = 0; p < MT / 64; p++) {
                int t = p * 256 + tid;
                int r = t >> 2, seg = t & 3;
                cp16(sa + r * GA_STRIDE + seg * 16,
                     A + (size_t)(rowBase + r) * K + kb + seg * 8);
            }
#pragma unroll
            for (int p = 0; p < 2; p++) {
                int t = p * 256 + tid;
                int r = t >> 4, seg = t & 15;
                cp16(sb + r * GB_STRIDE + seg * 16,
                     B + (size_t)(kb + r) * ldb + colBase + seg * 8);
            }
            CP_COMMIT();
            CP_WAIT(1);
        } else {
            CP_WAIT(0);
        }
        __syncthreads();

        uint32_t SAb = sbase + buf * BUF;
        uint32_t SBb = SAb + MT * GA_STRIDE;
#pragma unroll
        for (int kt = 0; kt < 2; kt++) {
            int kk = kt * 16;
            uint32_t af[MC][4];
#pragma unroll
            for (int mt = 0; mt < MC; mt++)
                ldsm_x4(af[mt], SAb + (wm + mt * 16 + a_row) * GA_STRIDE + (kk + a_kc) * 2);
            uint32_t bf[2][4];
#pragma unroll
            for (int np = 0; np < 2; np++)
                ldsm_x4_t(bf[np], SBb + (kk + b_kr) * GB_STRIDE + (wn + np * 16 + b_nc) * 2);
#pragma unroll
            for (int mt = 0; mt < MC; mt++)
#pragma unroll
                for (int nt = 0; nt < 4; nt++) {
                    uint32_t bb[2] = {bf[nt >> 1][(nt & 1) * 2],
                                      bf[nt >> 1][(nt & 1) * 2 + 1]};
                    mma_f16(acc[mt][nt], af[mt], bb);
                }
        }
        __syncthreads();
        buf ^= 1;
    }

#pragma unroll
    for (int mt = 0; mt < MC; mt++) {
        int r0 = rowBase + wm + mt * 16 + l4;
#pragma unroll
        for (int nt = 0; nt < 4; nt++) {
            int c = colBase + wn + nt * 8 + la3 * 2;
            float v[4] = {acc[mt][nt][0], acc[mt][nt][1], acc[mt][nt][2], acc[mt][nt][3]};
            if (flags & 1) {
#pragma unroll
                for (int e = 0; e < 4; e++) v[e] = fmaxf(v[e], 0.f);
            }
            if (flags & 2) {
                __half* Ch = (__half*)Cv;
                *(uint32_t*)&Ch[(size_t)r0 * ldc + c]       = packh2(v[0], v[1]);
                *(uint32_t*)&Ch[(size_t)(r0 + 8) * ldc + c] = packh2(v[2], v[3]);
            } else {
                float* Cf = (float*)Cv;
                *(float2*)(Cf + (size_t)r0 * ldc + c)       = make_float2(v[0], v[1]);
                *(float2*)(Cf + (size_t)(r0 + 8) * ldc + c) = make_float2(v[2], v[3]);
            }
        }
    }
}

// ---------------- FP16 flash attention (proven; half output) ----------------
#define AQS 36
#define AVS 72
#define SM_Q 0
#define SM_K (128*AQS)
#define SM_V (SM_K + 2*64*AQS)
#define ATTN_SMEM_BYTES ((SM_V + 2*32*AVS) * 4)

__global__ __launch_bounds__(256, 1)
void attn_kernel(const __half* __restrict__ Qp, const __half* __restrict__ KVp,
                 __half* __restrict__ O, int Lq, int Lkv, int kvx)
{
    extern __shared__ uint32_t sm[];
    int tid = threadIdx.x;
    int lane = tid & 31, wid = tid >> 5;
    int l4 = lane >> 2, la3 = lane & 3;
    int qt = blockIdx.x, h = blockIdx.y, b = blockIdx.z;
    int bk = b ^ kvx;
    int wq = wid * 16;

    const __half* Qb = Qp + ((size_t)b * Lq + qt * 128) * 768 + h * 64;
    const __half* Kb = KVp + (size_t)bk * Lkv * 768 + 256 + h * 64;
    const __half* Vb = Kb + 256;

#pragma unroll
    for (int p = 0; p < 4; p++) {
        int idx = p * 256 + tid;
        int r = idx >> 3, cg = idx & 7;
        uint4 v = *(const uint4*)(Qb + (size_t)r * 768 + cg * 8);
        *(uint4*)&sm[SM_Q + r * AQS + cg * 4] = v;
    }
    {
#pragma unroll
        for (int p = 0; p < 2; p++) {
            int idx = p * 256 + tid;
            int r = idx >> 3, cg = idx & 7;
            uint4 v = *(const uint4*)(Kb + (size_t)r * 768 + cg * 8);
            *(uint4*)&sm[SM_K + r * AQS + cg * 4] = v;
        }
        int q = tid >> 3, dg = tid & 7;
        uint4 va = *(const uint4*)(Vb + (size_t)(2 * q) * 768 + dg * 8);
        uint4 vb = *(const uint4*)(Vb + (size_t)(2 * q + 1) * 768 + dg * 8);
        uint4 o0, o1;
        o0.x = __byte_perm(va.x, vb.x, 0x5410); o0.y = __byte_perm(va.x, vb.x, 0x7632);
        o0.z = __byte_perm(va.y, vb.y, 0x5410); o0.w = __byte_perm(va.y, vb.y, 0x7632);
        o1.x = __byte_perm(va.z, vb.z, 0x5410); o1.y = __byte_perm(va.z, vb.z, 0x7632);
        o1.z = __byte_perm(va.w, vb.w, 0x5410); o1.w = __byte_perm(va.w, vb.w, 0x7632);
        *(uint4*)&sm[SM_V + q * AVS + dg * 8]     = o0;
        *(uint4*)&sm[SM_V + q * AVS + dg * 8 + 4] = o1;
    }
    __syncthreads();

    uint32_t qa[4][4];
#pragma unroll
    for (int kt = 0; kt < 4; kt++) {
        int kk = kt * 8;
        int r = wq + l4;
        qa[kt][0] = sm[SM_Q + r * AQS + kk + la3];
        qa[kt][1] = sm[SM_Q + (r + 8) * AQS + kk + la3];
        qa[kt][2] = sm[SM_Q + r * AQS + kk + 4 + la3];
        qa[kt][3] = sm[SM_Q + (r + 8) * AQS + kk + 4 + la3];
    }

    float oacc[8][4] = {};
    float mrow[2] = {-INFINITY, -INFINITY};
    float lrow[2] = {0.f, 0.f};
    int buf = 0;
    int nTiles = Lkv >> 6;

    for (int t = 0; t < nTiles; t++) {
        bool more = (t + 1 < nTiles);
        uint4 kst[2], vsta, vstb;
        if (more) {
            const __half* Kn = Kb + (size_t)(t + 1) * 64 * 768;
            const __half* Vn = Vb + (size_t)(t + 1) * 64 * 768;
#pragma unroll
            for (int p = 0; p < 2; p++) {
                int idx = p * 256 + tid;
                int r = idx >> 3, cg = idx & 7;
                kst[p] = *(const uint4*)(Kn + (size_t)r * 768 + cg * 8);
            }
            int q = tid >> 3, dg = tid & 7;
            vsta = *(const uint4*)(Vn + (size_t)(2 * q) * 768 + dg * 8);
            vstb = *(const uint4*)(Vn + (size_t)(2 * q + 1) * 768 + dg * 8);
        }

        const uint32_t* Ks = sm + SM_K + buf * 64 * AQS;
        const uint32_t* Vs = sm + SM_V + buf * 32 * AVS;

        float sacc[8][4] = {};
#pragma unroll
        for (int kt = 0; kt < 4; kt++) {
            int kk = kt * 8;
#pragma unroll
            for (int nt = 0; nt < 8; nt++) {
                uint32_t bb[2];
                int c = nt * 8 + l4;
                bb[0] = Ks[c * AQS + kk + la3];
                bb[1] = Ks[c * AQS + kk + 4 + la3];
                mma_f16(sacc[nt], qa[kt], bb);
            }
        }

        float mx0 = -INFINITY, mx1 = -INFINITY;
#pragma unroll
        for (int nt = 0; nt < 8; nt++) {
#pragma unroll
            for (int e = 0; e < 4; e++) sacc[nt][e] *= 0.125f;
            mx0 = fmaxf(mx0, fmaxf(sacc[nt][0], sacc[nt][1]));
            mx1 = fmaxf(mx1, fmaxf(sacc[nt][2], sacc[nt][3]));
        }
        mx0 = fmaxf(mx0, __shfl_xor_sync(0xffffffffu, mx0, 1));
        mx0 = fmaxf(mx0, __shfl_xor_sync(0xffffffffu, mx0, 2));
        mx1 = fmaxf(mx1, __shfl_xor_sync(0xffffffffu, mx1, 1));
        mx1 = fmaxf(mx1, __shfl_xor_sync(0xffffffffu, mx1, 2));
        float mn0 = fmaxf(mrow[0], mx0), mn1 = fmaxf(mrow[1], mx1);
        float sc0 = __expf(mrow[0] - mn0), sc1 = __expf(mrow[1] - mn1);
        float sum0 = 0.f, sum1 = 0.f;
#pragma unroll
        for (int nt = 0; nt < 8; nt++) {
            sacc[nt][0] = __expf(sacc[nt][0] - mn0);
            sacc[nt][1] = __expf(sacc[nt][1] - mn0);
            sacc[nt][2] = __expf(sacc[nt][2] - mn1);
            sacc[nt][3] = __expf(sacc[nt][3] - mn1);
            sum0 += sacc[nt][0] + sacc[nt][1];
            sum1 += sacc[nt][2] + sacc[nt][3];
        }
        sum0 += __shfl_xor_sync(0xffffffffu, sum0, 1);
        sum0 += __shfl_xor_sync(0xffffffffu, sum0, 2);
        sum1 += __shfl_xor_sync(0xffffffffu, sum1, 1);
        sum1 += __shfl_xor_sync(0xffffffffu, sum1, 2);
        lrow[0] = lrow[0] * sc0 + sum0;
        lrow[1] = lrow[1] * sc1 + sum1;
        mrow[0] = mn0; mrow[1] = mn1;
#pragma unroll
        for (int nt = 0; nt < 8; nt++) {
            oacc[nt][0] *= sc0; oacc[nt][1] *= sc0;
            oacc[nt][2] *= sc1; oacc[nt][3] *= sc1;
        }

        uint32_t pa[4][4];
#pragma unroll
        for (int kt = 0; kt < 4; kt++) {
            pa[kt][0] = packh2(sacc[2*kt][0],   sacc[2*kt][1]);
            pa[kt][1] = packh2(sacc[2*kt][2],   sacc[2*kt][3]);
            pa[kt][2] = packh2(sacc[2*kt+1][0], sacc[2*kt+1][1]);
            pa[kt][3] = packh2(sacc[2*kt+1][2], sacc[2*kt+1][3]);
        }

#pragma unroll
        for (int kt = 0; kt < 4; kt++) {
            int kk = kt * 8;
#pragma unroll
            for (int nt = 0; nt < 8; nt++) {
                uint32_t bb[2];
                int c = nt * 8 + l4;
                bb[0] = Vs[(kk + la3) * AVS + c];
                bb[1] = Vs[(kk + 4 + la3) * AVS + c];
                mma_f16(oacc[nt], pa[kt], bb);
            }
        }

        if (more) {
            uint32_t* Ks2 = sm + SM_K + (buf ^ 1) * 64 * AQS;
            uint32_t* Vs2 = sm + SM_V + (buf ^ 1) * 32 * AVS;
#pragma unroll
            for (int p = 0; p < 2; p++) {
                int idx = p * 256 + tid;
                int r = idx >> 3, cg = idx & 7;
                *(uint4*)&Ks2[r * AQS + cg * 4] = kst[p];
            }
            int q = tid >> 3, dg = tid & 7;
            uint4 o0, o1;
            o0.x = __byte_perm(vsta.x, vstb.x, 0x5410); o0.y = __byte_perm(vsta.x, vstb.x, 0x7632);
            o0.z = __byte_perm(vsta.y, vstb.y, 0x5410); o0.w = __byte_perm(vsta.y, vstb.y, 0x7632);
            o1.x = __byte_perm(vsta.z, vstb.z, 0x5410); o1.y = __byte_perm(vsta.z, vstb.z, 0x7632);
            o1.z = __byte_perm(vsta.w, vstb.w, 0x5410); o1.w = __byte_perm(vsta.w, vstb.w, 0x7632);
            *(uint4*)&Vs2[q * AVS + dg * 8]     = o0;
            *(uint4*)&Vs2[q * AVS + dg * 8 + 4] = o1;
        }
        __syncthreads();
        buf ^= 1;
    }

    float inv0 = 1.f / lrow[0], inv1 = 1.f / lrow[1];
    int rg = qt * 128 + wq + l4;
#pragma unroll
    for (int nt = 0; nt < 8; nt++) {
        int c = h * 64 + nt * 8 + la3 * 2;
        *(uint32_t*)&O[((size_t)b * Lq + rg) * C_DIM + c] =
            packh2(oacc[nt][0] * inv0, oacc[nt][1] * inv0);
        *(uint32_t*)&O[((size_t)b * Lq + rg + 8) * C_DIM + c] =
            packh2(oacc[nt][2] * inv1, oacc[nt][3] * inv1);
    }
}

// ---------------- LayerNorm / misc kernels ----------------
__global__ void ln_concat_kernel(const float* __restrict__ x, const float* __restrict__ t,
                                 __half* __restrict__ hh)
{
    int row = blockIdx.x, c = threadIdx.x;
    float v = t[(size_t)row * C_DIM + c];
    __shared__ float shs[8], shq[8];
    float s = v, q = v * v;
#pragma unroll
    for (int o = 16; o > 0; o >>= 1) {
        s += __shfl_xor_sync(0xffffffffu, s, o);
        q += __shfl_xor_sync(0xffffffffu, q, o);
    }
    if ((c & 31) == 0) { shs[c >> 5] = s; shq[c >> 5] = q; }
    __syncthreads();
    if (c < 32) {
        s = (c < 8) ? shs[c] : 0.f;
        q = (c < 8) ? shq[c] : 0.f;
#pragma unroll
        for (int o = 4; o > 0; o >>= 1) {
            s += __shfl_xor_sync(0xffffffffu, s, o);
            q += __shfl_xor_sync(0xffffffffu, q, o);
        }
        if (c == 0) { shs[0] = s; shq[0] = q; }
    }
    __syncthreads();
    float mean = shs[0] * (1.f / 256.f);
    float var  = shq[0] * (1.f / 256.f) - mean * mean;
    float y = (v - mean) * rsqrtf(var + 1e-5f);
    hh[(size_t)row * 512 + c]       = __float2half(x[(size_t)row * C_DIM + c]);
    hh[(size_t)row * 512 + 256 + c] = __float2half(y);
}

__global__ void ln_add_kernel(const float* __restrict__ x, const float* __restrict__ t,
                              float* __restrict__ outp, __half* __restrict__ outh)
{
    int row = blockIdx.x, c = threadIdx.x;
    float v = t[(size_t)row * C_DIM + c];
    __shared__ float shs[8], shq[8];
    float s = v, q = v * v;
#pragma unroll
    for (int o = 16; o > 0; o >>= 1) {
        s += __shfl_xor_sync(0xffffffffu, s, o);
        q += __shfl_xor_sync(0xffffffffu, q, o);
    }
    if ((c & 31) == 0) { shs[c >> 5] = s; shq[c >> 5] = q; }
    __syncthreads();
    if (c < 32) {
        s = (c < 8) ? shs[c] : 0.f;
        q = (c < 8) ? shq[c] : 0.f;
#pragma unroll
        for (int o = 4; o > 0; o >>= 1) {
            s += __shfl_xor_sync(0xffffffffu, s, o);
            q += __shfl_xor_sync(0xffffffffu, q, o);
        }
        if (c == 0) { shs[0] = s; shq[0] = q; }
    }
    __syncthreads();
    float mean = shs[0] * (1.f / 256.f);
    float var  = shq[0] * (1.f / 256.f) - mean * mean;
    float y = (v - mean) * rsqrtf(var + 1e-5f);
    float r = x[(size_t)row * C_DIM + c] + y;
    outp[(size_t)row * C_DIM + c] = r;
    outh[(size_t)row * C_DIM + c] = __float2half(r);
}

__global__ void add_kernel(float* __restrict__ x, __half* __restrict__ xh,
                           const float* __restrict__ a, int n)
{
    int i = blockIdx.x * 256 + threadIdx.x;
    if (i < n) {
        float v = x[i] + a[i];
        x[i] = v;
        xh[i] = __float2half(v);
    }
}

__global__ void gather_kernel(const float* __restrict__ feat, const int* __restrict__ idx,
                              float* __restrict__ outp, __half* __restrict__ outh,
                              int N, int Lp, int maskNum)
{
    int row = blockIdx.x;
    int g = row / Lp;
    int b = g / maskNum;
    int i = idx[row];
    int c = threadIdx.x;
    float val = 0.f;
    if (i >= 0 && i < N) val = feat[((size_t)b * N + i) * C_DIM + c];
    outp[(size_t)row * C_DIM + c] = val;
    outh[(size_t)row * C_DIM + c] = __float2half(val);
}

__global__ void cvt_h_kernel(const float* __restrict__ s, __half* __restrict__ d, int n)
{
    int i = blockIdx.x * 256 + threadIdx.x;
    if (i < n) d[i] = __float2half(s[i]);
}

__global__ void cvt_weights(const float* qW, const float* kW, const float* vW,
                            const float* mW, const float* w1, const float* w2,
                            const float* dino,
                            __half* wpackh, __half* mWh, __half* w1h, __half* w2h,
                            __half* dinoh)
{
    const int S1 = 5*256*768, S2 = 5*256*256, S3 = 5*512*512, S4 = 5*512*256, S5 = 384*256;
    int i = blockIdx.x * 256 + threadIdx.x;
    if (i < S1) {
        int li = i / (256 * 768), rem = i % (256 * 768);
        int k = rem / 768, j = rem % 768;
        int w = j >> 8, n = j & 255;
        const float* src = (w == 0) ? qW : (w == 1) ? kW : vW;
        wpackh[i] = __float2half(src[(size_t)li * 65536 + k * 256 + n]);
    } else if (i < S1 + S2) {
        mWh[i - S1] = __float2half(mW[i - S1]);
    } else if (i < S1 + S2 + S3) {
        w1h[i - S1 - S2] = __float2half(w1[i - S1 - S2]);
    } else if (i < S1 + S2 + S3 + S4) {
        w2h[i - S1 - S2 - S3] = __float2half(w2[i - S1 - S2 - S3]);
    } else if (i < S1 + S2 + S3 + S4 + S5) {
        dinoh[i - S1 - S2 - S3 - S4] = __float2half(dino[i - S1 - S2 - S3 - S4]);
    }
}

// ---------------- host orchestration ----------------
static void gemm(const __half* A, const __half* B, void* C, int M, int N, int K,
                 int ldb, int ldc, int flags)
{
    int ctas128 = (N / 128) * (M / 128);
    if (ctas128 < 256) {
        dim3 g(N / 128, M / 64);
        size_t sm = 2 * (64 * GA_STRIDE + 32 * GB_STRIDE);
        gemm_h<64><<<g, 256, sm>>>(A, B, C, M, N, K, ldb, ldc, flags);
    } else {
        dim3 g(N / 128, M / 128);
        size_t sm = 2 * (128 * GA_STRIDE + 32 * GB_STRIDE);
        gemm_h<128><<<g, 256, sm>>>(A, B, C, M, N, K, ldb, ldc, flags);
    }
}

struct Scr { __half *qkv, *oh, *hh, *t1h, *wpackh, *mWh, *w1h, *w2h; float* t2; };

static void layer_tail(const float* x, float* outp, __half* outh, int M, int li,
                       const Scr& S)
{
    const __half* mW = S.mWh + (size_t)li * 256 * 256;
    const __half* w1 = S.w1h + (size_t)li * 512 * 512;
    const __half* w2 = S.w2h + (size_t)li * 512 * 256;
    gemm(S.oh, mW, S.t2, M, 256, 256, 256, 256, 0);
    ln_concat_kernel<<<M, 256>>>(x, S.t2, S.hh);
    gemm(S.hh,  w1, S.t1h, M, 512, 512, 512, 512, 3);
    gemm(S.t1h, w2, S.t2,  M, 256, 512, 256, 256, 0);
    ln_add_kernel<<<M, 256>>>(x, S.t2, outp, outh);
}

extern "C" void kernel_launch(void* const* d_in, const int* in_sizes, int n_in,
                              void* d_out, int out_size)
{
    (void)in_sizes; (void)out_size;
    const float* in_srcF = (const float*)d_in[0];
    const float* in_tgtF = (const float*)d_in[1];
    const int*   si      = (const int*)  d_in[6];
    const int*   ti      = (const int*)  d_in[7];
    const float* src2d   = (const float*)d_in[11];
    const float* tgt2d   = (const float*)d_in[12];
    const float* w2A   = (const float*)d_in[n_in - 1];
    const float* w1A   = (const float*)d_in[n_in - 2];
    const float* mWA   = (const float*)d_in[n_in - 3];
    const float* vWA   = (const float*)d_in[n_in - 4];
    const float* kWA   = (const float*)d_in[n_in - 5];
    const float* qWA   = (const float*)d_in[n_in - 6];
    const float* dinoW = (const float*)d_in[n_in - 7];
    float* out = (float*)d_out;

    float *feat, *proj, *sub, *t2;
    __half *feath, *subh, *oh, *hh, *t1h, *qkv, *semh, *d2h;
    __half *wpackh, *mWh, *w1h, *w2h, *dinoh;
    cudaGetSymbolAddress((void**)&feat, g_feat);
    cudaGetSymbolAddress((void**)&proj, g_proj);
    cudaGetSymbolAddress((void**)&sub, g_sub);
    cudaGetSymbolAddress((void**)&t2, g_t2);
    cudaGetSymbolAddress((void**)&feath, g_feath);
    cudaGetSymbolAddress((void**)&subh, g_subh);
    cudaGetSymbolAddress((void**)&oh, g_oh);
    cudaGetSymbolAddress((void**)&hh, g_hh);
    cudaGetSymbolAddress((void**)&t1h, g_t1h);
    cudaGetSymbolAddress((void**)&qkv, g_qkv);
    cudaGetSymbolAddress((void**)&semh, g_semh);
    cudaGetSymbolAddress((void**)&d2h, g_2dh);
    cudaGetSymbolAddress((void**)&wpackh, g_wpackh);
    cudaGetSymbolAddress((void**)&mWh, g_mWh);
    cudaGetSymbolAddress((void**)&w1h, g_w1h);
    cudaGetSymbolAddress((void**)&w2h, g_w2h);
    cudaGetSymbolAddress((void**)&dinoh, g_dinoh);

    cudaFuncSetAttribute(attn_kernel, cudaFuncAttributeMaxDynamicSharedMemorySize,
                         ATTN_SMEM_BYTES);

    float* featS = feat;
    float* featT = feat + (size_t)4096 * 256;
    __half* featSh = feath;
    __half* featTh = feath + (size_t)4096 * 256;
    float* projS = proj;
    float* projT = proj + (size_t)4096 * 256;
    __half* src2h = d2h;
    __half* tgt2h = d2h + (size_t)4096 * 384;

    {
        const int TOT = 5*256*768 + 5*256*256 + 5*512*512 + 5*512*256 + 384*256;
        cvt_weights<<<(TOT + 255) / 256, 256>>>(qWA, kWA, vWA, mWA, w1A, w2A, dinoW,
                                                wpackh, mWh, w1h, w2h, dinoh);
    }
    cvt_h_kernel<<<(4096 * 384 + 255) / 256, 256>>>(src2d, src2h, 4096 * 384);
    cvt_h_kernel<<<(4096 * 384 + 255) / 256, 256>>>(tgt2d, tgt2h, 4096 * 384);

    Scr S{qkv, oh, hh, t1h, wpackh, mWh, w1h, w2h, t2};
    const size_t sideBytes = (size_t)4096 * 256 * sizeof(float);

    cudaMemcpyAsync(featS, in_srcF, sideBytes, cudaMemcpyDeviceToDevice, 0);
    cudaMemcpyAsync(featT, in_tgtF, sideBytes, cudaMemcpyDeviceToDevice, 0);

    gemm(src2h, dinoh, projS, 4096, 256, 384, 256, 256, 0);
    gemm(tgt2h, dinoh, projT, 4096, 256, 384, 256, 256, 0);

    for (int li = 0; li < 4; li++) {
        const __half* packL = wpackh + (size_t)li * 256 * 768;
        if ((li & 1) == 0) {
            // ---- self layer, both sides fused: M = 8192, batches 0..3 ----
            add_kernel<<<8192 * 256 / 256, 256>>>(feat, feath, proj, 8192 * 256);
            gemm(feath, packL, qkv, 8192, 768, 256, 768, 768, 2);
            attn_kernel<<<dim3(16, NHEAD, 4), 256, ATTN_SMEM_BYTES>>>(
                qkv, qkv, oh, 2048, 2048, 0);
            layer_tail(feat, feat, feath, 8192, li, S);
        } else {
            // ---- cross layer ----
            // fused QKV for BOTH sides from pre-update feats (one 384-CTA GEMM)
            gemm(feath, packL, qkv, 8192, 768, 256, 768, 768, 2);
            // src direction: Q batches 0,1; KV from batches 2,3 (tgt) via kvx=2
            attn_kernel<<<dim3(16, NHEAD, 2), 256, ATTN_SMEM_BYTES>>>(
                qkv, qkv, oh, 2048, 2048, 2);
            layer_tail(featS, featS, featSh, 4096, li, S);
            // recompute KV of UPDATED src into qkv rows 0..4095, cols [256,768)
            gemm(featSh, packL + 256, qkv + 256, 4096, 512, 256, 768, 768, 2);
            // tgt direction: Q from batches 2,3 (offset base), KV from batches 0,1
            attn_kernel<<<dim3(16, NHEAD, 2), 256, ATTN_SMEM_BYTES>>>(
                qkv + (size_t)2 * 2048 * 768, qkv, oh, 2048, 2048, 0);
            layer_tail(featT, featT, featTh, 4096, li, S);
        }
    }

    // ---- layer 4: semantic_subspace_cross, fused both directions: M = 16384 ----
    float* ssub = sub;
    float* tsub = sub + (size_t)8192 * 256;
    __half* ssubh = subh;
    __half* tsubh = subh + (size_t)8192 * 256;
    gather_kernel<<<16 * 512, 256>>>(featS, si, ssub, ssubh, 2048, 512, 8);
    gather_kernel<<<16 * 512, 256>>>(featT, ti, tsub, tsubh, 2048, 512, 8);
    {
        const __half* packL = wpackh + (size_t)4 * 256 * 768;
        gemm(subh, packL, qkv, 16384, 768, 256, 768, 768, 2);
        attn_kernel<<<dim3(4, NHEAD, 32), 256, ATTN_SMEM_BYTES>>>(
            qkv, qkv, oh, 512, 512, 16);
        layer_tail(sub, out + (size_t)2 * 1048576, semh, 16384, 4, S);
    }

    cudaMemcpyAsync(out,           featS, sideBytes, cudaMemcpyDeviceToDevice, 0);
    cudaMemcpyAsync(out + 1048576, featT, sideBytes, cudaMemcpyDeviceToDevice, 0);
}

// round 14
// speedup vs baseline: 6.0619x; 1.0102x over previous
#include <cuda_runtime.h>
#include <cuda_fp16.h>
#include <math.h>
#include <stdint.h>

#define C_DIM 256
#define NHEAD 4

// ---------------- device scratch (no allocation allowed) ----------------
__device__ float  g_feat [8192*256];
__device__ float  g_proj [8192*256];
__device__ float  g_sub  [16384*256];
__device__ float  g_t2   [16384*256];
__device__ __half g_feath[8192*256];
__device__ __half g_subh [16384*256];
__device__ __half g_oh   [16384*256];
__device__ __half g_hh   [16384*512];
__device__ __half g_t1h  [16384*512];
__device__ __half g_qkv  [16384*768];
__device__ __half g_semh [16384*256];
__device__ __half g_2dh  [2*4096*384];
__device__ __half g_wpackh[5*256*768];
__device__ __half g_mWh  [5*256*256];
__device__ __half g_w1h  [5*512*512];
__device__ __half g_w2h  [5*512*256];
__device__ __half g_dinoh[384*256];

// ---------------- helpers ----------------
__device__ __forceinline__ uint32_t packh2(float a, float b) {
    __half2 h = __floats2half2_rn(a, b);
    return *(uint32_t*)&h;
}
__device__ __forceinline__ void mma_f16(float (&d)[4], const uint32_t (&a)[4],
                                        const uint32_t (&b)[2]) {
    asm volatile(
        "mma.sync.aligned.m16n8k16.row.col.f32.f16.f16.f32 "
        "{%0,%1,%2,%3}, {%4,%5,%6,%7}, {%8,%9}, {%0,%1,%2,%3};"
        : "+f"(d[0]), "+f"(d[1]), "+f"(d[2]), "+f"(d[3])
        : "r"(a[0]), "r"(a[1]), "r"(a[2]), "r"(a[3]), "r"(b[0]), "r"(b[1]));
}
__device__ __forceinline__ void cp16(uint32_t smem_dst, const void* gsrc) {
    asm volatile("cp.async.cg.shared.global [%0], [%1], 16;"
                 :: "r"(smem_dst), "l"(gsrc));
}
#define CP_COMMIT() asm volatile("cp.async.commit_group;" ::: "memory")
#define CP_WAIT(n)  asm volatile("cp.async.wait_group %0;" :: "n"(n) : "memory")
__device__ __forceinline__ void ldsm_x4(uint32_t (&r)[4], uint32_t a) {
    asm volatile("ldmatrix.sync.aligned.m8n8.x4.shared.b16 {%0,%1,%2,%3}, [%4];"
        : "=r"(r[0]), "=r"(r[1]), "=r"(r[2]), "=r"(r[3]) : "r"(a));
}
__device__ __forceinline__ void ldsm_x4_t(uint32_t (&r)[4], uint32_t a) {
    asm volatile("ldmatrix.sync.aligned.m8n8.x4.trans.shared.b16 {%0,%1,%2,%3}, [%4];"
        : "=r"(r[0]), "=r"(r[1]), "=r"(r[2]), "=r"(r[3]) : "r"(a));
}

// ---------------- FP16 GEMM: ldmatrix + cp.async, MTx128x32 ----------------
#define GA_STRIDE 80
#define GB_STRIDE 272

template<int MT>
__global__ __launch_bounds__(256, 2)
void gemm_h(const __half* __restrict__ A, const __half* __restrict__ B,
            void* __restrict__ Cv, int M, int N, int K,
            int ldb, int ldc, int flags)
{
    constexpr int MC = MT / 32;
    constexpr int BUF = MT * GA_STRIDE + 32 * GB_STRIDE;
    extern __shared__ uint8_t gs[];
    uint32_t sbase = (uint32_t)__cvta_generic_to_shared(gs);
    int tid = threadIdx.x;
    int lane = tid & 31, wid = tid >> 5;
    int l4 = lane >> 2, la3 = lane & 3;
    int wm = (wid & 1) * (MT / 2), wn = (wid >> 1) * 32;
    int rowBase = blockIdx.y * MT, colBase = blockIdx.x << 7;
    int nC = K >> 5;

    int mtx = lane >> 3, rr = lane & 7;
    int a_row = (mtx & 1) * 8 + rr;
    int a_kc  = (mtx >> 1) * 8;
    int b_kr  = (mtx & 1) * 8 + rr;
    int b_nc  = (mtx >> 1) * 8;

    {
        uint32_t sa = sbase, sb = sbase + MT * GA_STRIDE;
#pragma unroll
        for (int p = 0; p < MT / 64; p++) {
            int t = p * 256 + tid;
            int r = t >> 2, seg = t & 3;
            cp16(sa + r * GA_STRIDE + seg * 16, A + (size_t)(rowBase + r) * K + seg * 8);
        }
#pragma unroll
        for (int p = 0; p < 2; p++) {
            int t = p * 256 + tid;
            int r = t >> 4, seg = t & 15;
            cp16(sb + r * GB_STRIDE + seg * 16, B + (size_t)r * ldb + colBase + seg * 8);
        }
    }
    CP_COMMIT();

    float acc[MC][4][4] = {};
    int buf = 0;
    for (int ci = 0; ci < nC; ci++) {
        if (ci + 1 < nC) {
            uint32_t sa = sbase + (buf ^ 1) * BUF;
            uint32_t sb = sa + MT * GA_STRIDE;
            int kb = (ci + 1) << 5;
#pragma unroll
            for (int p = 0; p < MT / 64; p++) {
                int t = p * 256 + tid;
                int r = t >> 2, seg = t & 3;
                cp16(sa + r * GA_STRIDE + seg * 16,
                     A + (size_t)(rowBase + r) * K + kb + seg * 8);
            }
#pragma unroll
            for (int p = 0; p < 2; p++) {
                int t = p * 256 + tid;
                int r = t >> 4, seg = t & 15;
                cp16(sb + r * GB_STRIDE + seg * 16,
                     B + (size_t)(kb + r) * ldb + colBase + seg * 8);
            }
            CP_COMMIT();
            CP_WAIT(1);
        } else {
            CP_WAIT(0);
        }
        __syncthreads();

        uint32_t SAb = sbase + buf * BUF;
        uint32_t SBb = SAb + MT * GA_STRIDE;
#pragma unroll
        for (int kt = 0; kt < 2; kt++) {
            int kk = kt * 16;
            uint32_t af[MC][4];
#pragma unroll
            for (int mt = 0; mt < MC; mt++)
                ldsm_x4(af[mt], SAb + (wm + mt * 16 + a_row) * GA_STRIDE + (kk + a_kc) * 2);
            uint32_t bf[2][4];
#pragma unroll
            for (int np = 0; np < 2; np++)
                ldsm_x4_t(bf[np], SBb + (kk + b_kr) * GB_STRIDE + (wn + np * 16 + b_nc) * 2);
#pragma unroll
            for (int mt = 0; mt < MC; mt++)
#pragma unroll
                for (int nt = 0; nt < 4; nt++) {
                    uint32_t bb[2] = {bf[nt >> 1][(nt & 1) * 2],
                                      bf[nt >> 1][(nt & 1) * 2 + 1]};
                    mma_f16(acc[mt][nt], af[mt], bb);
                }
        }
        __syncthreads();
        buf ^= 1;
    }

#pragma unroll
    for (int mt = 0; mt < MC; mt++) {
        int r0 = rowBase + wm + mt * 16 + l4;
#pragma unroll
        for (int nt = 0; nt < 4; nt++) {
            int c = colBase + wn + nt * 8 + la3 * 2;
            float v[4] = {acc[mt][nt][0], acc[mt][nt][1], acc[mt][nt][2], acc[mt][nt][3]};
            if (flags & 1) {
#pragma unroll
                for (int e = 0; e < 4; e++) v[e] = fmaxf(v[e], 0.f);
            }
            if (flags & 2) {
                __half* Ch = (__half*)Cv;
                *(uint32_t*)&Ch[(size_t)r0 * ldc + c]       = packh2(v[0], v[1]);
                *(uint32_t*)&Ch[(size_t)(r0 + 8) * ldc + c] = packh2(v[2], v[3]);
            } else {
                float* Cf = (float*)Cv;
                *(float2*)(Cf + (size_t)r0 * ldc + c)       = make_float2(v[0], v[1]);
                *(float2*)(Cf + (size_t)(r0 + 8) * ldc + c) = make_float2(v[2], v[3]);
            }
        }
    }
}

// ---------------- FP16 flash attention v2: ldmatrix + cp.async --------------
// K and V both stored as raw [64 rows][AQS u32] tiles (natural [s][d] layout).
// K frags: non-trans ldmatrix (B of S=QK^T); V frags: trans ldmatrix (B of PV).
#define AQS 36
#define SM_Q 0
#define SM_K (128*AQS)
#define SM_V (SM_K + 2*64*AQS)
#define ATTN_SMEM_BYTES ((SM_V + 2*64*AQS) * 4)   // 55296

__global__ __launch_bounds__(256, 2)
void attn_kernel(const __half* __restrict__ Qp, const __half* __restrict__ KVp,
                 __half* __restrict__ O, int Lq, int Lkv, int kvx)
{
    extern __shared__ uint32_t sm[];
    uint32_t sb = (uint32_t)__cvta_generic_to_shared(sm);
    int tid = threadIdx.x;
    int lane = tid & 31, wid = tid >> 5;
    int l4 = lane >> 2, la3 = lane & 3;
    int qt = blockIdx.x, h = blockIdx.y, b = blockIdx.z;
    int bk = b ^ kvx;
    int wq = wid * 16;
    int mtx = lane >> 3, rr = lane & 7;

    const __half* Qb = Qp + ((size_t)b * Lq + qt * 128) * 768 + h * 64;
    const __half* Kb = KVp + (size_t)bk * Lkv * 768 + 256 + h * 64;
    const __half* Vb = Kb + 256;

    // prologue: Q (128 rows) + K0/V0 (64 rows each) via cp.async, one group
#pragma unroll
    for (int p = 0; p < 4; p++) {
        int idx = p * 256 + tid;
        int r = idx >> 3, cg = idx & 7;
        cp16(sb + (SM_Q + r * AQS) * 4 + cg * 16, Qb + (size_t)r * 768 + cg * 8);
    }
#pragma unroll
    for (int p = 0; p < 2; p++) {
        int idx = p * 256 + tid;
        int r = idx >> 3, cg = idx & 7;
        cp16(sb + (SM_K + r * AQS) * 4 + cg * 16, Kb + (size_t)r * 768 + cg * 8);
        cp16(sb + (SM_V + r * AQS) * 4 + cg * 16, Vb + (size_t)r * 768 + cg * 8);
    }
    CP_COMMIT();

    uint32_t qa[4][4];
    float oacc[8][4] = {};
    float mrow[2] = {-INFINITY, -INFINITY};
    float lrow[2] = {0.f, 0.f};
    int buf = 0;
    int nTiles = Lkv >> 6;

    for (int t = 0; t < nTiles; t++) {
        if (t + 1 < nTiles) {
            const __half* Kn = Kb + (size_t)(t + 1) * 64 * 768;
            const __half* Vn = Vb + (size_t)(t + 1) * 64 * 768;
            uint32_t kd = sb + (SM_K + (buf ^ 1) * 64 * AQS) * 4;
            uint32_t vd = sb + (SM_V + (buf ^ 1) * 64 * AQS) * 4;
#pragma unroll
            for (int p = 0; p < 2; p++) {
                int idx = p * 256 + tid;
                int r = idx >> 3, cg = idx & 7;
                cp16(kd + r * AQS * 4 + cg * 16, Kn + (size_t)r * 768 + cg * 8);
                cp16(vd + r * AQS * 4 + cg * 16, Vn + (size_t)r * 768 + cg * 8);
            }
            CP_COMMIT();
            CP_WAIT(1);
        } else {
            CP_WAIT(0);
        }
        __syncthreads();

        if (t == 0) {   // hoist Q fragments once (Q landed with group 0)
#pragma unroll
            for (int kt = 0; kt < 4; kt++) {
                int kk = kt * 8;
                int r = wq + l4;
                qa[kt][0] = sm[SM_Q + r * AQS + kk + la3];
                qa[kt][1] = sm[SM_Q + (r + 8) * AQS + kk + la3];
                qa[kt][2] = sm[SM_Q + r * AQS + kk + 4 + la3];
                qa[kt][3] = sm[SM_Q + (r + 8) * AQS + kk + 4 + la3];
            }
        }

        uint32_t sbK = sb + (SM_K + buf * 64 * AQS) * 4;
        uint32_t sbV = sb + (SM_V + buf * 64 * AQS) * 4;

        // ---- S = Q @ K^T : K B-frags via non-trans ldmatrix.x4 ----
        float sacc[8][4] = {};
#pragma unroll
        for (int kt = 0; kt < 4; kt++) {
            int kk = kt * 8;
#pragma unroll
            for (int ng = 0; ng < 4; ng++) {
                uint32_t kf[4];
                // lanes 0-7: (n-oct 0, k low), 8-15: (n-oct 0, k high),
                // 16-23: (n-oct 1, k low), 24-31: (n-oct 1, k high)
                ldsm_x4(kf, sbK + ((ng * 16 + (mtx >> 1) * 8 + rr) * AQS
                                   + kk + (mtx & 1) * 4) * 4);
                uint32_t b0[2] = {kf[0], kf[1]};
                uint32_t b1[2] = {kf[2], kf[3]};
                mma_f16(sacc[2 * ng],     qa[kt], b0);
                mma_f16(sacc[2 * ng + 1], qa[kt], b1);
            }
        }

        // ---- online softmax ----
        float mx0 = -INFINITY, mx1 = -INFINITY;
#pragma unroll
        for (int nt = 0; nt < 8; nt++) {
#pragma unroll
            for (int e = 0; e < 4; e++) sacc[nt][e] *= 0.125f;
            mx0 = fmaxf(mx0, fmaxf(sacc[nt][0], sacc[nt][1]));
            mx1 = fmaxf(mx1, fmaxf(sacc[nt][2], sacc[nt][3]));
        }
        mx0 = fmaxf(mx0, __shfl_xor_sync(0xffffffffu, mx0, 1));
        mx0 = fmaxf(mx0, __shfl_xor_sync(0xffffffffu, mx0, 2));
        mx1 = fmaxf(mx1, __shfl_xor_sync(0xffffffffu, mx1, 1));
        mx1 = fmaxf(mx1, __shfl_xor_sync(0xffffffffu, mx1, 2));
        float mn0 = fmaxf(mrow[0], mx0), mn1 = fmaxf(mrow[1], mx1);
        float sc0 = __expf(mrow[0] - mn0), sc1 = __expf(mrow[1] - mn1);
        float sum0 = 0.f, sum1 = 0.f;
#pragma unroll
        for (int nt = 0; nt < 8; nt++) {
            sacc[nt][0] = __expf(sacc[nt][0] - mn0);
            sacc[nt][1] = __expf(sacc[nt][1] - mn0);
            sacc[nt][2] = __expf(sacc[nt][2] - mn1);
            sacc[nt][3] = __expf(sacc[nt][3] - mn1);
            sum0 += sacc[nt][0] + sacc[nt][1];
            sum1 += sacc[nt][2] + sacc[nt][3];
        }
        sum0 += __shfl_xor_sync(0xffffffffu, sum0, 1);
        sum0 += __shfl_xor_sync(0xffffffffu, sum0, 2);
        sum1 += __shfl_xor_sync(0xffffffffu, sum1, 1);
        sum1 += __shfl_xor_sync(0xffffffffu, sum1, 2);
        lrow[0] = lrow[0] * sc0 + sum0;
        lrow[1] = lrow[1] * sc1 + sum1;
        mrow[0] = mn0; mrow[1] = mn1;
#pragma unroll
        for (int nt = 0; nt < 8; nt++) {
            oacc[nt][0] *= sc0; oacc[nt][1] *= sc0;
            oacc[nt][2] *= sc1; oacc[nt][3] *= sc1;
        }

        // ---- pack P into register A-fragments ----
        uint32_t pa[4][4];
#pragma unroll
        for (int kt = 0; kt < 4; kt++) {
            pa[kt][0] = packh2(sacc[2*kt][0],   sacc[2*kt][1]);
            pa[kt][1] = packh2(sacc[2*kt][2],   sacc[2*kt][3]);
            pa[kt][2] = packh2(sacc[2*kt+1][0], sacc[2*kt+1][1]);
            pa[kt][3] = packh2(sacc[2*kt+1][2], sacc[2*kt+1][3]);
        }

        // ---- O += P @ V : V B-frags via trans ldmatrix.x4 ----
#pragma unroll
        for (int kt = 0; kt < 4; kt++) {
            int kk16 = kt * 16;
#pragma unroll
            for (int ng = 0; ng < 4; ng++) {
                uint32_t vf[4];
                ldsm_x4_t(vf, sbV + (kk16 + (mtx & 1) * 8 + rr) * AQS * 4
                              + (ng * 16 + (mtx >> 1) * 8) * 2);
                uint32_t b0[2] = {vf[0], vf[1]};
                uint32_t b1[2] = {vf[2], vf[3]};
                mma_f16(oacc[2 * ng],     pa[kt], b0);
                mma_f16(oacc[2 * ng + 1], pa[kt], b1);
            }
        }
        __syncthreads();
        buf ^= 1;
    }

    float inv0 = 1.f / lrow[0], inv1 = 1.f / lrow[1];
    int rg = qt * 128 + wq + l4;
#pragma unroll
    for (int nt = 0; nt < 8; nt++) {
        int c = h * 64 + nt * 8 + la3 * 2;
        *(uint32_t*)&O[((size_t)b * Lq + rg) * C_DIM + c] =
            packh2(oacc[nt][0] * inv0, oacc[nt][1] * inv0);
        *(uint32_t*)&O[((size_t)b * Lq + rg + 8) * C_DIM + c] =
            packh2(oacc[nt][2] * inv1, oacc[nt][3] * inv1);
    }
}

// ---------------- LayerNorm / misc kernels ----------------
__global__ void ln_concat_kernel(const float* __restrict__ x, const float* __restrict__ t,
                                 __half* __restrict__ hh)
{
    int row = blockIdx.x, c = threadIdx.x;
    float v = t[(size_t)row * C_DIM + c];
    __shared__ float shs[8], shq[8];
    float s = v, q = v * v;
#pragma unroll
    for (int o = 16; o > 0; o >>= 1) {
        s += __shfl_xor_sync(0xffffffffu, s, o);
        q += __shfl_xor_sync(0xffffffffu, q, o);
    }
    if ((c & 31) == 0) { shs[c >> 5] = s; shq[c >> 5] = q; }
    __syncthreads();
    if (c < 32) {
        s = (c < 8) ? shs[c] : 0.f;
        q = (c < 8) ? shq[c] : 0.f;
#pragma unroll
        for (int o = 4; o > 0; o >>= 1) {
            s += __shfl_xor_sync(0xffffffffu, s, o);
            q += __shfl_xor_sync(0xffffffffu, q, o);
        }
        if (c == 0) { shs[0] = s; shq[0] = q; }
    }
    __syncthreads();
    float mean = shs[0] * (1.f / 256.f);
    float var  = shq[0] * (1.f / 256.f) - mean * mean;
    float y = (v - mean) * rsqrtf(var + 1e-5f);
    hh[(size_t)row * 512 + c]       = __float2half(x[(size_t)row * C_DIM + c]);
    hh[(size_t)row * 512 + 256 + c] = __float2half(y);
}

__global__ void ln_add_kernel(const float* __restrict__ x, const float* __restrict__ t,
                              float* __restrict__ outp, __half* __restrict__ outh)
{
    int row = blockIdx.x, c = threadIdx.x;
    float v = t[(size_t)row * C_DIM + c];
    __shared__ float shs[8], shq[8];
    float s = v, q = v * v;
#pragma unroll
    for (int o = 16; o > 0; o >>= 1) {
        s += __shfl_xor_sync(0xffffffffu, s, o);
        q += __shfl_xor_sync(0xffffffffu, q, o);
    }
    if ((c & 31) == 0) { shs[c >> 5] = s; shq[c >> 5] = q; }
    __syncthreads();
    if (c < 32) {
        s = (c < 8) ? shs[c] : 0.f;
        q = (c < 8) ? shq[c] : 0.f;
#pragma unroll
        for (int o = 4; o > 0; o >>= 1) {
            s += __shfl_xor_sync(0xffffffffu, s, o);
            q += __shfl_xor_sync(0xffffffffu, q, o);
        }
        if (c == 0) { shs[0] = s; shq[0] = q; }
    }
    __syncthreads();
    float mean = shs[0] * (1.f / 256.f);
    float var  = shq[0] * (1.f / 256.f) - mean * mean;
    float y = (v - mean) * rsqrtf(var + 1e-5f);
    float r = x[(size_t)row * C_DIM + c] + y;
    outp[(size_t)row * C_DIM + c] = r;
    outh[(size_t)row * C_DIM + c] = __float2half(r);
}

__global__ void add_kernel(float* __restrict__ x, __half* __restrict__ xh,
                           const float* __restrict__ a, int n)
{
    int i = blockIdx.x * 256 + threadIdx.x;
    if (i < n) {
        float v = x[i] + a[i];
        x[i] = v;
        xh[i] = __float2half(v);
    }
}

__global__ void gather_kernel(const float* __restrict__ feat, const int* __restrict__ idx,
                              float* __restrict__ outp, __half* __restrict__ outh,
                              int N, int Lp, int maskNum)
{
    int row = blockIdx.x;
    int g = row / Lp;
    int b = g / maskNum;
    int i = idx[row];
    int c = threadIdx.x;
    float val = 0.f;
    if (i >= 0 && i < N) val = feat[((size_t)b * N + i) * C_DIM + c];
    outp[(size_t)row * C_DIM + c] = val;
    outh[(size_t)row * C_DIM + c] = __float2half(val);
}

__global__ void cvt_h_kernel(const float* __restrict__ s, __half* __restrict__ d, int n)
{
    int i = blockIdx.x * 256 + threadIdx.x;
    if (i < n) d[i] = __float2half(s[i]);
}

__global__ void cvt_weights(const float* qW, const float* kW, const float* vW,
                            const float* mW, const float* w1, const float* w2,
                            const float* dino,
                            __half* wpackh, __half* mWh, __half* w1h, __half* w2h,
                            __half* dinoh)
{
    const int S1 = 5*256*768, S2 = 5*256*256, S3 = 5*512*512, S4 = 5*512*256, S5 = 384*256;
    int i = blockIdx.x * 256 + threadIdx.x;
    if (i < S1) {
        int li = i / (256 * 768), rem = i % (256 * 768);
        int k = rem / 768, j = rem % 768;
        int w = j >> 8, n = j & 255;
        const float* src = (w == 0) ? qW : (w == 1) ? kW : vW;
        wpackh[i] = __float2half(src[(size_t)li * 65536 + k * 256 + n]);
    } else if (i < S1 + S2) {
        mWh[i - S1] = __float2half(mW[i - S1]);
    } else if (i < S1 + S2 + S3) {
        w1h[i - S1 - S2] = __float2half(w1[i - S1 - S2]);
    } else if (i < S1 + S2 + S3 + S4) {
        w2h[i - S1 - S2 - S3] = __float2half(w2[i - S1 - S2 - S3]);
    } else if (i < S1 + S2 + S3 + S4 + S5) {
        dinoh[i - S1 - S2 - S3 - S4] = __float2half(dino[i - S1 - S2 - S3 - S4]);
    }
}

// ---------------- host orchestration ----------------
static void gemm(const __half* A, const __half* B, void* C, int M, int N, int K,
                 int ldb, int ldc, int flags)
{
    int ctas128 = (N / 128) * (M / 128);
    if (ctas128 < 256) {
        dim3 g(N / 128, M / 64);
        size_t sm = 2 * (64 * GA_STRIDE + 32 * GB_STRIDE);
        gemm_h<64><<<g, 256, sm>>>(A, B, C, M, N, K, ldb, ldc, flags);
    } else {
        dim3 g(N / 128, M / 128);
        size_t sm = 2 * (128 * GA_STRIDE + 32 * GB_STRIDE);
        gemm_h<128><<<g, 256, sm>>>(A, B, C, M, N, K, ldb, ldc, flags);
    }
}

struct Scr { __half *qkv, *oh, *hh, *t1h, *wpackh, *mWh, *w1h, *w2h; float* t2; };

static void layer_tail(const float* x, float* outp, __half* outh, int M, int li,
                       const Scr& S)
{
    const __half* mW = S.mWh + (size_t)li * 256 * 256;
    const __half* w1 = S.w1h + (size_t)li * 512 * 512;
    const __half* w2 = S.w2h + (size_t)li * 512 * 256;
    gemm(S.oh, mW, S.t2, M, 256, 256, 256, 256, 0);
    ln_concat_kernel<<<M, 256>>>(x, S.t2, S.hh);
    gemm(S.hh,  w1, S.t1h, M, 512, 512, 512, 512, 3);
    gemm(S.t1h, w2, S.t2,  M, 256, 512, 256, 256, 0);
    ln_add_kernel<<<M, 256>>>(x, S.t2, outp, outh);
}

extern "C" void kernel_launch(void* const* d_in, const int* in_sizes, int n_in,
                              void* d_out, int out_size)
{
    (void)in_sizes; (void)out_size;
    const float* in_srcF = (const float*)d_in[0];
    const float* in_tgtF = (const float*)d_in[1];
    const int*   si      = (const int*)  d_in[6];
    const int*   ti      = (const int*)  d_in[7];
    const float* src2d   = (const float*)d_in[11];
    const float* tgt2d   = (const float*)d_in[12];
    const float* w2A   = (const float*)d_in[n_in - 1];
    const float* w1A   = (const float*)d_in[n_in - 2];
    const float* mWA   = (const float*)d_in[n_in - 3];
    const float* vWA   = (const float*)d_in[n_in - 4];
    const float* kWA   = (const float*)d_in[n_in - 5];
    const float* qWA   = (const float*)d_in[n_in - 6];
    const float* dinoW = (const float*)d_in[n_in - 7];
    float* out = (float*)d_out;

    float *feat, *proj, *sub, *t2;
    __half *feath, *subh, *oh, *hh, *t1h, *qkv, *semh, *d2h;
    __half *wpackh, *mWh, *w1h, *w2h, *dinoh;
    cudaGetSymbolAddress((void**)&feat, g_feat);
    cudaGetSymbolAddress((void**)&proj, g_proj);
    cudaGetSymbolAddress((void**)&sub, g_sub);
    cudaGetSymbolAddress((void**)&t2, g_t2);
    cudaGetSymbolAddress((void**)&feath, g_feath);
    cudaGetSymbolAddress((void**)&subh, g_subh);
    cudaGetSymbolAddress((void**)&oh, g_oh);
    cudaGetSymbolAddress((void**)&hh, g_hh);
    cudaGetSymbolAddress((void**)&t1h, g_t1h);
    cudaGetSymbolAddress((void**)&qkv, g_qkv);
    cudaGetSymbolAddress((void**)&semh, g_semh);
    cudaGetSymbolAddress((void**)&d2h, g_2dh);
    cudaGetSymbolAddress((void**)&wpackh, g_wpackh);
    cudaGetSymbolAddress((void**)&mWh, g_mWh);
    cudaGetSymbolAddress((void**)&w1h, g_w1h);
    cudaGetSymbolAddress((void**)&w2h, g_w2h);
    cudaGetSymbolAddress((void**)&dinoh, g_dinoh);

    cudaFuncSetAttribute(attn_kernel, cudaFuncAttributeMaxDynamicSharedMemorySize,
                         ATTN_SMEM_BYTES);

    float* featS = feat;
    float* featT = feat + (size_t)4096 * 256;
    __half* featSh = feath;
    __half* featTh = feath + (size_t)4096 * 256;
    float* projS = proj;
    float* projT = proj + (size_t)4096 * 256;
    __half* src2h = d2h;
    __half* tgt2h = d2h + (size_t)4096 * 384;

    {
        const int TOT = 5*256*768 + 5*256*256 + 5*512*512 + 5*512*256 + 384*256;
        cvt_weights<<<(TOT + 255) / 256, 256>>>(qWA, kWA, vWA, mWA, w1A, w2A, dinoW,
                                                wpackh, mWh, w1h, w2h, dinoh);
    }
    cvt_h_kernel<<<(4096 * 384 + 255) / 256, 256>>>(src2d, src2h, 4096 * 384);
    cvt_h_kernel<<<(4096 * 384 + 255) / 256, 256>>>(tgt2d, tgt2h, 4096 * 384);

    Scr S{qkv, oh, hh, t1h, wpackh, mWh, w1h, w2h, t2};
    const size_t sideBytes = (size_t)4096 * 256 * sizeof(float);

    cudaMemcpyAsync(featS, in_srcF, sideBytes, cudaMemcpyDeviceToDevice, 0);
    cudaMemcpyAsync(featT, in_tgtF, sideBytes, cudaMemcpyDeviceToDevice, 0);

    gemm(src2h, dinoh, projS, 4096, 256, 384, 256, 256, 0);
    gemm(tgt2h, dinoh, projT, 4096, 256, 384, 256, 256, 0);

    for (int li = 0; li < 4; li++) {
        const __half* packL = wpackh + (size_t)li * 256 * 768;
        if ((li & 1) == 0) {
            add_kernel<<<8192 * 256 / 256, 256>>>(feat, feath, proj, 8192 * 256);
            gemm(feath, packL, qkv, 8192, 768, 256, 768, 768, 2);
            attn_kernel<<<dim3(16, NHEAD, 4), 256, ATTN_SMEM_BYTES>>>(
                qkv, qkv, oh, 2048, 2048, 0);
            layer_tail(feat, feat, feath, 8192, li, S);
        } else {
            gemm(feath, packL, qkv, 8192, 768, 256, 768, 768, 2);
            attn_kernel<<<dim3(16, NHEAD, 2), 256, ATTN_SMEM_BYTES>>>(
                qkv, qkv, oh, 2048, 2048, 2);
            layer_tail(featS, featS, featSh, 4096, li, S);
            gemm(featSh, packL + 256, qkv + 256, 4096, 512, 256, 768, 768, 2);
            attn_kernel<<<dim3(16, NHEAD, 2), 256, ATTN_SMEM_BYTES>>>(
                qkv + (size_t)2 * 2048 * 768, qkv, oh, 2048, 2048, 0);
            layer_tail(featT, featT, featTh, 4096, li, S);
        }
    }

    float* ssub = sub;
    float* tsub = sub + (size_t)8192 * 256;
    __half* ssubh = subh;
    __half* tsubh = subh + (size_t)8192 * 256;
    gather_kernel<<<16 * 512, 256>>>(featS, si, ssub, ssubh, 2048, 512, 8);
    gather_kernel<<<16 * 512, 256>>>(featT, ti, tsub, tsubh, 2048, 512, 8);
    {
        const __half* packL = wpackh + (size_t)4 * 256 * 768;
        gemm(subh, packL, qkv, 16384, 768, 256, 768, 768, 2);
        attn_kernel<<<dim3(4, NHEAD, 32), 256, ATTN_SMEM_BYTES>>>(
            qkv, qkv, oh, 512, 512, 16);
        layer_tail(sub, out + (size_t)2 * 1048576, semh, 16384, 4, S);
    }

    cudaMemcpyAsync(out,           featS, sideBytes, cudaMemcpyDeviceToDevice, 0);
    cudaMemcpyAsync(out + 1048576, featT, sideBytes, cudaMemcpyDeviceToDevice, 0);
}

// round 15
// speedup vs baseline: 6.4343x; 1.0614x over previous
#include <cuda_runtime.h>
#include <cuda_fp16.h>
#include <math.h>
#include <stdint.h>

#define C_DIM 256
#define NHEAD 4

// ---------------- device scratch (no allocation allowed) ----------------
__device__ float  g_feat [8192*256];
__device__ float  g_proj [8192*256];
__device__ float  g_sub  [16384*256];
__device__ float  g_t2   [16384*256];
__device__ __half g_feath[8192*256];
__device__ __half g_subh [16384*256];
__device__ __half g_oh   [16384*256];
__device__ __half g_hh   [16384*512];
__device__ __half g_t1h  [16384*512];
__device__ __half g_qkv  [16384*768];
__device__ __half g_semh [16384*256];
__device__ __half g_2dh  [2*4096*384];
__device__ __half g_wpackh[5*256*768];
__device__ __half g_mWh  [5*256*256];
__device__ __half g_w1h  [5*512*512];
__device__ __half g_w2h  [5*512*256];
__device__ __half g_dinoh[384*256];

// ---------------- helpers ----------------
__device__ __forceinline__ uint32_t packh2(float a, float b) {
    __half2 h = __floats2half2_rn(a, b);
    return *(uint32_t*)&h;
}
__device__ __forceinline__ void mma_f16(float (&d)[4], const uint32_t (&a)[4],
                                        const uint32_t (&b)[2]) {
    asm volatile(
        "mma.sync.aligned.m16n8k16.row.col.f32.f16.f16.f32 "
        "{%0,%1,%2,%3}, {%4,%5,%6,%7}, {%8,%9}, {%0,%1,%2,%3};"
        : "+f"(d[0]), "+f"(d[1]), "+f"(d[2]), "+f"(d[3])
        : "r"(a[0]), "r"(a[1]), "r"(a[2]), "r"(a[3]), "r"(b[0]), "r"(b[1]));
}
__device__ __forceinline__ void cp16(uint32_t smem_dst, const void* gsrc) {
    asm volatile("cp.async.cg.shared.global [%0], [%1], 16;"
                 :: "r"(smem_dst), "l"(gsrc));
}
#define CP_COMMIT() asm volatile("cp.async.commit_group;" ::: "memory")
#define CP_WAIT(n)  asm volatile("cp.async.wait_group %0;" :: "n"(n) : "memory")
__device__ __forceinline__ void ldsm_x4(uint32_t (&r)[4], uint32_t a) {
    asm volatile("ldmatrix.sync.aligned.m8n8.x4.shared.b16 {%0,%1,%2,%3}, [%4];"
        : "=r"(r[0]), "=r"(r[1]), "=r"(r[2]), "=r"(r[3]) : "r"(a));
}
__device__ __forceinline__ void ldsm_x4_t(uint32_t (&r)[4], uint32_t a) {
    asm volatile("ldmatrix.sync.aligned.m8n8.x4.trans.shared.b16 {%0,%1,%2,%3}, [%4];"
        : "=r"(r[0]), "=r"(r[1]), "=r"(r[2]), "=r"(r[3]) : "r"(a));
}

// ---------------- FP16 GEMM: ldmatrix + cp.async, 4-stage pipeline ----------
// C[M,N](ldc) = A[M,K] @ B[K,N](ldb); A,B half.
// flags: 1=ReLU, 2=half out, 4=scale cols<256 by 0.125 (exact pow2).
// M%MT==0, N%128==0, K%32==0, K>=96. 256 threads, 8 warps (2m x 4n).
#define GA_STRIDE 80
#define GB_STRIDE 272

template<int MT>
__global__ __launch_bounds__(256, 2)
void gemm_h(const __half* __restrict__ A, const __half* __restrict__ B,
            void* __restrict__ Cv, int M, int N, int K,
            int ldb, int ldc, int flags)
{
    constexpr int MC = MT / 32;
    constexpr int BUF = MT * GA_STRIDE + 32 * GB_STRIDE;
    extern __shared__ uint8_t gs[];
    uint32_t sbase = (uint32_t)__cvta_generic_to_shared(gs);
    int tid = threadIdx.x;
    int lane = tid & 31, wid = tid >> 5;
    int l4 = lane >> 2, la3 = lane & 3;
    int wm = (wid & 1) * (MT / 2), wn = (wid >> 1) * 32;
    int rowBase = blockIdx.y * MT, colBase = blockIdx.x << 7;
    int nC = K >> 5;

    int mtx = lane >> 3, rr = lane & 7;
    int a_row = (mtx & 1) * 8 + rr;
    int a_kc  = (mtx >> 1) * 8;
    int b_kr  = (mtx & 1) * 8 + rr;
    int b_nc  = (mtx >> 1) * 8;

    // prologue: fill chunks 0,1,2 (nC >= 3 always here)
#pragma unroll
    for (int s = 0; s < 3; s++) {
        uint32_t sa = sbase + s * BUF;
        uint32_t sbuf = sa + MT * GA_STRIDE;
        int kb = s << 5;
#pragma unroll
        for (int p = 0; p < MT / 64; p++) {
            int t = p * 256 + tid;
            int r = t >> 2, seg = t & 3;
            cp16(sa + r * GA_STRIDE + seg * 16,
                 A + (size_t)(rowBase + r) * K + kb + seg * 8);
        }
#pragma unroll
        for (int p = 0; p < 2; p++) {
            int t = p * 256 + tid;
            int r = t >> 4, seg = t & 15;
            cp16(sbuf + r * GB_STRIDE + seg * 16,
                 B + (size_t)(kb + r) * ldb + colBase + seg * 8);
        }
        CP_COMMIT();
    }

    float acc[MC][4][4] = {};
    for (int ci = 0; ci < nC; ci++) {
        int rem = nC - 1 - ci;
        if (rem >= 2) { CP_WAIT(2); }
        else if (rem == 1) { CP_WAIT(1); }
        else { CP_WAIT(0); }
        __syncthreads();

        uint32_t SAb = sbase + (ci & 3) * BUF;
        uint32_t SBb = SAb + MT * GA_STRIDE;
#pragma unroll
        for (int kt = 0; kt < 2; kt++) {
            int kk = kt * 16;
            uint32_t af[MC][4];
#pragma unroll
            for (int mt = 0; mt < MC; mt++)
                ldsm_x4(af[mt], SAb + (wm + mt * 16 + a_row) * GA_STRIDE + (kk + a_kc) * 2);
            uint32_t bf[2][4];
#pragma unroll
            for (int np = 0; np < 2; np++)
                ldsm_x4_t(bf[np], SBb + (kk + b_kr) * GB_STRIDE + (wn + np * 16 + b_nc) * 2);
#pragma unroll
            for (int mt = 0; mt < MC; mt++)
#pragma unroll
                for (int nt = 0; nt < 4; nt++) {
                    uint32_t bb[2] = {bf[nt >> 1][(nt & 1) * 2],
                                      bf[nt >> 1][(nt & 1) * 2 + 1]};
                    mma_f16(acc[mt][nt], af[mt], bb);
                }
        }
        if (ci + 3 < nC) {
            uint32_t sa = sbase + ((ci + 3) & 3) * BUF;   // buffer of chunk ci-1: safe
            uint32_t sbuf = sa + MT * GA_STRIDE;
            int kb = (ci + 3) << 5;
#pragma unroll
            for (int p = 0; p < MT / 64; p++) {
                int t = p * 256 + tid;
                int r = t >> 2, seg = t & 3;
                cp16(sa + r * GA_STRIDE + seg * 16,
                     A + (size_t)(rowBase + r) * K + kb + seg * 8);
            }
#pragma unroll
            for (int p = 0; p < 2; p++) {
                int t = p * 256 + tid;
                int r = t >> 4, seg = t & 15;
                cp16(sbuf + r * GB_STRIDE + seg * 16,
                     B + (size_t)(kb + r) * ldb + colBase + seg * 8);
            }
            CP_COMMIT();
        }
    }

    float scl = ((flags & 4) && colBase < 256) ? 0.125f : 1.0f;
#pragma unroll
    for (int mt = 0; mt < MC; mt++) {
        int r0 = rowBase + wm + mt * 16 + l4;
#pragma unroll
        for (int nt = 0; nt < 4; nt++) {
            int c = colBase + wn + nt * 8 + la3 * 2;
            float v[4] = {acc[mt][nt][0], acc[mt][nt][1], acc[mt][nt][2], acc[mt][nt][3]};
#pragma unroll
            for (int e = 0; e < 4; e++) v[e] *= scl;
            if (flags & 1) {
#pragma unroll
                for (int e = 0; e < 4; e++) v[e] = fmaxf(v[e], 0.f);
            }
            if (flags & 2) {
                __half* Ch = (__half*)Cv;
                *(uint32_t*)&Ch[(size_t)r0 * ldc + c]       = packh2(v[0], v[1]);
                *(uint32_t*)&Ch[(size_t)(r0 + 8) * ldc + c] = packh2(v[2], v[3]);
            } else {
                float* Cf = (float*)Cv;
                *(float2*)(Cf + (size_t)r0 * ldc + c)       = make_float2(v[0], v[1]);
                *(float2*)(Cf + (size_t)(r0 + 8) * ldc + c) = make_float2(v[2], v[3]);
            }
        }
    }
}

// ---------------- FP16 flash attention v2 (Q pre-scaled by 0.125) -----------
#define AQS 36
#define SM_Q 0
#define SM_K (128*AQS)
#define SM_V (SM_K + 2*64*AQS)
#define ATTN_SMEM_BYTES ((SM_V + 2*64*AQS) * 4)   // 55296

__global__ __launch_bounds__(256, 2)
void attn_kernel(const __half* __restrict__ Qp, const __half* __restrict__ KVp,
                 __half* __restrict__ O, int Lq, int Lkv, int kvx)
{
    extern __shared__ uint32_t sm[];
    uint32_t sb = (uint32_t)__cvta_generic_to_shared(sm);
    int tid = threadIdx.x;
    int lane = tid & 31, wid = tid >> 5;
    int l4 = lane >> 2, la3 = lane & 3;
    int qt = blockIdx.x, h = blockIdx.y, b = blockIdx.z;
    int bk = b ^ kvx;
    int wq = wid * 16;
    int mtx = lane >> 3, rr = lane & 7;

    const __half* Qb = Qp + ((size_t)b * Lq + qt * 128) * 768 + h * 64;
    const __half* Kb = KVp + (size_t)bk * Lkv * 768 + 256 + h * 64;
    const __half* Vb = Kb + 256;

#pragma unroll
    for (int p = 0; p < 4; p++) {
        int idx = p * 256 + tid;
        int r = idx >> 3, cg = idx & 7;
        cp16(sb + (SM_Q + r * AQS) * 4 + cg * 16, Qb + (size_t)r * 768 + cg * 8);
    }
#pragma unroll
    for (int p = 0; p < 2; p++) {
        int idx = p * 256 + tid;
        int r = idx >> 3, cg = idx & 7;
        cp16(sb + (SM_K + r * AQS) * 4 + cg * 16, Kb + (size_t)r * 768 + cg * 8);
        cp16(sb + (SM_V + r * AQS) * 4 + cg * 16, Vb + (size_t)r * 768 + cg * 8);
    }
    CP_COMMIT();

    uint32_t qa[4][4];
    float oacc[8][4] = {};
    float mrow[2] = {-INFINITY, -INFINITY};
    float lrow[2] = {0.f, 0.f};
    int buf = 0;
    int nTiles = Lkv >> 6;

    for (int t = 0; t < nTiles; t++) {
        if (t + 1 < nTiles) {
            const __half* Kn = Kb + (size_t)(t + 1) * 64 * 768;
            const __half* Vn = Vb + (size_t)(t + 1) * 64 * 768;
            uint32_t kd = sb + (SM_K + (buf ^ 1) * 64 * AQS) * 4;
            uint32_t vd = sb + (SM_V + (buf ^ 1) * 64 * AQS) * 4;
#pragma unroll
            for (int p = 0; p < 2; p++) {
                int idx = p * 256 + tid;
                int r = idx >> 3, cg = idx & 7;
                cp16(kd + r * AQS * 4 + cg * 16, Kn + (size_t)r * 768 + cg * 8);
                cp16(vd + r * AQS * 4 + cg * 16, Vn + (size_t)r * 768 + cg * 8);
            }
            CP_COMMIT();
            CP_WAIT(1);
        } else {
            CP_WAIT(0);
        }
        __syncthreads();

        if (t == 0) {
#pragma unroll
            for (int kt = 0; kt < 4; kt++) {
                int kk = kt * 8;
                int r = wq + l4;
                qa[kt][0] = sm[SM_Q + r * AQS + kk + la3];
                qa[kt][1] = sm[SM_Q + (r + 8) * AQS + kk + la3];
                qa[kt][2] = sm[SM_Q + r * AQS + kk + 4 + la3];
                qa[kt][3] = sm[SM_Q + (r + 8) * AQS + kk + 4 + la3];
            }
        }

        uint32_t sbK = sb + (SM_K + buf * 64 * AQS) * 4;
        uint32_t sbV = sb + (SM_V + buf * 64 * AQS) * 4;

        // ---- S = Q @ K^T (Q already scaled) ----
        float sacc[8][4] = {};
#pragma unroll
        for (int kt = 0; kt < 4; kt++) {
            int kk = kt * 8;
#pragma unroll
            for (int ng = 0; ng < 4; ng++) {
                uint32_t kf[4];
                ldsm_x4(kf, sbK + ((ng * 16 + (mtx >> 1) * 8 + rr) * AQS
                                   + kk + (mtx & 1) * 4) * 4);
                uint32_t b0[2] = {kf[0], kf[1]};
                uint32_t b1[2] = {kf[2], kf[3]};
                mma_f16(sacc[2 * ng],     qa[kt], b0);
                mma_f16(sacc[2 * ng + 1], qa[kt], b1);
            }
        }

        // ---- online softmax ----
        float mx0 = -INFINITY, mx1 = -INFINITY;
#pragma unroll
        for (int nt = 0; nt < 8; nt++) {
            mx0 = fmaxf(mx0, fmaxf(sacc[nt][0], sacc[nt][1]));
            mx1 = fmaxf(mx1, fmaxf(sacc[nt][2], sacc[nt][3]));
        }
        mx0 = fmaxf(mx0, __shfl_xor_sync(0xffffffffu, mx0, 1));
        mx0 = fmaxf(mx0, __shfl_xor_sync(0xffffffffu, mx0, 2));
        mx1 = fmaxf(mx1, __shfl_xor_sync(0xffffffffu, mx1, 1));
        mx1 = fmaxf(mx1, __shfl_xor_sync(0xffffffffu, mx1, 2));
        float mn0 = fmaxf(mrow[0], mx0), mn1 = fmaxf(mrow[1], mx1);
        float sc0 = __expf(mrow[0] - mn0), sc1 = __expf(mrow[1] - mn1);
        float sum0 = 0.f, sum1 = 0.f;
#pragma unroll
        for (int nt = 0; nt < 8; nt++) {
            sacc[nt][0] = __expf(sacc[nt][0] - mn0);
            sacc[nt][1] = __expf(sacc[nt][1] - mn0);
            sacc[nt][2] = __expf(sacc[nt][2] - mn1);
            sacc[nt][3] = __expf(sacc[nt][3] - mn1);
            sum0 += sacc[nt][0] + sacc[nt][1];
            sum1 += sacc[nt][2] + sacc[nt][3];
        }
        sum0 += __shfl_xor_sync(0xffffffffu, sum0, 1);
        sum0 += __shfl_xor_sync(0xffffffffu, sum0, 2);
        sum1 += __shfl_xor_sync(0xffffffffu, sum1, 1);
        sum1 += __shfl_xor_sync(0xffffffffu, sum1, 2);
        lrow[0] = lrow[0] * sc0 + sum0;
        lrow[1] = lrow[1] * sc1 + sum1;
        mrow[0] = mn0; mrow[1] = mn1;
#pragma unroll
        for (int nt = 0; nt < 8; nt++) {
            oacc[nt][0] *= sc0; oacc[nt][1] *= sc0;
            oacc[nt][2] *= sc1; oacc[nt][3] *= sc1;
        }

        uint32_t pa[4][4];
#pragma unroll
        for (int kt = 0; kt < 4; kt++) {
            pa[kt][0] = packh2(sacc[2*kt][0],   sacc[2*kt][1]);
            pa[kt][1] = packh2(sacc[2*kt][2],   sacc[2*kt][3]);
            pa[kt][2] = packh2(sacc[2*kt+1][0], sacc[2*kt+1][1]);
            pa[kt][3] = packh2(sacc[2*kt+1][2], sacc[2*kt+1][3]);
        }

        // ---- O += P @ V ----
#pragma unroll
        for (int kt = 0; kt < 4; kt++) {
            int kk16 = kt * 16;
#pragma unroll
            for (int ng = 0; ng < 4; ng++) {
                uint32_t vf[4];
                ldsm_x4_t(vf, sbV + (kk16 + (mtx & 1) * 8 + rr) * AQS * 4
                              + (ng * 16 + (mtx >> 1) * 8) * 2);
                uint32_t b0[2] = {vf[0], vf[1]};
                uint32_t b1[2] = {vf[2], vf[3]};
                mma_f16(oacc[2 * ng],     pa[kt], b0);
                mma_f16(oacc[2 * ng + 1], pa[kt], b1);
            }
        }
        __syncthreads();
        buf ^= 1;
    }

    float inv0 = 1.f / lrow[0], inv1 = 1.f / lrow[1];
    int rg = qt * 128 + wq + l4;
#pragma unroll
    for (int nt = 0; nt < 8; nt++) {
        int c = h * 64 + nt * 8 + la3 * 2;
        *(uint32_t*)&O[((size_t)b * Lq + rg) * C_DIM + c] =
            packh2(oacc[nt][0] * inv0, oacc[nt][1] * inv0);
        *(uint32_t*)&O[((size_t)b * Lq + rg + 8) * C_DIM + c] =
            packh2(oacc[nt][2] * inv1, oacc[nt][3] * inv1);
    }
}

// ---------------- LayerNorm / misc kernels ----------------
__global__ void ln_concat_kernel(const float* __restrict__ x, const float* __restrict__ t,
                                 __half* __restrict__ hh)
{
    int row = blockIdx.x, c = threadIdx.x;
    float v = t[(size_t)row * C_DIM + c];
    __shared__ float shs[8], shq[8];
    float s = v, q = v * v;
#pragma unroll
    for (int o = 16; o > 0; o >>= 1) {
        s += __shfl_xor_sync(0xffffffffu, s, o);
        q += __shfl_xor_sync(0xffffffffu, q, o);
    }
    if ((c & 31) == 0) { shs[c >> 5] = s; shq[c >> 5] = q; }
    __syncthreads();
    if (c < 32) {
        s = (c < 8) ? shs[c] : 0.f;
        q = (c < 8) ? shq[c] : 0.f;
#pragma unroll
        for (int o = 4; o > 0; o >>= 1) {
            s += __shfl_xor_sync(0xffffffffu, s, o);
            q += __shfl_xor_sync(0xffffffffu, q, o);
        }
        if (c == 0) { shs[0] = s; shq[0] = q; }
    }
    __syncthreads();
    float mean = shs[0] * (1.f / 256.f);
    float var  = shq[0] * (1.f / 256.f) - mean * mean;
    float y = (v - mean) * rsqrtf(var + 1e-5f);
    hh[(size_t)row * 512 + c]       = __float2half(x[(size_t)row * C_DIM + c]);
    hh[(size_t)row * 512 + 256 + c] = __float2half(y);
}

__global__ void ln_add_kernel(const float* __restrict__ x, const float* __restrict__ t,
                              float* __restrict__ outp, __half* __restrict__ outh)
{
    int row = blockIdx.x, c = threadIdx.x;
    float v = t[(size_t)row * C_DIM + c];
    __shared__ float shs[8], shq[8];
    float s = v, q = v * v;
#pragma unroll
    for (int o = 16; o > 0; o >>= 1) {
        s += __shfl_xor_sync(0xffffffffu, s, o);
        q += __shfl_xor_sync(0xffffffffu, q, o);
    }
    if ((c & 31) == 0) { shs[c >> 5] = s; shq[c >> 5] = q; }
    __syncthreads();
    if (c < 32) {
        s = (c < 8) ? shs[c] : 0.f;
        q = (c < 8) ? shq[c] : 0.f;
#pragma unroll
        for (int o = 4; o > 0; o >>= 1) {
            s += __shfl_xor_sync(0xffffffffu, s, o);
            q += __shfl_xor_sync(0xffffffffu, q, o);
        }
        if (c == 0) { shs[0] = s; shq[0] = q; }
    }
    __syncthreads();
    float mean = shs[0] * (1.f / 256.f);
    float var  = shq[0] * (1.f / 256.f) - mean * mean;
    float y = (v - mean) * rsqrtf(var + 1e-5f);
    float r = x[(size_t)row * C_DIM + c] + y;
    outp[(size_t)row * C_DIM + c] = r;
    outh[(size_t)row * C_DIM + c] = __float2half(r);
}

__global__ void add_kernel(float* __restrict__ x, __half* __restrict__ xh,
                           const float* __restrict__ a, int n)
{
    int i = blockIdx.x * 256 + threadIdx.x;
    if (i < n) {
        float v = x[i] + a[i];
        x[i] = v;
        xh[i] = __float2half(v);
    }
}

__global__ void gather_kernel(const float* __restrict__ feat, const int* __restrict__ idx,
                              float* __restrict__ outp, __half* __restrict__ outh,
                              int N, int Lp, int maskNum)
{
    int row = blockIdx.x;
    int g = row / Lp;
    int b = g / maskNum;
    int i = idx[row];
    int c = threadIdx.x;
    float val = 0.f;
    if (i >= 0 && i < N) val = feat[((size_t)b * N + i) * C_DIM + c];
    outp[(size_t)row * C_DIM + c] = val;
    outh[(size_t)row * C_DIM + c] = __float2half(val);
}

__global__ void cvt_h_kernel(const float* __restrict__ s, __half* __restrict__ d, int n)
{
    int i = blockIdx.x * 256 + threadIdx.x;
    if (i < n) d[i] = __float2half(s[i]);
}

__global__ void cvt_weights(const float* qW, const float* kW, const float* vW,
                            const float* mW, const float* w1, const float* w2,
                            const float* dino,
                            __half* wpackh, __half* mWh, __half* w1h, __half* w2h,
                            __half* dinoh)
{
    const int S1 = 5*256*768, S2 = 5*256*256, S3 = 5*512*512, S4 = 5*512*256, S5 = 384*256;
    int i = blockIdx.x * 256 + threadIdx.x;
    if (i < S1) {
        int li = i / (256 * 768), rem = i % (256 * 768);
        int k = rem / 768, j = rem % 768;
        int w = j >> 8, n = j & 255;
        const float* src = (w == 0) ? qW : (w == 1) ? kW : vW;
        wpackh[i] = __float2half(src[(size_t)li * 65536 + k * 256 + n]);
    } else if (i < S1 + S2) {
        mWh[i - S1] = __float2half(mW[i - S1]);
    } else if (i < S1 + S2 + S3) {
        w1h[i - S1 - S2] = __float2half(w1[i - S1 - S2]);
    } else if (i < S1 + S2 + S3 + S4) {
        w2h[i - S1 - S2 - S3] = __float2half(w2[i - S1 - S2 - S3]);
    } else if (i < S1 + S2 + S3 + S4 + S5) {
        dinoh[i - S1 - S2 - S3 - S4] = __float2half(dino[i - S1 - S2 - S3 - S4]);
    }
}

// ---------------- host orchestration ----------------
static void gemm(const __half* A, const __half* B, void* C, int M, int N, int K,
                 int ldb, int ldc, int flags)
{
    int ctas128 = (N / 128) * (M / 128);
    if (ctas128 < 256) {
        dim3 g(N / 128, M / 64);
        size_t sm = 4 * (64 * GA_STRIDE + 32 * GB_STRIDE);
        gemm_h<64><<<g, 256, sm>>>(A, B, C, M, N, K, ldb, ldc, flags);
    } else {
        dim3 g(N / 128, M / 128);
        size_t sm = 4 * (128 * GA_STRIDE + 32 * GB_STRIDE);
        gemm_h<128><<<g, 256, sm>>>(A, B, C, M, N, K, ldb, ldc, flags);
    }
}

struct Scr { __half *qkv, *oh, *hh, *t1h, *wpackh, *mWh, *w1h, *w2h; float* t2; };

static void layer_tail(const float* x, float* outp, __half* outh, int M, int li,
                       const Scr& S)
{
    const __half* mW = S.mWh + (size_t)li * 256 * 256;
    const __half* w1 = S.w1h + (size_t)li * 512 * 512;
    const __half* w2 = S.w2h + (size_t)li * 512 * 256;
    gemm(S.oh, mW, S.t2, M, 256, 256, 256, 256, 0);
    ln_concat_kernel<<<M, 256>>>(x, S.t2, S.hh);
    gemm(S.hh,  w1, S.t1h, M, 512, 512, 512, 512, 3);
    gemm(S.t1h, w2, S.t2,  M, 256, 512, 256, 256, 0);
    ln_add_kernel<<<M, 256>>>(x, S.t2, outp, outh);
}

extern "C" void kernel_launch(void* const* d_in, const int* in_sizes, int n_in,
                              void* d_out, int out_size)
{
    (void)in_sizes; (void)out_size;
    const float* in_srcF = (const float*)d_in[0];
    const float* in_tgtF = (const float*)d_in[1];
    const int*   si      = (const int*)  d_in[6];
    const int*   ti      = (const int*)  d_in[7];
    const float* src2d   = (const float*)d_in[11];
    const float* tgt2d   = (const float*)d_in[12];
    const float* w2A   = (const float*)d_in[n_in - 1];
    const float* w1A   = (const float*)d_in[n_in - 2];
    const float* mWA   = (const float*)d_in[n_in - 3];
    const float* vWA   = (const float*)d_in[n_in - 4];
    const float* kWA   = (const float*)d_in[n_in - 5];
    const float* qWA   = (const float*)d_in[n_in - 6];
    const float* dinoW = (const float*)d_in[n_in - 7];
    float* out = (float*)d_out;

    float *feat, *proj, *sub, *t2;
    __half *feath, *subh, *oh, *hh, *t1h, *qkv, *semh, *d2h;
    __half *wpackh, *mWh, *w1h, *w2h, *dinoh;
    cudaGetSymbolAddress((void**)&feat, g_feat);
    cudaGetSymbolAddress((void**)&proj, g_proj);
    cudaGetSymbolAddress((void**)&sub, g_sub);
    cudaGetSymbolAddress((void**)&t2, g_t2);
    cudaGetSymbolAddress((void**)&feath, g_feath);
    cudaGetSymbolAddress((void**)&subh, g_subh);
    cudaGetSymbolAddress((void**)&oh, g_oh);
    cudaGetSymbolAddress((void**)&hh, g_hh);
    cudaGetSymbolAddress((void**)&t1h, g_t1h);
    cudaGetSymbolAddress((void**)&qkv, g_qkv);
    cudaGetSymbolAddress((void**)&semh, g_semh);
    cudaGetSymbolAddress((void**)&d2h, g_2dh);
    cudaGetSymbolAddress((void**)&wpackh, g_wpackh);
    cudaGetSymbolAddress((void**)&mWh, g_mWh);
    cudaGetSymbolAddress((void**)&w1h, g_w1h);
    cudaGetSymbolAddress((void**)&w2h, g_w2h);
    cudaGetSymbolAddress((void**)&dinoh, g_dinoh);

    cudaFuncSetAttribute(attn_kernel, cudaFuncAttributeMaxDynamicSharedMemorySize,
                         ATTN_SMEM_BYTES);
    cudaFuncSetAttribute(gemm_h<64>, cudaFuncAttributeMaxDynamicSharedMemorySize,
                         4 * (64 * GA_STRIDE + 32 * GB_STRIDE));
    cudaFuncSetAttribute(gemm_h<128>, cudaFuncAttributeMaxDynamicSharedMemorySize,
                         4 * (128 * GA_STRIDE + 32 * GB_STRIDE));

    float* featS = feat;
    float* featT = feat + (size_t)4096 * 256;
    __half* featSh = feath;
    __half* featTh = feath + (size_t)4096 * 256;
    float* projS = proj;
    float* projT = proj + (size_t)4096 * 256;
    __half* src2h = d2h;
    __half* tgt2h = d2h + (size_t)4096 * 384;

    {
        const int TOT = 5*256*768 + 5*256*256 + 5*512*512 + 5*512*256 + 384*256;
        cvt_weights<<<(TOT + 255) / 256, 256>>>(qWA, kWA, vWA, mWA, w1A, w2A, dinoW,
                                                wpackh, mWh, w1h, w2h, dinoh);
    }
    cvt_h_kernel<<<(4096 * 384 + 255) / 256, 256>>>(src2d, src2h, 4096 * 384);
    cvt_h_kernel<<<(4096 * 384 + 255) / 256, 256>>>(tgt2d, tgt2h, 4096 * 384);

    Scr S{qkv, oh, hh, t1h, wpackh, mWh, w1h, w2h, t2};
    const size_t sideBytes = (size_t)4096 * 256 * sizeof(float);

    cudaMemcpyAsync(featS, in_srcF, sideBytes, cudaMemcpyDeviceToDevice, 0);
    cudaMemcpyAsync(featT, in_tgtF, sideBytes, cudaMemcpyDeviceToDevice, 0);

    gemm(src2h, dinoh, projS, 4096, 256, 384, 256, 256, 0);
    gemm(tgt2h, dinoh, projT, 4096, 256, 384, 256, 256, 0);

    for (int li = 0; li < 4; li++) {
        const __half* packL = wpackh + (size_t)li * 256 * 768;
        if ((li & 1) == 0) {
            add_kernel<<<8192 * 256 / 256, 256>>>(feat, feath, proj, 8192 * 256);
            gemm(feath, packL, qkv, 8192, 768, 256, 768, 768, 6);   // half out + Q scale
            attn_kernel<<<dim3(16, NHEAD, 4), 256, ATTN_SMEM_BYTES>>>(
                qkv, qkv, oh, 2048, 2048, 0);
            layer_tail(feat, feat, feath, 8192, li, S);
        } else {
            gemm(feath, packL, qkv, 8192, 768, 256, 768, 768, 6);   // fused both sides
            attn_kernel<<<dim3(16, NHEAD, 2), 256, ATTN_SMEM_BYTES>>>(
                qkv, qkv, oh, 2048, 2048, 2);
            layer_tail(featS, featS, featSh, 4096, li, S);
            gemm(featSh, packL + 256, qkv + 256, 4096, 512, 256, 768, 768, 2);  // KV only
            attn_kernel<<<dim3(16, NHEAD, 2), 256, ATTN_SMEM_BYTES>>>(
                qkv + (size_t)2 * 2048 * 768, qkv, oh, 2048, 2048, 0);
            layer_tail(featT, featT, featTh, 4096, li, S);
        }
    }

    float* ssub = sub;
    float* tsub = sub + (size_t)8192 * 256;
    __half* ssubh = subh;
    __half* tsubh = subh + (size_t)8192 * 256;
    gather_kernel<<<16 * 512, 256>>>(featS, si, ssub, ssubh, 2048, 512, 8);
    gather_kernel<<<16 * 512, 256>>>(featT, ti, tsub, tsubh, 2048, 512, 8);
    {
        const __half* packL = wpackh + (size_t)4 * 256 * 768;
        gemm(subh, packL, qkv, 16384, 768, 256, 768, 768, 6);
        attn_kernel<<<dim3(4, NHEAD, 32), 256, ATTN_SMEM_BYTES>>>(
            qkv, qkv, oh, 512, 512, 16);
        layer_tail(sub, out + (size_t)2 * 1048576, semh, 16384, 4, S);
    }

    cudaMemcpyAsync(out,           featS, sideBytes, cudaMemcpyDeviceToDevice, 0);
    cudaMemcpyAsync(out + 1048576, featT, sideBytes, cudaMemcpyDeviceToDevice, 0);
}

// round 16
// speedup vs baseline: 6.7502x; 1.0491x over previous
#include <cuda_runtime.h>
#include <cuda_fp16.h>
#include <math.h>
#include <stdint.h>

#define C_DIM 256
#define NHEAD 4

// ---------------- device scratch (no allocation allowed) ----------------
__device__ float  g_feat [8192*256];
__device__ float  g_proj [8192*256];
__device__ float  g_sub  [16384*256];
__device__ __half g_feath[8192*256];
__device__ __half g_subh [16384*256];
__device__ __half g_oh   [16384*256];
__device__ __half g_hh   [16384*512];
__device__ __half g_t1h  [16384*512];
__device__ __half g_qkv  [16384*768];
__device__ __half g_semh [16384*256];
__device__ __half g_2dh  [2*4096*384];
__device__ __half g_wpackh[5*256*768];
__device__ __half g_mWh  [5*256*256];
__device__ __half g_w1h  [5*512*512];
__device__ __half g_w2h  [5*512*256];
__device__ __half g_dinoh[384*256];
__device__ float  g_proj2[8192*256];   // spare (keeps layout stable)

// ---------------- helpers ----------------
__device__ __forceinline__ uint32_t packh2(float a, float b) {
    __half2 h = __floats2half2_rn(a, b);
    return *(uint32_t*)&h;
}
__device__ __forceinline__ void mma_f16(float (&d)[4], const uint32_t (&a)[4],
                                        const uint32_t (&b)[2]) {
    asm volatile(
        "mma.sync.aligned.m16n8k16.row.col.f32.f16.f16.f32 "
        "{%0,%1,%2,%3}, {%4,%5,%6,%7}, {%8,%9}, {%0,%1,%2,%3};"
        : "+f"(d[0]), "+f"(d[1]), "+f"(d[2]), "+f"(d[3])
        : "r"(a[0]), "r"(a[1]), "r"(a[2]), "r"(a[3]), "r"(b[0]), "r"(b[1]));
}
__device__ __forceinline__ void cp16(uint32_t smem_dst, const void* gsrc) {
    asm volatile("cp.async.cg.shared.global [%0], [%1], 16;"
                 :: "r"(smem_dst), "l"(gsrc));
}
#define CP_COMMIT() asm volatile("cp.async.commit_group;" ::: "memory")
#define CP_WAIT(n)  asm volatile("cp.async.wait_group %0;" :: "n"(n) : "memory")
__device__ __forceinline__ void ldsm_x4(uint32_t (&r)[4], uint32_t a) {
    asm volatile("ldmatrix.sync.aligned.m8n8.x4.shared.b16 {%0,%1,%2,%3}, [%4];"
        : "=r"(r[0]), "=r"(r[1]), "=r"(r[2]), "=r"(r[3]) : "r"(a));
}
__device__ __forceinline__ void ldsm_x4_t(uint32_t (&r)[4], uint32_t a) {
    asm volatile("ldmatrix.sync.aligned.m8n8.x4.trans.shared.b16 {%0,%1,%2,%3}, [%4];"
        : "=r"(r[0]), "=r"(r[1]), "=r"(r[2]), "=r"(r[3]) : "r"(a));
}

// ---------------- FP16 GEMM: ldmatrix + cp.async, 4-stage pipeline ----------
// flags: 1=ReLU, 2=half out, 4=scale cols<256 by 0.125 (exact pow2).
#define GA_STRIDE 80
#define GB_STRIDE 272

template<int MT>
__global__ __launch_bounds__(256, 2)
void gemm_h(const __half* __restrict__ A, const __half* __restrict__ B,
            void* __restrict__ Cv, int M, int N, int K,
            int ldb, int ldc, int flags)
{
    constexpr int MC = MT / 32;
    constexpr int BUF = MT * GA_STRIDE + 32 * GB_STRIDE;
    extern __shared__ uint8_t gs[];
    uint32_t sbase = (uint32_t)__cvta_generic_to_shared(gs);
    int tid = threadIdx.x;
    int lane = tid & 31, wid = tid >> 5;
    int l4 = lane >> 2, la3 = lane & 3;
    int wm = (wid & 1) * (MT / 2), wn = (wid >> 1) * 32;
    int rowBase = blockIdx.y * MT, colBase = blockIdx.x << 7;
    int nC = K >> 5;

    int mtx = lane >> 3, rr = lane & 7;
    int a_row = (mtx & 1) * 8 + rr;
    int a_kc  = (mtx >> 1) * 8;
    int b_kr  = (mtx & 1) * 8 + rr;
    int b_nc  = (mtx >> 1) * 8;

#pragma unroll
    for (int s = 0; s < 3; s++) {
        uint32_t sa = sbase + s * BUF;
        uint32_t sbuf = sa + MT * GA_STRIDE;
        int kb = s << 5;
#pragma unroll
        for (int p = 0; p < MT / 64; p++) {
            int t = p * 256 + tid;
            int r = t >> 2, seg = t & 3;
            cp16(sa + r * GA_STRIDE + seg * 16,
                 A + (size_t)(rowBase + r) * K + kb + seg * 8);
        }
#pragma unroll
        for (int p = 0; p < 2; p++) {
            int t = p * 256 + tid;
            int r = t >> 4, seg = t & 15;
            cp16(sbuf + r * GB_STRIDE + seg * 16,
                 B + (size_t)(kb + r) * ldb + colBase + seg * 8);
        }
        CP_COMMIT();
    }

    float acc[MC][4][4] = {};
    for (int ci = 0; ci < nC; ci++) {
        int rem = nC - 1 - ci;
        if (rem >= 2) { CP_WAIT(2); }
        else if (rem == 1) { CP_WAIT(1); }
        else { CP_WAIT(0); }
        __syncthreads();

        uint32_t SAb = sbase + (ci & 3) * BUF;
        uint32_t SBb = SAb + MT * GA_STRIDE;
#pragma unroll
        for (int kt = 0; kt < 2; kt++) {
            int kk = kt * 16;
            uint32_t af[MC][4];
#pragma unroll
            for (int mt = 0; mt < MC; mt++)
                ldsm_x4(af[mt], SAb + (wm + mt * 16 + a_row) * GA_STRIDE + (kk + a_kc) * 2);
            uint32_t bf[2][4];
#pragma unroll
            for (int np = 0; np < 2; np++)
                ldsm_x4_t(bf[np], SBb + (kk + b_kr) * GB_STRIDE + (wn + np * 16 + b_nc) * 2);
#pragma unroll
            for (int mt = 0; mt < MC; mt++)
#pragma unroll
                for (int nt = 0; nt < 4; nt++) {
                    uint32_t bb[2] = {bf[nt >> 1][(nt & 1) * 2],
                                      bf[nt >> 1][(nt & 1) * 2 + 1]};
                    mma_f16(acc[mt][nt], af[mt], bb);
                }
        }
        if (ci + 3 < nC) {
            uint32_t sa = sbase + ((ci + 3) & 3) * BUF;
            uint32_t sbuf = sa + MT * GA_STRIDE;
            int kb = (ci + 3) << 5;
#pragma unroll
            for (int p = 0; p < MT / 64; p++) {
                int t = p * 256 + tid;
                int r = t >> 2, seg = t & 3;
                cp16(sa + r * GA_STRIDE + seg * 16,
                     A + (size_t)(rowBase + r) * K + kb + seg * 8);
            }
#pragma unroll
            for (int p = 0; p < 2; p++) {
                int t = p * 256 + tid;
                int r = t >> 4, seg = t & 15;
                cp16(sbuf + r * GB_STRIDE + seg * 16,
                     B + (size_t)(kb + r) * ldb + colBase + seg * 8);
            }
            CP_COMMIT();
        }
    }

    float scl = ((flags & 4) && colBase < 256) ? 0.125f : 1.0f;
#pragma unroll
    for (int mt = 0; mt < MC; mt++) {
        int r0 = rowBase + wm + mt * 16 + l4;
#pragma unroll
        for (int nt = 0; nt < 4; nt++) {
            int c = colBase + wn + nt * 8 + la3 * 2;
            float v[4] = {acc[mt][nt][0], acc[mt][nt][1], acc[mt][nt][2], acc[mt][nt][3]};
#pragma unroll
            for (int e = 0; e < 4; e++) v[e] *= scl;
            if (flags & 1) {
#pragma unroll
                for (int e = 0; e < 4; e++) v[e] = fmaxf(v[e], 0.f);
            }
            if (flags & 2) {
                __half* Ch = (__half*)Cv;
                *(uint32_t*)&Ch[(size_t)r0 * ldc + c]       = packh2(v[0], v[1]);
                *(uint32_t*)&Ch[(size_t)(r0 + 8) * ldc + c] = packh2(v[2], v[3]);
            } else {
                float* Cf = (float*)Cv;
                *(float2*)(Cf + (size_t)r0 * ldc + c)       = make_float2(v[0], v[1]);
                *(float2*)(Cf + (size_t)(r0 + 8) * ldc + c) = make_float2(v[2], v[3]);
            }
        }
    }
}

// ---------------- fused GEMM(N=256) + LayerNorm epilogue --------------------
// y = LN(A @ B) per row. MODE 0: outh[row]=[half(x)|half(y)] (stride 512).
// MODE 1: outp[row]=x+y (f32, stride 256), outh[row]=half(x+y).
// Block tile 32x256 (full rows). 8 warps 2m x 4n, warp 16x64. 4-stage pipeline.
#define GLN_ASZ   (32*80)
#define GLN_BSTR  528
#define GLN_STAGE (GLN_ASZ + 32*GLN_BSTR)          // 19456
#define GLN_SMEM  (4*GLN_STAGE + 1024)             // 78848

template<int MODE>
__global__ __launch_bounds__(256, 2)
void gemm_ln(const __half* __restrict__ A, const __half* __restrict__ B,
             const float* __restrict__ x, float* __restrict__ outp,
             __half* __restrict__ outh, int M, int K, int ldb)
{
    extern __shared__ uint8_t gs[];
    uint32_t sbase = (uint32_t)__cvta_generic_to_shared(gs);
    float* ps = (float*)(gs + 4 * GLN_STAGE);      // [32][4]
    float* pq = ps + 128;                          // [32][4]
    int tid = threadIdx.x, lane = tid & 31, wid = tid >> 5;
    int l4 = lane >> 2, la3 = lane & 3;
    int wm = (wid & 1) * 16, wn = (wid >> 1) * 64;
    int rowBase = blockIdx.x * 32;
    int nC = K >> 5;
    int mtx = lane >> 3, rr = lane & 7;
    int a_row = (mtx & 1) * 8 + rr, a_kc = (mtx >> 1) * 8;
    int b_kr  = (mtx & 1) * 8 + rr, b_nc = (mtx >> 1) * 8;

#pragma unroll
    for (int s = 0; s < 3; s++) {
        uint32_t sa = sbase + s * GLN_STAGE, sb2 = sa + GLN_ASZ;
        int kb = s << 5;
        if (tid < 128) {
            int r = tid >> 2, seg = tid & 3;
            cp16(sa + r * 80 + seg * 16, A + (size_t)(rowBase + r) * K + kb + seg * 8);
        }
#pragma unroll
        for (int p = 0; p < 4; p++) {
            int t = p * 256 + tid;
            int r = t >> 5, seg = t & 31;
            cp16(sb2 + r * GLN_BSTR + seg * 16, B + (size_t)(kb + r) * ldb + seg * 8);
        }
        CP_COMMIT();
    }

    float acc[8][4] = {};
    for (int ci = 0; ci < nC; ci++) {
        int rem = nC - 1 - ci;
        if (rem >= 2) { CP_WAIT(2); }
        else if (rem == 1) { CP_WAIT(1); }
        else { CP_WAIT(0); }
        __syncthreads();

        uint32_t SAb = sbase + (ci & 3) * GLN_STAGE;
        uint32_t SBb = SAb + GLN_ASZ;
#pragma unroll
        for (int kt = 0; kt < 2; kt++) {
            int kk = kt * 16;
            uint32_t af[4];
            ldsm_x4(af, SAb + (wm + a_row) * 80 + (kk + a_kc) * 2);
            uint32_t bf[4][4];
#pragma unroll
            for (int np = 0; np < 4; np++)
                ldsm_x4_t(bf[np], SBb + (kk + b_kr) * GLN_BSTR + (wn + np * 16 + b_nc) * 2);
#pragma unroll
            for (int nf = 0; nf < 8; nf++) {
                uint32_t bb[2] = {bf[nf >> 1][(nf & 1) * 2], bf[nf >> 1][(nf & 1) * 2 + 1]};
                mma_f16(acc[nf], af, bb);
            }
        }
        if (ci + 3 < nC) {
            uint32_t sa = sbase + ((ci + 3) & 3) * GLN_STAGE, sb2 = sa + GLN_ASZ;
            int kb = (ci + 3) << 5;
            if (tid < 128) {
                int r = tid >> 2, seg = tid & 3;
                cp16(sa + r * 80 + seg * 16, A + (size_t)(rowBase + r) * K + kb + seg * 8);
            }
#pragma unroll
            for (int p = 0; p < 4; p++) {
                int t = p * 256 + tid;
                int r = t >> 5, seg = t & 31;
                cp16(sb2 + r * GLN_BSTR + seg * 16, B + (size_t)(kb + r) * ldb + seg * 8);
            }
            CP_COMMIT();
        }
    }

    // ---- LN reduction: per-thread partials over 16 cols x 2 rows ----
    float s0 = 0.f, s1 = 0.f, q0 = 0.f, q1 = 0.f;
#pragma unroll
    for (int nf = 0; nf < 8; nf++) {
        s0 += acc[nf][0] + acc[nf][1];
        q0 += acc[nf][0] * acc[nf][0] + acc[nf][1] * acc[nf][1];
        s1 += acc[nf][2] + acc[nf][3];
        q1 += acc[nf][2] * acc[nf][2] + acc[nf][3] * acc[nf][3];
    }
    s0 += __shfl_xor_sync(0xffffffffu, s0, 1); s0 += __shfl_xor_sync(0xffffffffu, s0, 2);
    q0 += __shfl_xor_sync(0xffffffffu, q0, 1); q0 += __shfl_xor_sync(0xffffffffu, q0, 2);
    s1 += __shfl_xor_sync(0xffffffffu, s1, 1); s1 += __shfl_xor_sync(0xffffffffu, s1, 2);
    q1 += __shfl_xor_sync(0xffffffffu, q1, 1); q1 += __shfl_xor_sync(0xffffffffu, q1, 2);
    if (la3 == 0) {
        int r = wm + l4, wnid = wid >> 1;
        ps[r * 4 + wnid] = s0; pq[r * 4 + wnid] = q0;
        ps[(r + 8) * 4 + wnid] = s1; pq[(r + 8) * 4 + wnid] = q1;
    }
    __syncthreads();

    int r0 = wm + l4, r1 = r0 + 8;
    float m0 = (ps[r0*4] + ps[r0*4+1] + ps[r0*4+2] + ps[r0*4+3]) * (1.f / 256.f);
    float v0 = (pq[r0*4] + pq[r0*4+1] + pq[r0*4+2] + pq[r0*4+3]) * (1.f / 256.f) - m0 * m0;
    float is0 = rsqrtf(v0 + 1e-5f);
    float m1 = (ps[r1*4] + ps[r1*4+1] + ps[r1*4+2] + ps[r1*4+3]) * (1.f / 256.f);
    float v1 = (pq[r1*4] + pq[r1*4+1] + pq[r1*4+2] + pq[r1*4+3]) * (1.f / 256.f) - m1 * m1;
    float is1 = rsqrtf(v1 + 1e-5f);

#pragma unroll
    for (int nf = 0; nf < 8; nf++) {
        int c = wn + nf * 8 + la3 * 2;
        float y0 = (acc[nf][0] - m0) * is0, y1 = (acc[nf][1] - m0) * is0;
        float y2 = (acc[nf][2] - m1) * is1, y3 = (acc[nf][3] - m1) * is1;
        if (MODE == 0) {
            *(uint32_t*)&outh[(size_t)(rowBase + r0) * 512 + 256 + c] = packh2(y0, y1);
            *(uint32_t*)&outh[(size_t)(rowBase + r1) * 512 + 256 + c] = packh2(y2, y3);
        } else {
            float xa0 = x[(size_t)(rowBase + r0) * 256 + c];
            float xa1 = x[(size_t)(rowBase + r0) * 256 + c + 1];
            float xb0 = x[(size_t)(rowBase + r1) * 256 + c];
            float xb1 = x[(size_t)(rowBase + r1) * 256 + c + 1];
            float o0 = xa0 + y0, o1 = xa1 + y1, o2 = xb0 + y2, o3 = xb1 + y3;
            *(float2*)(outp + (size_t)(rowBase + r0) * 256 + c) = make_float2(o0, o1);
            *(float2*)(outp + (size_t)(rowBase + r1) * 256 + c) = make_float2(o2, o3);
            *(uint32_t*)&outh[(size_t)(rowBase + r0) * 256 + c] = packh2(o0, o1);
            *(uint32_t*)&outh[(size_t)(rowBase + r1) * 256 + c] = packh2(o2, o3);
        }
    }
    if (MODE == 0) {   // copy x (f32 -> half) into cols [0,256)
#pragma unroll
        for (int p = 0; p < 32; p++) {
            int i = p * 256 + tid;
            int r = i >> 8, c = i & 255;
            outh[(size_t)(rowBase + r) * 512 + c] =
                __float2half(x[(size_t)(rowBase + r) * 256 + c]);
        }
    }
}

// ---------------- FP16 flash attention v2 (Q pre-scaled by 0.125) -----------
#define AQS 36
#define SM_Q 0
#define SM_K (128*AQS)
#define SM_V (SM_K + 2*64*AQS)
#define ATTN_SMEM_BYTES ((SM_V + 2*64*AQS) * 4)   // 55296

__global__ __launch_bounds__(256, 2)
void attn_kernel(const __half* __restrict__ Qp, const __half* __restrict__ KVp,
                 __half* __restrict__ O, int Lq, int Lkv, int kvx)
{
    extern __shared__ uint32_t sm[];
    uint32_t sb = (uint32_t)__cvta_generic_to_shared(sm);
    int tid = threadIdx.x;
    int lane = tid & 31, wid = tid >> 5;
    int l4 = lane >> 2, la3 = lane & 3;
    int qt = blockIdx.x, h = blockIdx.y, b = blockIdx.z;
    int bk = b ^ kvx;
    int wq = wid * 16;
    int mtx = lane >> 3, rr = lane & 7;

    const __half* Qb = Qp + ((size_t)b * Lq + qt * 128) * 768 + h * 64;
    const __half* Kb = KVp + (size_t)bk * Lkv * 768 + 256 + h * 64;
    const __half* Vb = Kb + 256;

#pragma unroll
    for (int p = 0; p < 4; p++) {
        int idx = p * 256 + tid;
        int r = idx >> 3, cg = idx & 7;
        cp16(sb + (SM_Q + r * AQS) * 4 + cg * 16, Qb + (size_t)r * 768 + cg * 8);
    }
#pragma unroll
    for (int p = 0; p < 2; p++) {
        int idx = p * 256 + tid;
        int r = idx >> 3, cg = idx & 7;
        cp16(sb + (SM_K + r * AQS) * 4 + cg * 16, Kb + (size_t)r * 768 + cg * 8);
        cp16(sb + (SM_V + r * AQS) * 4 + cg * 16, Vb + (size_t)r * 768 + cg * 8);
    }
    CP_COMMIT();

    uint32_t qa[4][4];
    float oacc[8][4] = {};
    float mrow[2] = {-INFINITY, -INFINITY};
    float lrow[2] = {0.f, 0.f};
    int buf = 0;
    int nTiles = Lkv >> 6;

    for (int t = 0; t < nTiles; t++) {
        if (t + 1 < nTiles) {
            const __half* Kn = Kb + (size_t)(t + 1) * 64 * 768;
            const __half* Vn = Vb + (size_t)(t + 1) * 64 * 768;
            uint32_t kd = sb + (SM_K + (buf ^ 1) * 64 * AQS) * 4;
            uint32_t vd = sb + (SM_V + (buf ^ 1) * 64 * AQS) * 4;
#pragma unroll
            for (int p = 0; p < 2; p++) {
                int idx = p * 256 + tid;
                int r = idx >> 3, cg = idx & 7;
                cp16(kd + r * AQS * 4 + cg * 16, Kn + (size_t)r * 768 + cg * 8);
                cp16(vd + r * AQS * 4 + cg * 16, Vn + (size_t)r * 768 + cg * 8);
            }
            CP_COMMIT();
            CP_WAIT(1);
        } else {
            CP_WAIT(0);
        }
        __syncthreads();

        if (t == 0) {
#pragma unroll
            for (int kt = 0; kt < 4; kt++) {
                int kk = kt * 8;
                int r = wq + l4;
                qa[kt][0] = sm[SM_Q + r * AQS + kk + la3];
                qa[kt][1] = sm[SM_Q + (r + 8) * AQS + kk + la3];
                qa[kt][2] = sm[SM_Q + r * AQS + kk + 4 + la3];
                qa[kt][3] = sm[SM_Q + (r + 8) * AQS + kk + 4 + la3];
            }
        }

        uint32_t sbK = sb + (SM_K + buf * 64 * AQS) * 4;
        uint32_t sbV = sb + (SM_V + buf * 64 * AQS) * 4;

        float sacc[8][4] = {};
#pragma unroll
        for (int kt = 0; kt < 4; kt++) {
            int kk = kt * 8;
#pragma unroll
            for (int ng = 0; ng < 4; ng++) {
                uint32_t kf[4];
                ldsm_x4(kf, sbK + ((ng * 16 + (mtx >> 1) * 8 + rr) * AQS
                                   + kk + (mtx & 1) * 4) * 4);
                uint32_t b0[2] = {kf[0], kf[1]};
                uint32_t b1[2] = {kf[2], kf[3]};
                mma_f16(sacc[2 * ng],     qa[kt], b0);
                mma_f16(sacc[2 * ng + 1], qa[kt], b1);
            }
        }

        float mx0 = -INFINITY, mx1 = -INFINITY;
#pragma unroll
        for (int nt = 0; nt < 8; nt++) {
            mx0 = fmaxf(mx0, fmaxf(sacc[nt][0], sacc[nt][1]));
            mx1 = fmaxf(mx1, fmaxf(sacc[nt][2], sacc[nt][3]));
        }
        mx0 = fmaxf(mx0, __shfl_xor_sync(0xffffffffu, mx0, 1));
        mx0 = fmaxf(mx0, __shfl_xor_sync(0xffffffffu, mx0, 2));
        mx1 = fmaxf(mx1, __shfl_xor_sync(0xffffffffu, mx1, 1));
        mx1 = fmaxf(mx1, __shfl_xor_sync(0xffffffffu, mx1, 2));
        float mn0 = fmaxf(mrow[0], mx0), mn1 = fmaxf(mrow[1], mx1);
        float sc0 = __expf(mrow[0] - mn0), sc1 = __expf(mrow[1] - mn1);
        float sum0 = 0.f, sum1 = 0.f;
#pragma unroll
        for (int nt = 0; nt < 8; nt++) {
            sacc[nt][0] = __expf(sacc[nt][0] - mn0);
            sacc[nt][1] = __expf(sacc[nt][1] - mn0);
            sacc[nt][2] = __expf(sacc[nt][2] - mn1);
            sacc[nt][3] = __expf(sacc[nt][3] - mn1);
            sum0 += sacc[nt][0] + sacc[nt][1];
            sum1 += sacc[nt][2] + sacc[nt][3];
        }
        sum0 += __shfl_xor_sync(0xffffffffu, sum0, 1);
        sum0 += __shfl_xor_sync(0xffffffffu, sum0, 2);
        sum1 += __shfl_xor_sync(0xffffffffu, sum1, 1);
        sum1 += __shfl_xor_sync(0xffffffffu, sum1, 2);
        lrow[0] = lrow[0] * sc0 + sum0;
        lrow[1] = lrow[1] * sc1 + sum1;
        mrow[0] = mn0; mrow[1] = mn1;
#pragma unroll
        for (int nt = 0; nt < 8; nt++) {
            oacc[nt][0] *= sc0; oacc[nt][1] *= sc0;
            oacc[nt][2] *= sc1; oacc[nt][3] *= sc1;
        }

        uint32_t pa[4][4];
#pragma unroll
        for (int kt = 0; kt < 4; kt++) {
            pa[kt][0] = packh2(sacc[2*kt][0],   sacc[2*kt][1]);
            pa[kt][1] = packh2(sacc[2*kt][2],   sacc[2*kt][3]);
            pa[kt][2] = packh2(sacc[2*kt+1][0], sacc[2*kt+1][1]);
            pa[kt][3] = packh2(sacc[2*kt+1][2], sacc[2*kt+1][3]);
        }

#pragma unroll
        for (int kt = 0; kt < 4; kt++) {
            int kk16 = kt * 16;
#pragma unroll
            for (int ng = 0; ng < 4; ng++) {
                uint32_t vf[4];
                ldsm_x4_t(vf, sbV + (kk16 + (mtx & 1) * 8 + rr) * AQS * 4
                              + (ng * 16 + (mtx >> 1) * 8) * 2);
                uint32_t b0[2] = {vf[0], vf[1]};
                uint32_t b1[2] = {vf[2], vf[3]};
                mma_f16(oacc[2 * ng],     pa[kt], b0);
                mma_f16(oacc[2 * ng + 1], pa[kt], b1);
            }
        }
        __syncthreads();
        buf ^= 1;
    }

    float inv0 = 1.f / lrow[0], inv1 = 1.f / lrow[1];
    int rg = qt * 128 + wq + l4;
#pragma unroll
    for (int nt = 0; nt < 8; nt++) {
        int c = h * 64 + nt * 8 + la3 * 2;
        *(uint32_t*)&O[((size_t)b * Lq + rg) * C_DIM + c] =
            packh2(oacc[nt][0] * inv0, oacc[nt][1] * inv0);
        *(uint32_t*)&O[((size_t)b * Lq + rg + 8) * C_DIM + c] =
            packh2(oacc[nt][2] * inv1, oacc[nt][3] * inv1);
    }
}

// ---------------- misc kernels ----------------
__global__ void add_kernel(float* __restrict__ x, __half* __restrict__ xh,
                           const float* __restrict__ a, int n)
{
    int i = blockIdx.x * 256 + threadIdx.x;
    if (i < n) {
        float v = x[i] + a[i];
        x[i] = v;
        xh[i] = __float2half(v);
    }
}

__global__ void gather_kernel(const float* __restrict__ feat, const int* __restrict__ idx,
                              float* __restrict__ outp, __half* __restrict__ outh,
                              int N, int Lp, int maskNum)
{
    int row = blockIdx.x;
    int g = row / Lp;
    int b = g / maskNum;
    int i = idx[row];
    int c = threadIdx.x;
    float val = 0.f;
    if (i >= 0 && i < N) val = feat[((size_t)b * N + i) * C_DIM + c];
    outp[(size_t)row * C_DIM + c] = val;
    outh[(size_t)row * C_DIM + c] = __float2half(val);
}

__global__ void cvt_h_kernel(const float* __restrict__ s, __half* __restrict__ d, int n)
{
    int i = blockIdx.x * 256 + threadIdx.x;
    if (i < n) d[i] = __float2half(s[i]);
}

__global__ void cvt_weights(const float* qW, const float* kW, const float* vW,
                            const float* mW, const float* w1, const float* w2,
                            const float* dino,
                            __half* wpackh, __half* mWh, __half* w1h, __half* w2h,
                            __half* dinoh)
{
    const int S1 = 5*256*768, S2 = 5*256*256, S3 = 5*512*512, S4 = 5*512*256, S5 = 384*256;
    int i = blockIdx.x * 256 + threadIdx.x;
    if (i < S1) {
        int li = i / (256 * 768), rem = i % (256 * 768);
        int k = rem / 768, j = rem % 768;
        int w = j >> 8, n = j & 255;
        const float* src = (w == 0) ? qW : (w == 1) ? kW : vW;
        wpackh[i] = __float2half(src[(size_t)li * 65536 + k * 256 + n]);
    } else if (i < S1 + S2) {
        mWh[i - S1] = __float2half(mW[i - S1]);
    } else if (i < S1 + S2 + S3) {
        w1h[i - S1 - S2] = __float2half(w1[i - S1 - S2]);
    } else if (i < S1 + S2 + S3 + S4) {
        w2h[i - S1 - S2 - S3] = __float2half(w2[i - S1 - S2 - S3]);
    } else if (i < S1 + S2 + S3 + S4 + S5) {
        dinoh[i - S1 - S2 - S3 - S4] = __float2half(dino[i - S1 - S2 - S3 - S4]);
    }
}

// ---------------- host orchestration ----------------
static void gemm(const __half* A, const __half* B, void* C, int M, int N, int K,
                 int ldb, int ldc, int flags)
{
    int ctas128 = (N / 128) * (M / 128);
    if (ctas128 < 256) {
        dim3 g(N / 128, M / 64);
        size_t sm = 4 * (64 * GA_STRIDE + 32 * GB_STRIDE);
        gemm_h<64><<<g, 256, sm>>>(A, B, C, M, N, K, ldb, ldc, flags);
    } else {
        dim3 g(N / 128, M / 128);
        size_t sm = 4 * (128 * GA_STRIDE + 32 * GB_STRIDE);
        gemm_h<128><<<g, 256, sm>>>(A, B, C, M, N, K, ldb, ldc, flags);
    }
}

struct Scr { __half *qkv, *oh, *hh, *t1h, *wpackh, *mWh, *w1h, *w2h; };

static void layer_tail(const float* x, float* outp, __half* outh, int M, int li,
                       const Scr& S)
{
    const __half* mW = S.mWh + (size_t)li * 256 * 256;
    const __half* w1 = S.w1h + (size_t)li * 512 * 512;
    const __half* w2 = S.w2h + (size_t)li * 512 * 256;
    gemm_ln<0><<<M / 32, 256, GLN_SMEM>>>(S.oh, mW, x, nullptr, S.hh, M, 256, 256);
    gemm(S.hh,  w1, S.t1h, M, 512, 512, 512, 512, 3);
    gemm_ln<1><<<M / 32, 256, GLN_SMEM>>>(S.t1h, w2, x, outp, outh, M, 512, 256);
}

extern "C" void kernel_launch(void* const* d_in, const int* in_sizes, int n_in,
                              void* d_out, int out_size)
{
    (void)in_sizes; (void)out_size;
    const float* in_srcF = (const float*)d_in[0];
    const float* in_tgtF = (const float*)d_in[1];
    const int*   si      = (const int*)  d_in[6];
    const int*   ti      = (const int*)  d_in[7];
    const float* src2d   = (const float*)d_in[11];
    const float* tgt2d   = (const float*)d_in[12];
    const float* w2A   = (const float*)d_in[n_in - 1];
    const float* w1A   = (const float*)d_in[n_in - 2];
    const float* mWA   = (const float*)d_in[n_in - 3];
    const float* vWA   = (const float*)d_in[n_in - 4];
    const float* kWA   = (const float*)d_in[n_in - 5];
    const float* qWA   = (const float*)d_in[n_in - 6];
    const float* dinoW = (const float*)d_in[n_in - 7];
    float* out = (float*)d_out;

    float *feat, *proj, *sub;
    __half *feath, *subh, *oh, *hh, *t1h, *qkv, *semh, *d2h;
    __half *wpackh, *mWh, *w1h, *w2h, *dinoh;
    cudaGetSymbolAddress((void**)&feat, g_feat);
    cudaGetSymbolAddress((void**)&proj, g_proj);
    cudaGetSymbolAddress((void**)&sub, g_sub);
    cudaGetSymbolAddress((void**)&feath, g_feath);
    cudaGetSymbolAddress((void**)&subh, g_subh);
    cudaGetSymbolAddress((void**)&oh, g_oh);
    cudaGetSymbolAddress((void**)&hh, g_hh);
    cudaGetSymbolAddress((void**)&t1h, g_t1h);
    cudaGetSymbolAddress((void**)&qkv, g_qkv);
    cudaGetSymbolAddress((void**)&semh, g_semh);
    cudaGetSymbolAddress((void**)&d2h, g_2dh);
    cudaGetSymbolAddress((void**)&wpackh, g_wpackh);
    cudaGetSymbolAddress((void**)&mWh, g_mWh);
    cudaGetSymbolAddress((void**)&w1h, g_w1h);
    cudaGetSymbolAddress((void**)&w2h, g_w2h);
    cudaGetSymbolAddress((void**)&dinoh, g_dinoh);

    cudaFuncSetAttribute(attn_kernel, cudaFuncAttributeMaxDynamicSharedMemorySize,
                         ATTN_SMEM_BYTES);
    cudaFuncSetAttribute(gemm_h<64>, cudaFuncAttributeMaxDynamicSharedMemorySize,
                         4 * (64 * GA_STRIDE + 32 * GB_STRIDE));
    cudaFuncSetAttribute(gemm_h<128>, cudaFuncAttributeMaxDynamicSharedMemorySize,
                         4 * (128 * GA_STRIDE + 32 * GB_STRIDE));
    cudaFuncSetAttribute(gemm_ln<0>, cudaFuncAttributeMaxDynamicSharedMemorySize,
                         GLN_SMEM);
    cudaFuncSetAttribute(gemm_ln<1>, cudaFuncAttributeMaxDynamicSharedMemorySize,
                         GLN_SMEM);

    float* featS = feat;
    float* featT = feat + (size_t)4096 * 256;
    __half* featSh = feath;
    __half* featTh = feath + (size_t)4096 * 256;
    float* projS = proj;
    float* projT = proj + (size_t)4096 * 256;
    __half* src2h = d2h;
    __half* tgt2h = d2h + (size_t)4096 * 384;

    {
        const int TOT = 5*256*768 + 5*256*256 + 5*512*512 + 5*512*256 + 384*256;
        cvt_weights<<<(TOT + 255) / 256, 256>>>(qWA, kWA, vWA, mWA, w1A, w2A, dinoW,
                                                wpackh, mWh, w1h, w2h, dinoh);
    }
    cvt_h_kernel<<<(4096 * 384 + 255) / 256, 256>>>(src2d, src2h, 4096 * 384);
    cvt_h_kernel<<<(4096 * 384 + 255) / 256, 256>>>(tgt2d, tgt2h, 4096 * 384);

    Scr S{qkv, oh, hh, t1h, wpackh, mWh, w1h, w2h};
    const size_t sideBytes = (size_t)4096 * 256 * sizeof(float);

    cudaMemcpyAsync(featS, in_srcF, sideBytes, cudaMemcpyDeviceToDevice, 0);
    cudaMemcpyAsync(featT, in_tgtF, sideBytes, cudaMemcpyDeviceToDevice, 0);

    gemm(src2h, dinoh, projS, 4096, 256, 384, 256, 256, 0);
    gemm(tgt2h, dinoh, projT, 4096, 256, 384, 256, 256, 0);

    for (int li = 0; li < 4; li++) {
        const __half* packL = wpackh + (size_t)li * 256 * 768;
        if ((li & 1) == 0) {
            add_kernel<<<8192 * 256 / 256, 256>>>(feat, feath, proj, 8192 * 256);
            gemm(feath, packL, qkv, 8192, 768, 256, 768, 768, 6);
            attn_kernel<<<dim3(16, NHEAD, 4), 256, ATTN_SMEM_BYTES>>>(
                qkv, qkv, oh, 2048, 2048, 0);
            layer_tail(feat, feat, feath, 8192, li, S);
        } else {
            gemm(feath, packL, qkv, 8192, 768, 256, 768, 768, 6);
            attn_kernel<<<dim3(16, NHEAD, 2), 256, ATTN_SMEM_BYTES>>>(
                qkv, qkv, oh, 2048, 2048, 2);
            layer_tail(featS, featS, featSh, 4096, li, S);
            gemm(featSh, packL + 256, qkv + 256, 4096, 512, 256, 768, 768, 2);
            attn_kernel<<<dim3(16, NHEAD, 2), 256, ATTN_SMEM_BYTES>>>(
                qkv + (size_t)2 * 2048 * 768, qkv, oh, 2048, 2048, 0);
            layer_tail(featT, featT, featTh, 4096, li, S);
        }
    }

    float* ssub = sub;
    float* tsub = sub + (size_t)8192 * 256;
    __half* ssubh = subh;
    __half* tsubh = subh + (size_t)8192 * 256;
    gather_kernel<<<16 * 512, 256>>>(featS, si, ssub, ssubh, 2048, 512, 8);
    gather_kernel<<<16 * 512, 256>>>(featT, ti, tsub, tsubh, 2048, 512, 8);
    {
        const __half* packL = wpackh + (size_t)4 * 256 * 768;
        gemm(subh, packL, qkv, 16384, 768, 256, 768, 768, 6);
        attn_kernel<<<dim3(4, NHEAD, 32), 256, ATTN_SMEM_BYTES>>>(
            qkv, qkv, oh, 512, 512, 16);
        layer_tail(sub, out + (size_t)2 * 1048576, semh, 16384, 4, S);
    }

    cudaMemcpyAsync(out,           featS, sideBytes, cudaMemcpyDeviceToDevice, 0);
    cudaMemcpyAsync(out + 1048576, featT, sideBytes, cudaMemcpyDeviceToDevice, 0);
}